// round 5
// baseline (speedup 1.0000x reference)
#include <cuda_runtime.h>
#include <mma.h>
#include <math.h>

using namespace nvcuda;

#define Bq     64
#define Nq     384
#define NFEAT  16
#define Eq     3
#define NHID   128
#define ST_HID 64
#define ST_OUT 16
#define MFLAT  (Bq * Nq)

// ---------------- device scratch (tf32 values stored in float) ----------------
__device__ float g_adjhi[Bq * Eq * Nq * Nq];    // 113 MB
__device__ float g_adjlo[Bq * Eq * Nq * Nq];    // 113 MB
__device__ float g_supphi[Bq * Eq * Nq * NHID]; // 37.7 MB
__device__ float g_supplo[Bq * Eq * Nq * NHID];
__device__ float g_hhi[MFLAT * NHID];
__device__ float g_hlo[MFLAT * NHID];
__device__ float g_h[MFLAT * NHID];
__device__ float g_xhi[MFLAT * NFEAT];
__device__ float g_xlo[MFLAT * NFEAT];
__device__ float g_c1hi[Eq * NFEAT * NHID];
__device__ float g_c1lo[Eq * NFEAT * NHID];
__device__ float g_w2hi[Eq * NHID * NHID];
__device__ float g_w2lo[Eq * NHID * NHID];
__device__ float g_w3hi[Eq * NHID * NHID];
__device__ float g_w3lo[Eq * NHID * NHID];

// ---------------- tf32 rounding ----------------
__device__ __forceinline__ float tf32r(float v) {
    unsigned u;
    asm("cvt.rna.tf32.f32 %0, %1;" : "=r"(u) : "f"(v));
    return __uint_as_float(u);
}
__device__ __forceinline__ void split1(float v, float& hi, float& lo) {
    hi = tf32r(v);
    lo = tf32r(v - hi);
}

__global__ void split_kernel(const float* __restrict__ src,
                             float* __restrict__ hi, float* __restrict__ lo,
                             int n4) {
    int i = blockIdx.x * blockDim.x + threadIdx.x;
    if (i >= n4) return;
    float4 v = *(const float4*)(src + (size_t)i * 4);
    float4 h, l;
    split1(v.x, h.x, l.x); split1(v.y, h.y, l.y);
    split1(v.z, h.z, l.z); split1(v.w, h.w, l.w);
    *(float4*)(hi + (size_t)i * 4) = h;
    *(float4*)(lo + (size_t)i * 4) = l;
}

// C1[e][f][h] = sum_d emb_w[d][f] * gc1_w[e][d][h], tf32-split
__global__ void c1_split_kernel(const float* __restrict__ emb_w,
                                const float* __restrict__ gc1_w,
                                float* __restrict__ hi, float* __restrict__ lo) {
    int idx = blockIdx.x * 256 + threadIdx.x;
    if (idx >= Eq * NFEAT * NHID) return;
    int h = idx & 127, f = (idx >> 7) & 15, e = idx >> 11;
    float acc = 0.f;
#pragma unroll
    for (int d = 0; d < NFEAT; d++)
        acc += emb_w[d * NFEAT + f] * gc1_w[(e * NFEAT + d) * NHID + h];
    float hh, ll;
    split1(acc, hh, ll);
    hi[idx] = hh; lo[idx] = ll;
}

// ---------------- shared-mem layouts (floats) ----------------
// agg: A tiles 64x32 (ld 36), B tiles 32x128 (ld 132)
#define AG_LDA 36
#define AG_LDB 132
#define AG_AHI 0
#define AG_ALO (64 * AG_LDA * 4)                 // 9216
#define AG_BHI (2 * 64 * AG_LDA * 4)             // 18432
#define AG_BLO (AG_BHI + 32 * AG_LDB * 4)        // 35328
#define AG_SMEM (AG_BLO + 32 * AG_LDB * 4)       // 52224
// support: A tiles 64x16 (ld 20), B tiles 16x128 (ld 132)
#define SP_LDA 20
#define SP_AHI 0
#define SP_ALO (64 * SP_LDA * 4)                 // 5120
#define SP_BHI (2 * 64 * SP_LDA * 4)             // 10240
#define SP_BLO (SP_BHI + 16 * AG_LDB * 4)        // 18688
#define SP_SMEM_MIN (SP_BLO + 16 * AG_LDB * 4)   // 27136
#define ELDM 132
#define EP_SMEM (64 * ELDM * 4)                  // 33792
#define SP_SMEM ((SP_SMEM_MIN > EP_SMEM) ? SP_SMEM_MIN : EP_SMEM)

typedef wmma::fragment<wmma::matrix_a, 16, 16, 8, wmma::precision::tf32, wmma::row_major> AFrag;
typedef wmma::fragment<wmma::matrix_b, 16, 16, 8, wmma::precision::tf32, wmma::row_major> BFrag;
typedef wmma::fragment<wmma::accumulator, 16, 16, 16, float> CFrag;  // shape tag only
typedef wmma::fragment<wmma::accumulator, 16, 16, 8, float> CFrag8;

// ---------------------------------------------------------------------------
// Aggregation: h[b,m,:] = sum_e act( adj[b,e,m,:] @ supp[b,e,:,:] )
// BM=64, BN=128, 8 warps (2x4), warp tile 32x32, BK=32, 3xTF32.
// grid: (Nq/64, Bq). MODE 0: relu + tf32-split out; MODE 1: fp32 out.
// ---------------------------------------------------------------------------
template <int MODE>
__global__ __launch_bounds__(256, 2)
void agg_wmma(const float* __restrict__ adjhi, const float* __restrict__ adjlo,
              const float* __restrict__ shi, const float* __restrict__ slo,
              float* __restrict__ outhi, float* __restrict__ outlo,
              float* __restrict__ outf) {
    extern __shared__ char sm[];
    float* Ahi = (float*)(sm + AG_AHI);
    float* Alo = (float*)(sm + AG_ALO);
    float* Bhi = (float*)(sm + AG_BHI);
    float* Blo = (float*)(sm + AG_BLO);
    float* E   = (float*)sm;

    const int tid = threadIdx.x;
    const int wid = tid >> 5;
    const int wm = wid >> 2, wn = wid & 3;
    const int b = blockIdx.y, m0 = blockIdx.x * 64;

    CFrag8 tot[2][2], c[2][2];
#pragma unroll
    for (int i = 0; i < 2; i++)
#pragma unroll
        for (int j = 0; j < 2; j++) wmma::fill_fragment(tot[i][j], 0.f);

    for (int e = 0; e < Eq; e++) {
#pragma unroll
        for (int i = 0; i < 2; i++)
#pragma unroll
            for (int j = 0; j < 2; j++) wmma::fill_fragment(c[i][j], 0.f);

        const float* aH = adjhi + ((size_t)(b * Eq + e) * Nq + m0) * Nq;
        const float* aL = adjlo + ((size_t)(b * Eq + e) * Nq + m0) * Nq;
        const float* bH = shi + (size_t)(b * Eq + e) * Nq * NHID;
        const float* bL = slo + (size_t)(b * Eq + e) * Nq * NHID;

        for (int kt = 0; kt < Nq / 32; kt++) {
            // A tiles: 64x32 floats each -> 2 float4/thread/array
#pragma unroll
            for (int t = 0; t < 2; t++) {
                int idx = tid + t * 256;
                int r = idx >> 3, c4 = idx & 7;
                size_t g = (size_t)r * Nq + kt * 32 + c4 * 4;
                *(float4*)&Ahi[r * AG_LDA + c4 * 4] = *(const float4*)(aH + g);
                *(float4*)&Alo[r * AG_LDA + c4 * 4] = *(const float4*)(aL + g);
            }
            // B tiles: 32x128 floats each -> 4 float4/thread/array
#pragma unroll
            for (int t = 0; t < 4; t++) {
                int idx = tid + t * 256;
                int r = idx >> 5, c4 = idx & 31;
                size_t g = (size_t)(kt * 32 + r) * NHID + c4 * 4;
                *(float4*)&Bhi[r * AG_LDB + c4 * 4] = *(const float4*)(bH + g);
                *(float4*)&Blo[r * AG_LDB + c4 * 4] = *(const float4*)(bL + g);
            }
            __syncthreads();

#pragma unroll
            for (int k8 = 0; k8 < 4; k8++) {
                AFrag afH[2], afL[2];
                BFrag bfH[2], bfL[2];
#pragma unroll
                for (int i = 0; i < 2; i++) {
                    const float* p = &Ahi[(wm * 32 + i * 16) * AG_LDA + k8 * 8];
                    wmma::load_matrix_sync(afH[i], p, AG_LDA);
                    wmma::load_matrix_sync(afL[i], p + (AG_ALO - AG_AHI) / 4, AG_LDA);
                }
#pragma unroll
                for (int j = 0; j < 2; j++) {
                    const float* p = &Bhi[(k8 * 8) * AG_LDB + wn * 32 + j * 16];
                    wmma::load_matrix_sync(bfH[j], p, AG_LDB);
                    wmma::load_matrix_sync(bfL[j], p + (AG_BLO - AG_BHI) / 4, AG_LDB);
                }
#pragma unroll
                for (int i = 0; i < 2; i++)
#pragma unroll
                    for (int j = 0; j < 2; j++) {
                        wmma::mma_sync(c[i][j], afH[i], bfH[j], c[i][j]);
                        wmma::mma_sync(c[i][j], afH[i], bfL[j], c[i][j]);
                        wmma::mma_sync(c[i][j], afL[i], bfH[j], c[i][j]);
                    }
            }
            __syncthreads();
        }

#pragma unroll
        for (int i = 0; i < 2; i++)
#pragma unroll
            for (int j = 0; j < 2; j++)
#pragma unroll
                for (int t = 0; t < c[i][j].num_elements; t++)
                    tot[i][j].x[t] += (MODE == 0) ? fmaxf(c[i][j].x[t], 0.f)
                                                  : c[i][j].x[t];
    }

    // Epilogue: stage fp32 tile in smem, then write tf32-split (or fp32)
#pragma unroll
    for (int i = 0; i < 2; i++)
#pragma unroll
        for (int j = 0; j < 2; j++)
            wmma::store_matrix_sync(&E[(wm * 32 + i * 16) * ELDM + wn * 32 + j * 16],
                                    tot[i][j], ELDM, wmma::mem_row_major);
    __syncthreads();

#pragma unroll
    for (int t = 0; t < 8; t++) {                // 64*128/4 quads / 256 thr
        int p = tid + t * 256;
        int r = p >> 5, c4 = (p & 31) * 4;
        float4 v = *(float4*)&E[r * ELDM + c4];
        size_t o = (size_t)(b * Nq + m0 + r) * NHID + c4;
        if (MODE == 0) {
            float4 h, l;
            split1(v.x, h.x, l.x); split1(v.y, h.y, l.y);
            split1(v.z, h.z, l.z); split1(v.w, h.w, l.w);
            *(float4*)(outhi + o) = h;
            *(float4*)(outlo + o) = l;
        } else {
            *(float4*)(outf + o) = v;
        }
    }
}

// ---------------------------------------------------------------------------
// Support: supp[b,e,n,:] = act_in[row,:] @ W[e];  BK=16, 3xTF32.
// grid: (MFLAT/64, Eq). Output tf32-split.
// ---------------------------------------------------------------------------
template <int K>
__global__ __launch_bounds__(256, 2)
void support_wmma(const float* __restrict__ ahi, const float* __restrict__ alo,
                  const float* __restrict__ whi, const float* __restrict__ wlo,
                  float* __restrict__ supphi, float* __restrict__ supplo) {
    extern __shared__ char sm[];
    float* Ahi = (float*)(sm + SP_AHI);
    float* Alo = (float*)(sm + SP_ALO);
    float* Bhi = (float*)(sm + SP_BHI);
    float* Blo = (float*)(sm + SP_BLO);
    float* E   = (float*)sm;

    const int tid = threadIdx.x;
    const int wid = tid >> 5;
    const int wm = wid >> 2, wn = wid & 3;
    const int e = blockIdx.y;
    const int m0 = blockIdx.x * 64;
    const int b = m0 / Nq, n0 = m0 % Nq;

    const float* aH = ahi + (size_t)m0 * K;
    const float* aL = alo + (size_t)m0 * K;
    const float* wH = whi + (size_t)e * K * NHID;
    const float* wL = wlo + (size_t)e * K * NHID;

    CFrag8 c[2][2];
#pragma unroll
    for (int i = 0; i < 2; i++)
#pragma unroll
        for (int j = 0; j < 2; j++) wmma::fill_fragment(c[i][j], 0.f);

#pragma unroll
    for (int kt = 0; kt < K / 16; kt++) {
        // A tiles: 64x16 floats -> 1 float4/thread/array
        {
            int r = tid >> 2, c4 = tid & 3;
            size_t g = (size_t)r * K + kt * 16 + c4 * 4;
            *(float4*)&Ahi[r * SP_LDA + c4 * 4] = *(const float4*)(aH + g);
            *(float4*)&Alo[r * SP_LDA + c4 * 4] = *(const float4*)(aL + g);
        }
        // B tiles: 16x128 floats -> 2 float4/thread/array
#pragma unroll
        for (int t = 0; t < 2; t++) {
            int idx = tid + t * 256;
            int r = idx >> 5, c4 = idx & 31;
            size_t g = (size_t)(kt * 16 + r) * NHID + c4 * 4;
            *(float4*)&Bhi[r * AG_LDB + c4 * 4] = *(const float4*)(wH + g);
            *(float4*)&Blo[r * AG_LDB + c4 * 4] = *(const float4*)(wL + g);
        }
        __syncthreads();

#pragma unroll
        for (int k8 = 0; k8 < 2; k8++) {
            AFrag afH[2], afL[2];
            BFrag bfH[2], bfL[2];
#pragma unroll
            for (int i = 0; i < 2; i++) {
                const float* p = &Ahi[(wm * 32 + i * 16) * SP_LDA + k8 * 8];
                wmma::load_matrix_sync(afH[i], p, SP_LDA);
                wmma::load_matrix_sync(afL[i], p + (SP_ALO - SP_AHI) / 4, SP_LDA);
            }
#pragma unroll
            for (int j = 0; j < 2; j++) {
                const float* p = &Bhi[(k8 * 8) * AG_LDB + wn * 32 + j * 16];
                wmma::load_matrix_sync(bfH[j], p, AG_LDB);
                wmma::load_matrix_sync(bfL[j], p + (SP_BLO - SP_BHI) / 4, AG_LDB);
            }
#pragma unroll
            for (int i = 0; i < 2; i++)
#pragma unroll
                for (int j = 0; j < 2; j++) {
                    wmma::mma_sync(c[i][j], afH[i], bfH[j], c[i][j]);
                    wmma::mma_sync(c[i][j], afH[i], bfL[j], c[i][j]);
                    wmma::mma_sync(c[i][j], afL[i], bfH[j], c[i][j]);
                }
        }
        __syncthreads();
    }

#pragma unroll
    for (int i = 0; i < 2; i++)
#pragma unroll
        for (int j = 0; j < 2; j++)
            wmma::store_matrix_sync(&E[(wm * 32 + i * 16) * ELDM + wn * 32 + j * 16],
                                    c[i][j], ELDM, wmma::mem_row_major);
    __syncthreads();

#pragma unroll
    for (int t = 0; t < 8; t++) {
        int p = tid + t * 256;
        int r = p >> 5, c4 = (p & 31) * 4;
        float4 v = *(float4*)&E[r * ELDM + c4];
        float4 h, l;
        split1(v.x, h.x, l.x); split1(v.y, h.y, l.y);
        split1(v.z, h.z, l.z); split1(v.w, h.w, l.w);
        size_t o = ((size_t)(b * Eq + e) * Nq + n0 + r) * NHID + c4;
        *(float4*)(supphi + o) = h;
        *(float4*)(supplo + o) = l;
    }
}

// ---------------------------------------------------------------------------
// Head (SIMT, fp32)
// ---------------------------------------------------------------------------
__global__ __launch_bounds__(256)
void head_kernel(const float* __restrict__ hin,
                 const float* __restrict__ w1, const float* __restrict__ b1,
                 const float* __restrict__ w2, const float* __restrict__ b2,
                 const float* __restrict__ rescale, float* __restrict__ out) {
    __shared__ float w1T[NHID][68];
    __shared__ float hS[16][NHID];
    __shared__ float z1S[16][68];

    const int tid = threadIdx.x;
    const int row0 = blockIdx.x * 16;

    for (int i = tid; i < ST_HID * NHID; i += 256) {
        int hid = i >> 7, d = i & 127;
        w1T[d][hid] = w1[i];
    }
    const float* base = hin + (size_t)row0 * NHID;
#pragma unroll
    for (int t = 0; t < 2; t++) {
        int idx = tid + t * 256;
        int r = idx >> 5, c = idx & 31;
        *(float4*)&hS[r][c * 4] = *(const float4*)(base + (size_t)r * NHID + c * 4);
    }
    __syncthreads();

    {
        int row = tid >> 4, hg = tid & 15;
        float a0 = b1[hg * 4 + 0], a1 = b1[hg * 4 + 1];
        float a2 = b1[hg * 4 + 2], a3 = b1[hg * 4 + 3];
#pragma unroll 8
        for (int d = 0; d < NHID; d++) {
            float h = hS[row][d];
            float4 w = *(const float4*)&w1T[d][hg * 4];
            a0 = fmaf(h, w.x, a0); a1 = fmaf(h, w.y, a1);
            a2 = fmaf(h, w.z, a2); a3 = fmaf(h, w.w, a3);
        }
        z1S[row][hg * 4 + 0] = tanhf(a0);
        z1S[row][hg * 4 + 1] = tanhf(a1);
        z1S[row][hg * 4 + 2] = tanhf(a2);
        z1S[row][hg * 4 + 3] = tanhf(a3);
    }
    __syncthreads();

    const float ew = expf(rescale[0]);
    for (int p = tid; p < 16 * 32; p += 256) {
        int row = p >> 5, j = p & 31;
        float acc = b2[j];
#pragma unroll 8
        for (int k = 0; k < ST_HID; k++)
            acc += z1S[row][k] * w2[j * ST_HID + k];
        int grow = row0 + row;
        if (j < ST_OUT)
            out[(size_t)grow * ST_OUT + j] = ew * tanhf(acc);
        else
            out[(size_t)MFLAT * ST_OUT + (size_t)grow * ST_OUT + (j - ST_OUT)] = acc;
    }
}

// ---------------------------------------------------------------------------
extern "C" void kernel_launch(void* const* d_in, const int* in_sizes, int n_in,
                              void* d_out, int out_size) {
    const float* x       = (const float*)d_in[0];
    const float* adj     = (const float*)d_in[1];
    const float* emb_w   = (const float*)d_in[2];
    const float* gc1_w   = (const float*)d_in[3];
    const float* gc2_w   = (const float*)d_in[4];
    const float* gc3_w   = (const float*)d_in[5];
    const float* st_w1   = (const float*)d_in[6];
    const float* st_b1   = (const float*)d_in[7];
    const float* st_w2   = (const float*)d_in[8];
    const float* st_b2   = (const float*)d_in[9];
    const float* rescale = (const float*)d_in[10];
    float* out = (float*)d_out;

    float *adjhi, *adjlo, *supphi, *supplo, *hhi, *hlo, *h, *xhi, *xlo;
    float *c1hi, *c1lo, *w2hi, *w2lo, *w3hi, *w3lo;
    cudaGetSymbolAddress((void**)&adjhi,  g_adjhi);
    cudaGetSymbolAddress((void**)&adjlo,  g_adjlo);
    cudaGetSymbolAddress((void**)&supphi, g_supphi);
    cudaGetSymbolAddress((void**)&supplo, g_supplo);
    cudaGetSymbolAddress((void**)&hhi,    g_hhi);
    cudaGetSymbolAddress((void**)&hlo,    g_hlo);
    cudaGetSymbolAddress((void**)&h,      g_h);
    cudaGetSymbolAddress((void**)&xhi,    g_xhi);
    cudaGetSymbolAddress((void**)&xlo,    g_xlo);
    cudaGetSymbolAddress((void**)&c1hi,   g_c1hi);
    cudaGetSymbolAddress((void**)&c1lo,   g_c1lo);
    cudaGetSymbolAddress((void**)&w2hi,   g_w2hi);
    cudaGetSymbolAddress((void**)&w2lo,   g_w2lo);
    cudaGetSymbolAddress((void**)&w3hi,   g_w3hi);
    cudaGetSymbolAddress((void**)&w3lo,   g_w3lo);

    cudaFuncSetAttribute(agg_wmma<0>, cudaFuncAttributeMaxDynamicSharedMemorySize, AG_SMEM);
    cudaFuncSetAttribute(agg_wmma<1>, cudaFuncAttributeMaxDynamicSharedMemorySize, AG_SMEM);
    cudaFuncSetAttribute(support_wmma<NFEAT>, cudaFuncAttributeMaxDynamicSharedMemorySize, SP_SMEM);
    cudaFuncSetAttribute(support_wmma<NHID>,  cudaFuncAttributeMaxDynamicSharedMemorySize, SP_SMEM);

    // ---- prep: tf32-split everything once ----
    const int adjN4 = (Bq * Eq * Nq * Nq) / 4;
    const int xN4   = (MFLAT * NFEAT) / 4;
    const int wN4   = (Eq * NHID * NHID) / 4;
    split_kernel<<<(adjN4 + 255) / 256, 256>>>(adj, adjhi, adjlo, adjN4);
    split_kernel<<<(xN4 + 255) / 256, 256>>>(x, xhi, xlo, xN4);
    split_kernel<<<(wN4 + 255) / 256, 256>>>(gc2_w, w2hi, w2lo, wN4);
    split_kernel<<<(wN4 + 255) / 256, 256>>>(gc3_w, w3hi, w3lo, wN4);
    c1_split_kernel<<<(Eq * NFEAT * NHID + 255) / 256, 256>>>(emb_w, gc1_w, c1hi, c1lo);

    dim3 sgrid(MFLAT / 64, Eq);     // (384, 3)
    dim3 agrid(Nq / 64, Bq);        // (6, 64)

    // Layer 1 (embedding folded into C1)
    support_wmma<NFEAT><<<sgrid, 256, SP_SMEM>>>(xhi, xlo, c1hi, c1lo, supphi, supplo);
    agg_wmma<0><<<agrid, 256, AG_SMEM>>>(adjhi, adjlo, supphi, supplo, hhi, hlo, h);
    // Layer 2
    support_wmma<NHID><<<sgrid, 256, SP_SMEM>>>(hhi, hlo, w2hi, w2lo, supphi, supplo);
    agg_wmma<0><<<agrid, 256, AG_SMEM>>>(adjhi, adjlo, supphi, supplo, hhi, hlo, h);
    // Layer 3 (no relu, fp32 out)
    support_wmma<NHID><<<sgrid, 256, SP_SMEM>>>(hhi, hlo, w3hi, w3lo, supphi, supplo);
    agg_wmma<1><<<agrid, 256, AG_SMEM>>>(adjhi, adjlo, supphi, supplo, hhi, hlo, h);

    // Head
    head_kernel<<<MFLAT / 16, 256>>>(h, st_w1, st_b1, st_w2, st_b2, rescale, out);
}

// round 6
// speedup vs baseline: 1.1746x; 1.1746x over previous
#include <cuda_runtime.h>
#include <mma.h>
#include <math.h>

using namespace nvcuda;

#define Bq     64
#define Nq     384
#define NFEAT  16
#define Eq     3
#define NHID   128
#define ST_HID 64
#define ST_OUT 16
#define MFLAT  (Bq * Nq)

// ---------------- device scratch ----------------
__device__ float g_adjhi[Bq * Eq * Nq * Nq];    // 113 MB
__device__ float g_adjlo[Bq * Eq * Nq * Nq];    // 113 MB
__device__ float g_supphi[Bq * Eq * Nq * NHID];
__device__ float g_supplo[Bq * Eq * Nq * NHID];
__device__ float g_oe[Bq * Eq * Nq * NHID];     // per-relation fp32 outputs
__device__ float g_c1hi[Eq * NFEAT * NHID];
__device__ float g_c1lo[Eq * NFEAT * NHID];
__device__ float g_w2hi[Eq * NHID * NHID];
__device__ float g_w2lo[Eq * NHID * NHID];
__device__ float g_w3hi[Eq * NHID * NHID];
__device__ float g_w3lo[Eq * NHID * NHID];

// ---------------- tf32 split ----------------
__device__ __forceinline__ float tf32r(float v) {
    unsigned u;
    asm("cvt.rna.tf32.f32 %0, %1;" : "=r"(u) : "f"(v));
    return __uint_as_float(u);
}
__device__ __forceinline__ void split1(float v, float& hi, float& lo) {
    hi = tf32r(v);
    lo = tf32r(v - hi);
}

__global__ void split_kernel(const float* __restrict__ src,
                             float* __restrict__ hi, float* __restrict__ lo,
                             int n4) {
    int i = blockIdx.x * blockDim.x + threadIdx.x;
    if (i >= n4) return;
    float4 v = *(const float4*)(src + (size_t)i * 4);
    float4 h, l;
    split1(v.x, h.x, l.x); split1(v.y, h.y, l.y);
    split1(v.z, h.z, l.z); split1(v.w, h.w, l.w);
    *(float4*)(hi + (size_t)i * 4) = h;
    *(float4*)(lo + (size_t)i * 4) = l;
}

__global__ void c1_split_kernel(const float* __restrict__ emb_w,
                                const float* __restrict__ gc1_w,
                                float* __restrict__ hi, float* __restrict__ lo) {
    int idx = blockIdx.x * 256 + threadIdx.x;
    if (idx >= Eq * NFEAT * NHID) return;
    int h = idx & 127, f = (idx >> 7) & 15, e = idx >> 11;
    float acc = 0.f;
#pragma unroll
    for (int d = 0; d < NFEAT; d++)
        acc += emb_w[d * NFEAT + f] * gc1_w[(e * NFEAT + d) * NHID + h];
    float hh, ll;
    split1(acc, hh, ll);
    hi[idx] = hh; lo[idx] = ll;
}

// ---------------- smem layouts ----------------
// agg: A 128x32 (ld 36) hi/lo, B 32x128 (ld 132) hi/lo
#define AG_LDA 36
#define LDB    132
#define AG_ALO_OFF (128 * AG_LDA)
#define AG_B_BASE  (2 * 128 * AG_LDA)
#define AG_BLO_OFF (32 * LDB)
#define AG_SMEM ((AG_B_BASE + 2 * 32 * LDB) * 4)     // 70656 B
// support: A 128x16 (ld 20) hi/lo, B 16x128 (ld 132) hi/lo
#define SP_LDA 20
#define SP_ALO_OFF (128 * SP_LDA)
#define SP_B_BASE  (2 * 128 * SP_LDA)
#define SP_BLO_OFF (16 * LDB)
#define SP_SMEM ((SP_B_BASE + 2 * 16 * LDB) * 4)     // 37376 B

typedef wmma::fragment<wmma::matrix_a, 16, 16, 8, wmma::precision::tf32, wmma::row_major> AFrag;
typedef wmma::fragment<wmma::matrix_b, 16, 16, 8, wmma::precision::tf32, wmma::row_major> BFrag;
typedef wmma::fragment<wmma::accumulator, 16, 16, 8, float> CFrag;

// ---------------------------------------------------------------------------
// Per-relation aggregation: oe[b,e,m,:] = act( adj[b,e,m,:] @ supp[b,e,:,:] )
// BM=128, BN=128, BK=32, 256 thr (8 warps, 4x2), warp tile 32x64, 3xTF32.
// grid: (Nq/128=3, Bq, Eq)
// ---------------------------------------------------------------------------
template <int RELU>
__global__ __launch_bounds__(256, 2)
void agg_wmma(const float* __restrict__ adjhi, const float* __restrict__ adjlo,
              const float* __restrict__ shi, const float* __restrict__ slo,
              float* __restrict__ oe) {
    extern __shared__ float sm[];
    float* Ahi = sm;
    float* Alo = sm + AG_ALO_OFF;
    float* Bhi = sm + AG_B_BASE;
    float* Blo = sm + AG_B_BASE + AG_BLO_OFF;

    const int tid = threadIdx.x;
    const int wid = tid >> 5;
    const int wm = wid >> 1, wn = wid & 1;     // 4 x 2 warps
    const int m0 = blockIdx.x * 128;
    const int b = blockIdx.y, e = blockIdx.z;

    const float* aH = adjhi + ((size_t)(b * Eq + e) * Nq + m0) * Nq;
    const float* aL = adjlo + ((size_t)(b * Eq + e) * Nq + m0) * Nq;
    const float* bH = shi + (size_t)(b * Eq + e) * Nq * NHID;
    const float* bL = slo + (size_t)(b * Eq + e) * Nq * NHID;

    CFrag c[2][4];
#pragma unroll
    for (int i = 0; i < 2; i++)
#pragma unroll
        for (int j = 0; j < 4; j++) wmma::fill_fragment(c[i][j], 0.f);

    for (int kt = 0; kt < Nq / 32; kt++) {
        // A tiles: 128x32 floats hi/lo -> 4 float4/thread each
#pragma unroll
        for (int t = 0; t < 4; t++) {
            int idx = tid + t * 256;
            int r = idx >> 3, c4 = idx & 7;
            size_t g = (size_t)r * Nq + kt * 32 + c4 * 4;
            *(float4*)&Ahi[r * AG_LDA + c4 * 4] = *(const float4*)(aH + g);
            *(float4*)&Alo[r * AG_LDA + c4 * 4] = *(const float4*)(aL + g);
        }
        // B tiles: 32x128 floats hi/lo -> 4 float4/thread each
#pragma unroll
        for (int t = 0; t < 4; t++) {
            int idx = tid + t * 256;
            int r = idx >> 5, c4 = idx & 31;
            size_t g = (size_t)(kt * 32 + r) * NHID + c4 * 4;
            *(float4*)&Bhi[r * LDB + c4 * 4] = *(const float4*)(bH + g);
            *(float4*)&Blo[r * LDB + c4 * 4] = *(const float4*)(bL + g);
        }
        __syncthreads();

#pragma unroll
        for (int k8 = 0; k8 < 4; k8++) {
            AFrag afH[2], afL[2];
#pragma unroll
            for (int i = 0; i < 2; i++) {
                const float* p = &Ahi[(wm * 32 + i * 16) * AG_LDA + k8 * 8];
                wmma::load_matrix_sync(afH[i], p, AG_LDA);
                wmma::load_matrix_sync(afL[i], p + AG_ALO_OFF, AG_LDA);
            }
#pragma unroll
            for (int j = 0; j < 4; j++) {
                BFrag bfH, bfL;
                const float* p = &Bhi[(k8 * 8) * LDB + wn * 64 + j * 16];
                wmma::load_matrix_sync(bfH, p, LDB);
                wmma::load_matrix_sync(bfL, p + AG_BLO_OFF, LDB);
#pragma unroll
                for (int i = 0; i < 2; i++) {
                    wmma::mma_sync(c[i][j], afH[i], bfH, c[i][j]);
                    wmma::mma_sync(c[i][j], afH[i], bfL, c[i][j]);
                    wmma::mma_sync(c[i][j], afL[i], bfH, c[i][j]);
                }
            }
        }
        __syncthreads();
    }

    // Epilogue: optional relu, store fp32 per-relation direct to global
#pragma unroll
    for (int i = 0; i < 2; i++)
#pragma unroll
        for (int j = 0; j < 4; j++) {
            if (RELU) {
#pragma unroll
                for (int t = 0; t < c[i][j].num_elements; t++)
                    c[i][j].x[t] = fmaxf(c[i][j].x[t], 0.f);
            }
            float* op = oe + ((size_t)(b * Eq + e) * Nq + m0 + wm * 32 + i * 16) * NHID
                           + wn * 64 + j * 16;
            wmma::store_matrix_sync(op, c[i][j], NHID, wmma::mem_row_major);
        }
}

// ---------------------------------------------------------------------------
// Support: supp[b,e,n,:] = rowin @ W[e], rowin = x (NE=1) or sum_e' oe (NE=3),
// split to tf32 hi/lo on the fly. Output tf32-split.
// BM=128 rows of MFLAT, BN=128, BK=16. grid: (MFLAT/128=192, Eq)
// ---------------------------------------------------------------------------
template <int K, int NE>
__global__ __launch_bounds__(256, 2)
void support_wmma(const float* __restrict__ in,
                  const float* __restrict__ whi, const float* __restrict__ wlo,
                  float* __restrict__ supphi, float* __restrict__ supplo) {
    extern __shared__ float sm[];
    float* Ahi = sm;
    float* Alo = sm + SP_ALO_OFF;
    float* Bhi = sm + SP_B_BASE;
    float* Blo = sm + SP_B_BASE + SP_BLO_OFF;

    const int tid = threadIdx.x;
    const int wid = tid >> 5;
    const int wm = wid >> 1, wn = wid & 1;
    const int e = blockIdx.y;
    const int m0 = blockIdx.x * 128;
    const int b = m0 / Nq, n0 = m0 % Nq;

    // row stride of the input is K in both cases (x: K=16; oe: NHID=128=K)
    const float* aBase = (NE == 1)
        ? in + (size_t)m0 * K
        : in + (size_t)(b * Eq) * Nq * NHID + (size_t)n0 * NHID;
    const size_t eS = (size_t)Nq * NHID;
    const float* wH = whi + (size_t)e * K * NHID;
    const float* wL = wlo + (size_t)e * K * NHID;

    CFrag c[2][4];
#pragma unroll
    for (int i = 0; i < 2; i++)
#pragma unroll
        for (int j = 0; j < 4; j++) wmma::fill_fragment(c[i][j], 0.f);

#pragma unroll
    for (int kt = 0; kt < K / 16; kt++) {
        // A: 128x16 fp32 -> sum relations (NE=3) -> split -> smem (2 f4/thread)
#pragma unroll
        for (int t = 0; t < 2; t++) {
            int idx = tid + t * 256;
            int r = idx >> 2, c4 = idx & 3;
            const float* rp = aBase + (size_t)r * K + kt * 16 + c4 * 4;
            float4 v = *(const float4*)rp;
            if (NE == 3) {
                float4 v1 = *(const float4*)(rp + eS);
                float4 v2 = *(const float4*)(rp + 2 * eS);
                v.x += v1.x + v2.x; v.y += v1.y + v2.y;
                v.z += v1.z + v2.z; v.w += v1.w + v2.w;
            }
            float4 h, l;
            split1(v.x, h.x, l.x); split1(v.y, h.y, l.y);
            split1(v.z, h.z, l.z); split1(v.w, h.w, l.w);
            *(float4*)&Ahi[r * SP_LDA + c4 * 4] = h;
            *(float4*)&Alo[r * SP_LDA + c4 * 4] = l;
        }
        // B: 16x128 pre-split weights (2 f4/thread each)
#pragma unroll
        for (int t = 0; t < 2; t++) {
            int idx = tid + t * 256;
            int r = idx >> 5, c4 = idx & 31;
            size_t g = (size_t)(kt * 16 + r) * NHID + c4 * 4;
            *(float4*)&Bhi[r * LDB + c4 * 4] = *(const float4*)(wH + g);
            *(float4*)&Blo[r * LDB + c4 * 4] = *(const float4*)(wL + g);
        }
        __syncthreads();

#pragma unroll
        for (int k8 = 0; k8 < 2; k8++) {
            AFrag afH[2], afL[2];
#pragma unroll
            for (int i = 0; i < 2; i++) {
                const float* p = &Ahi[(wm * 32 + i * 16) * SP_LDA + k8 * 8];
                wmma::load_matrix_sync(afH[i], p, SP_LDA);
                wmma::load_matrix_sync(afL[i], p + SP_ALO_OFF, SP_LDA);
            }
#pragma unroll
            for (int j = 0; j < 4; j++) {
                BFrag bfH, bfL;
                const float* p = &Bhi[(k8 * 8) * LDB + wn * 64 + j * 16];
                wmma::load_matrix_sync(bfH, p, LDB);
                wmma::load_matrix_sync(bfL, p + SP_BLO_OFF, LDB);
#pragma unroll
                for (int i = 0; i < 2; i++) {
                    wmma::mma_sync(c[i][j], afH[i], bfH, c[i][j]);
                    wmma::mma_sync(c[i][j], afH[i], bfL, c[i][j]);
                    wmma::mma_sync(c[i][j], afL[i], bfH, c[i][j]);
                }
            }
        }
        __syncthreads();
    }

    // Epilogue: tf32-split the fragments, two direct global stores
#pragma unroll
    for (int i = 0; i < 2; i++)
#pragma unroll
        for (int j = 0; j < 4; j++) {
            CFrag hf, lf;
#pragma unroll
            for (int t = 0; t < c[i][j].num_elements; t++) {
                float hh, ll;
                split1(c[i][j].x[t], hh, ll);
                hf.x[t] = hh; lf.x[t] = ll;
            }
            size_t o = ((size_t)(b * Eq + e) * Nq + n0 + wm * 32 + i * 16) * NHID
                     + wn * 64 + j * 16;
            wmma::store_matrix_sync(supphi + o, hf, NHID, wmma::mem_row_major);
            wmma::store_matrix_sync(supplo + o, lf, NHID, wmma::mem_row_major);
        }
}

// ---------------------------------------------------------------------------
// Head: rows summed over relations, then 2-layer MLP + tanh/scale outputs
// ---------------------------------------------------------------------------
__global__ __launch_bounds__(256)
void head_kernel(const float* __restrict__ oe,
                 const float* __restrict__ w1, const float* __restrict__ b1,
                 const float* __restrict__ w2, const float* __restrict__ b2,
                 const float* __restrict__ rescale, float* __restrict__ out) {
    __shared__ float w1T[NHID][68];
    __shared__ float hS[16][NHID];
    __shared__ float z1S[16][68];

    const int tid = threadIdx.x;
    const int row0 = blockIdx.x * 16;
    const int b = row0 / Nq;
    const int n0 = row0 % Nq;

    for (int i = tid; i < ST_HID * NHID; i += 256) {
        int hid = i >> 7, d = i & 127;
        w1T[d][hid] = w1[i];
    }
    const float* base = oe + (size_t)(b * Eq) * Nq * NHID + (size_t)n0 * NHID;
    const size_t eS = (size_t)Nq * NHID;
#pragma unroll
    for (int t = 0; t < 2; t++) {
        int idx = tid + t * 256;
        int r = idx >> 5, c = idx & 31;
        float4 v0 = *(const float4*)(base + (size_t)r * NHID + c * 4);
        float4 v1 = *(const float4*)(base + eS + (size_t)r * NHID + c * 4);
        float4 v2 = *(const float4*)(base + 2 * eS + (size_t)r * NHID + c * 4);
        *(float4*)&hS[r][c * 4] = make_float4(v0.x + v1.x + v2.x, v0.y + v1.y + v2.y,
                                              v0.z + v1.z + v2.z, v0.w + v1.w + v2.w);
    }
    __syncthreads();

    {
        int row = tid >> 4, hg = tid & 15;
        float a0 = b1[hg * 4 + 0], a1 = b1[hg * 4 + 1];
        float a2 = b1[hg * 4 + 2], a3 = b1[hg * 4 + 3];
#pragma unroll 8
        for (int d = 0; d < NHID; d++) {
            float h = hS[row][d];
            float4 w = *(const float4*)&w1T[d][hg * 4];
            a0 = fmaf(h, w.x, a0); a1 = fmaf(h, w.y, a1);
            a2 = fmaf(h, w.z, a2); a3 = fmaf(h, w.w, a3);
        }
        z1S[row][hg * 4 + 0] = tanhf(a0);
        z1S[row][hg * 4 + 1] = tanhf(a1);
        z1S[row][hg * 4 + 2] = tanhf(a2);
        z1S[row][hg * 4 + 3] = tanhf(a3);
    }
    __syncthreads();

    const float ew = expf(rescale[0]);
    for (int p = tid; p < 16 * 32; p += 256) {
        int row = p >> 5, j = p & 31;
        float acc = b2[j];
#pragma unroll 8
        for (int k = 0; k < ST_HID; k++)
            acc += z1S[row][k] * w2[j * ST_HID + k];
        int grow = row0 + row;
        if (j < ST_OUT)
            out[(size_t)grow * ST_OUT + j] = ew * tanhf(acc);
        else
            out[(size_t)MFLAT * ST_OUT + (size_t)grow * ST_OUT + (j - ST_OUT)] = acc;
    }
}

// ---------------------------------------------------------------------------
extern "C" void kernel_launch(void* const* d_in, const int* in_sizes, int n_in,
                              void* d_out, int out_size) {
    const float* x       = (const float*)d_in[0];
    const float* adj     = (const float*)d_in[1];
    const float* emb_w   = (const float*)d_in[2];
    const float* gc1_w   = (const float*)d_in[3];
    const float* gc2_w   = (const float*)d_in[4];
    const float* gc3_w   = (const float*)d_in[5];
    const float* st_w1   = (const float*)d_in[6];
    const float* st_b1   = (const float*)d_in[7];
    const float* st_w2   = (const float*)d_in[8];
    const float* st_b2   = (const float*)d_in[9];
    const float* rescale = (const float*)d_in[10];
    float* out = (float*)d_out;

    float *adjhi, *adjlo, *supphi, *supplo, *oe;
    float *c1hi, *c1lo, *w2hi, *w2lo, *w3hi, *w3lo;
    cudaGetSymbolAddress((void**)&adjhi,  g_adjhi);
    cudaGetSymbolAddress((void**)&adjlo,  g_adjlo);
    cudaGetSymbolAddress((void**)&supphi, g_supphi);
    cudaGetSymbolAddress((void**)&supplo, g_supplo);
    cudaGetSymbolAddress((void**)&oe,     g_oe);
    cudaGetSymbolAddress((void**)&c1hi,   g_c1hi);
    cudaGetSymbolAddress((void**)&c1lo,   g_c1lo);
    cudaGetSymbolAddress((void**)&w2hi,   g_w2hi);
    cudaGetSymbolAddress((void**)&w2lo,   g_w2lo);
    cudaGetSymbolAddress((void**)&w3hi,   g_w3hi);
    cudaGetSymbolAddress((void**)&w3lo,   g_w3lo);

    cudaFuncSetAttribute(agg_wmma<1>, cudaFuncAttributeMaxDynamicSharedMemorySize, AG_SMEM);
    cudaFuncSetAttribute(agg_wmma<0>, cudaFuncAttributeMaxDynamicSharedMemorySize, AG_SMEM);
    cudaFuncSetAttribute(support_wmma<NFEAT, 1>, cudaFuncAttributeMaxDynamicSharedMemorySize, SP_SMEM);
    cudaFuncSetAttribute(support_wmma<NHID, 3>,  cudaFuncAttributeMaxDynamicSharedMemorySize, SP_SMEM);

    // prep (5 launches so ncu -s 5 captures the first agg)
    const int adjN4 = (Bq * Eq * Nq * Nq) / 4;
    const int wN4   = (Eq * NHID * NHID) / 4;
    split_kernel<<<(adjN4 + 255) / 256, 256>>>(adj, adjhi, adjlo, adjN4);
    split_kernel<<<(wN4 + 255) / 256, 256>>>(gc2_w, w2hi, w2lo, wN4);
    split_kernel<<<(wN4 + 255) / 256, 256>>>(gc3_w, w3hi, w3lo, wN4);
    c1_split_kernel<<<(Eq * NFEAT * NHID + 255) / 256, 256>>>(emb_w, gc1_w, c1hi, c1lo);

    dim3 sgrid(MFLAT / 128, Eq);      // (192, 3)
    dim3 agrid(Nq / 128, Bq, Eq);     // (3, 64, 3)

    // Layer 1 (embedding folded into C1)
    support_wmma<NFEAT, 1><<<sgrid, 256, SP_SMEM>>>(x, c1hi, c1lo, supphi, supplo);
    agg_wmma<1><<<agrid, 256, AG_SMEM>>>(adjhi, adjlo, supphi, supplo, oe);
    // Layer 2
    support_wmma<NHID, 3><<<sgrid, 256, SP_SMEM>>>(oe, w2hi, w2lo, supphi, supplo);
    agg_wmma<1><<<agrid, 256, AG_SMEM>>>(adjhi, adjlo, supphi, supplo, oe);
    // Layer 3 (no relu)
    support_wmma<NHID, 3><<<sgrid, 256, SP_SMEM>>>(oe, w3hi, w3lo, supphi, supplo);
    agg_wmma<0><<<agrid, 256, AG_SMEM>>>(adjhi, adjlo, supphi, supplo, oe);

    // Head (sums relations on load)
    head_kernel<<<MFLAT / 16, 256>>>(oe, st_w1, st_b1, st_w2, st_b2, rescale, out);
}

// round 7
// speedup vs baseline: 1.2069x; 1.0275x over previous
#include <cuda_runtime.h>
#include <mma.h>
#include <math.h>

using namespace nvcuda;

#define Bq     64
#define Nq     384
#define NFEAT  16
#define Eq     3
#define NHID   128
#define ST_HID 64
#define ST_OUT 16
#define MFLAT  (Bq * Nq)

// ---------------- device scratch ----------------
__device__ float g_adjhi[Bq * Eq * Nq * Nq];
__device__ float g_adjlo[Bq * Eq * Nq * Nq];
__device__ float g_supphi[Bq * Eq * Nq * NHID];
__device__ float g_supplo[Bq * Eq * Nq * NHID];
__device__ float g_oe[Bq * Eq * Nq * NHID];
__device__ float g_c1hi[Eq * NFEAT * NHID];
__device__ float g_c1lo[Eq * NFEAT * NHID];
__device__ float g_w2hi[Eq * NHID * NHID];
__device__ float g_w2lo[Eq * NHID * NHID];
__device__ float g_w3hi[Eq * NHID * NHID];
__device__ float g_w3lo[Eq * NHID * NHID];

// ---------------- tf32 split ----------------
__device__ __forceinline__ float tf32r(float v) {
    unsigned u;
    asm("cvt.rna.tf32.f32 %0, %1;" : "=r"(u) : "f"(v));
    return __uint_as_float(u);
}
__device__ __forceinline__ void split1(float v, float& hi, float& lo) {
    hi = tf32r(v);
    lo = tf32r(v - hi);
}

__global__ void split_kernel(const float* __restrict__ src,
                             float* __restrict__ hi, float* __restrict__ lo,
                             int n4) {
    int i = blockIdx.x * blockDim.x + threadIdx.x;
    if (i >= n4) return;
    float4 v = *(const float4*)(src + (size_t)i * 4);
    float4 h, l;
    split1(v.x, h.x, l.x); split1(v.y, h.y, l.y);
    split1(v.z, h.z, l.z); split1(v.w, h.w, l.w);
    *(float4*)(hi + (size_t)i * 4) = h;
    *(float4*)(lo + (size_t)i * 4) = l;
}

__global__ void c1_split_kernel(const float* __restrict__ emb_w,
                                const float* __restrict__ gc1_w,
                                float* __restrict__ hi, float* __restrict__ lo) {
    int idx = blockIdx.x * 256 + threadIdx.x;
    if (idx >= Eq * NFEAT * NHID) return;
    int h = idx & 127, f = (idx >> 7) & 15, e = idx >> 11;
    float acc = 0.f;
#pragma unroll
    for (int d = 0; d < NFEAT; d++)
        acc += emb_w[d * NFEAT + f] * gc1_w[(e * NFEAT + d) * NHID + h];
    float hh, ll;
    split1(acc, hh, ll);
    hi[idx] = hh; lo[idx] = ll;
}

// ---------------- cp.async ----------------
__device__ __forceinline__ void cpa16(unsigned s, const void* g) {
    asm volatile("cp.async.cg.shared.global [%0], [%1], 16;" :: "r"(s), "l"(g));
}
#define CPA_COMMIT() asm volatile("cp.async.commit_group;" ::: "memory")
#define CPA_WAIT(N)  asm volatile("cp.async.wait_group %0;" :: "n"(N) : "memory")

// ---------------- smem layouts ----------------
// agg stage: Ahi 128x16 (ld20), Alo, Bhi 16x128 (ld132), Blo
#define AG_LDA 20
#define LDB    132
#define ST_AHI 0
#define ST_ALO (128 * AG_LDA)
#define ST_BHI (2 * 128 * AG_LDA)
#define ST_BLO (ST_BHI + 16 * LDB)
#define STAGE_FLTS (ST_BLO + 16 * LDB)          // 9344 floats
#define AG_SMEM (2 * STAGE_FLTS * 4)            // 74752 B

// support: A 128x16 (ld 20) hi/lo, B 16x128 (ld 132) hi/lo  (single stage)
#define SP_LDA 20
#define SP_ALO_OFF (128 * SP_LDA)
#define SP_B_BASE  (2 * 128 * SP_LDA)
#define SP_BLO_OFF (16 * LDB)
#define SP_SMEM ((SP_B_BASE + 2 * 16 * LDB) * 4)

typedef wmma::fragment<wmma::matrix_a, 16, 16, 8, wmma::precision::tf32, wmma::row_major> AFrag;
typedef wmma::fragment<wmma::matrix_b, 16, 16, 8, wmma::precision::tf32, wmma::row_major> BFrag;
typedef wmma::fragment<wmma::accumulator, 16, 16, 8, float> CFrag;

// ---------------------------------------------------------------------------
// Per-relation aggregation, double-buffered cp.async:
//   oe[b,e,m,:] = act( adj[b,e,m,:] @ supp[b,e,:,:] ),  3xTF32
// BM=128, BN=128, BK=16, 256 thr (8 warps 4x2), warp tile 32x64.
// grid: (3, Bq, Eq)
// ---------------------------------------------------------------------------
__device__ __forceinline__ void ag_load_stage(unsigned sb, const float* aH,
                                              const float* aL, const float* bH,
                                              const float* bL, int kt, int tid) {
#pragma unroll
    for (int t = 0; t < 2; t++) {
        int idx = tid + t * 256;               // [0,512)
        int r = idx >> 2, c4 = idx & 3;
        size_t g = (size_t)r * Nq + kt * 16 + c4 * 4;
        cpa16(sb + (ST_AHI + r * AG_LDA + c4 * 4) * 4, aH + g);
        cpa16(sb + (ST_ALO + r * AG_LDA + c4 * 4) * 4, aL + g);
    }
#pragma unroll
    for (int t = 0; t < 2; t++) {
        int idx = tid + t * 256;
        int r = idx >> 5, c4 = idx & 31;
        size_t g = (size_t)(kt * 16 + r) * NHID + c4 * 4;
        cpa16(sb + (ST_BHI + r * LDB + c4 * 4) * 4, bH + g);
        cpa16(sb + (ST_BLO + r * LDB + c4 * 4) * 4, bL + g);
    }
}

template <int RELU>
__global__ __launch_bounds__(256, 2)
void agg_wmma(const float* __restrict__ adjhi, const float* __restrict__ adjlo,
              const float* __restrict__ shi, const float* __restrict__ slo,
              float* __restrict__ oe) {
    extern __shared__ float sm[];
    const unsigned sbase = (unsigned)__cvta_generic_to_shared(sm);

    const int tid = threadIdx.x;
    const int wid = tid >> 5;
    const int wm = wid >> 1, wn = wid & 1;     // 4 x 2 warps
    const int m0 = blockIdx.x * 128;
    const int b = blockIdx.y, e = blockIdx.z;

    const float* aH = adjhi + ((size_t)(b * Eq + e) * Nq + m0) * Nq;
    const float* aL = adjlo + ((size_t)(b * Eq + e) * Nq + m0) * Nq;
    const float* bH = shi + (size_t)(b * Eq + e) * Nq * NHID;
    const float* bL = slo + (size_t)(b * Eq + e) * Nq * NHID;

    CFrag c[2][4];
#pragma unroll
    for (int i = 0; i < 2; i++)
#pragma unroll
        for (int j = 0; j < 4; j++) wmma::fill_fragment(c[i][j], 0.f);

    constexpr int KT = Nq / 16;                // 24
    ag_load_stage(sbase, aH, aL, bH, bL, 0, tid);
    CPA_COMMIT();

    for (int kt = 0; kt < KT; kt++) {
        if (kt + 1 < KT) {
            ag_load_stage(sbase + ((kt + 1) & 1) * STAGE_FLTS * 4,
                          aH, aL, bH, bL, kt + 1, tid);
            CPA_COMMIT();
            CPA_WAIT(1);
        } else {
            CPA_WAIT(0);
        }
        __syncthreads();

        const float* S = sm + (kt & 1) * STAGE_FLTS;
#pragma unroll
        for (int k8 = 0; k8 < 2; k8++) {
            AFrag afH[2], afL[2];
#pragma unroll
            for (int i = 0; i < 2; i++) {
                const float* p = &S[ST_AHI + (wm * 32 + i * 16) * AG_LDA + k8 * 8];
                wmma::load_matrix_sync(afH[i], p, AG_LDA);
                wmma::load_matrix_sync(afL[i], p + (ST_ALO - ST_AHI), AG_LDA);
            }
#pragma unroll
            for (int j = 0; j < 4; j++) {
                BFrag bfH, bfL;
                const float* p = &S[ST_BHI + (k8 * 8) * LDB + wn * 64 + j * 16];
                wmma::load_matrix_sync(bfH, p, LDB);
                wmma::load_matrix_sync(bfL, p + (ST_BLO - ST_BHI), LDB);
#pragma unroll
                for (int i = 0; i < 2; i++) {
                    wmma::mma_sync(c[i][j], afH[i], bfH, c[i][j]);
                    wmma::mma_sync(c[i][j], afH[i], bfL, c[i][j]);
                    wmma::mma_sync(c[i][j], afL[i], bfH, c[i][j]);
                }
            }
        }
        __syncthreads();
    }

#pragma unroll
    for (int i = 0; i < 2; i++)
#pragma unroll
        for (int j = 0; j < 4; j++) {
            if (RELU) {
#pragma unroll
                for (int t = 0; t < c[i][j].num_elements; t++)
                    c[i][j].x[t] = fmaxf(c[i][j].x[t], 0.f);
            }
            float* op = oe + ((size_t)(b * Eq + e) * Nq + m0 + wm * 32 + i * 16) * NHID
                           + wn * 64 + j * 16;
            wmma::store_matrix_sync(op, c[i][j], NHID, wmma::mem_row_major);
        }
}

// ---------------------------------------------------------------------------
// Support: supp[b,e,n,:] = rowin @ W[e], rowin = x (NE=1) or sum_e' oe (NE=3)
// ---------------------------------------------------------------------------
template <int K, int NE>
__global__ __launch_bounds__(256, 2)
void support_wmma(const float* __restrict__ in,
                  const float* __restrict__ whi, const float* __restrict__ wlo,
                  float* __restrict__ supphi, float* __restrict__ supplo) {
    extern __shared__ float sm[];
    float* Ahi = sm;
    float* Alo = sm + SP_ALO_OFF;
    float* Bhi = sm + SP_B_BASE;
    float* Blo = sm + SP_B_BASE + SP_BLO_OFF;

    const int tid = threadIdx.x;
    const int wid = tid >> 5;
    const int wm = wid >> 1, wn = wid & 1;
    const int e = blockIdx.y;
    const int m0 = blockIdx.x * 128;
    const int b = m0 / Nq, n0 = m0 % Nq;

    const float* aBase = (NE == 1)
        ? in + (size_t)m0 * K
        : in + (size_t)(b * Eq) * Nq * NHID + (size_t)n0 * NHID;
    const size_t eS = (size_t)Nq * NHID;
    const float* wH = whi + (size_t)e * K * NHID;
    const float* wL = wlo + (size_t)e * K * NHID;

    CFrag c[2][4];
#pragma unroll
    for (int i = 0; i < 2; i++)
#pragma unroll
        for (int j = 0; j < 4; j++) wmma::fill_fragment(c[i][j], 0.f);

#pragma unroll
    for (int kt = 0; kt < K / 16; kt++) {
#pragma unroll
        for (int t = 0; t < 2; t++) {
            int idx = tid + t * 256;
            int r = idx >> 2, c4 = idx & 3;
            const float* rp = aBase + (size_t)r * K + kt * 16 + c4 * 4;
            float4 v = *(const float4*)rp;
            if (NE == 3) {
                float4 v1 = *(const float4*)(rp + eS);
                float4 v2 = *(const float4*)(rp + 2 * eS);
                v.x += v1.x + v2.x; v.y += v1.y + v2.y;
                v.z += v1.z + v2.z; v.w += v1.w + v2.w;
            }
            float4 h, l;
            split1(v.x, h.x, l.x); split1(v.y, h.y, l.y);
            split1(v.z, h.z, l.z); split1(v.w, h.w, l.w);
            *(float4*)&Ahi[r * SP_LDA + c4 * 4] = h;
            *(float4*)&Alo[r * SP_LDA + c4 * 4] = l;
        }
#pragma unroll
        for (int t = 0; t < 2; t++) {
            int idx = tid + t * 256;
            int r = idx >> 5, c4 = idx & 31;
            size_t g = (size_t)(kt * 16 + r) * NHID + c4 * 4;
            *(float4*)&Bhi[r * LDB + c4 * 4] = *(const float4*)(wH + g);
            *(float4*)&Blo[r * LDB + c4 * 4] = *(const float4*)(wL + g);
        }
        __syncthreads();

#pragma unroll
        for (int k8 = 0; k8 < 2; k8++) {
            AFrag afH[2], afL[2];
#pragma unroll
            for (int i = 0; i < 2; i++) {
                const float* p = &Ahi[(wm * 32 + i * 16) * SP_LDA + k8 * 8];
                wmma::load_matrix_sync(afH[i], p, SP_LDA);
                wmma::load_matrix_sync(afL[i], p + SP_ALO_OFF, SP_LDA);
            }
#pragma unroll
            for (int j = 0; j < 4; j++) {
                BFrag bfH, bfL;
                const float* p = &Bhi[(k8 * 8) * LDB + wn * 64 + j * 16];
                wmma::load_matrix_sync(bfH, p, LDB);
                wmma::load_matrix_sync(bfL, p + SP_BLO_OFF, LDB);
#pragma unroll
                for (int i = 0; i < 2; i++) {
                    wmma::mma_sync(c[i][j], afH[i], bfH, c[i][j]);
                    wmma::mma_sync(c[i][j], afH[i], bfL, c[i][j]);
                    wmma::mma_sync(c[i][j], afL[i], bfH, c[i][j]);
                }
            }
        }
        __syncthreads();
    }

#pragma unroll
    for (int i = 0; i < 2; i++)
#pragma unroll
        for (int j = 0; j < 4; j++) {
            CFrag hf, lf;
#pragma unroll
            for (int t = 0; t < c[i][j].num_elements; t++) {
                float hh, ll;
                split1(c[i][j].x[t], hh, ll);
                hf.x[t] = hh; lf.x[t] = ll;
            }
            size_t o = ((size_t)(b * Eq + e) * Nq + n0 + wm * 32 + i * 16) * NHID
                     + wn * 64 + j * 16;
            wmma::store_matrix_sync(supphi + o, hf, NHID, wmma::mem_row_major);
            wmma::store_matrix_sync(supplo + o, lf, NHID, wmma::mem_row_major);
        }
}

// ---------------------------------------------------------------------------
// Head
// ---------------------------------------------------------------------------
__global__ __launch_bounds__(256)
void head_kernel(const float* __restrict__ oe,
                 const float* __restrict__ w1, const float* __restrict__ b1,
                 const float* __restrict__ w2, const float* __restrict__ b2,
                 const float* __restrict__ rescale, float* __restrict__ out) {
    __shared__ float w1T[NHID][68];
    __shared__ float hS[16][NHID];
    __shared__ float z1S[16][68];

    const int tid = threadIdx.x;
    const int row0 = blockIdx.x * 16;
    const int b = row0 / Nq;
    const int n0 = row0 % Nq;

    for (int i = tid; i < ST_HID * NHID; i += 256) {
        int hid = i >> 7, d = i & 127;
        w1T[d][hid] = w1[i];
    }
    const float* base = oe + (size_t)(b * Eq) * Nq * NHID + (size_t)n0 * NHID;
    const size_t eS = (size_t)Nq * NHID;
#pragma unroll
    for (int t = 0; t < 2; t++) {
        int idx = tid + t * 256;
        int r = idx >> 5, c = idx & 31;
        float4 v0 = *(const float4*)(base + (size_t)r * NHID + c * 4);
        float4 v1 = *(const float4*)(base + eS + (size_t)r * NHID + c * 4);
        float4 v2 = *(const float4*)(base + 2 * eS + (size_t)r * NHID + c * 4);
        *(float4*)&hS[r][c * 4] = make_float4(v0.x + v1.x + v2.x, v0.y + v1.y + v2.y,
                                              v0.z + v1.z + v2.z, v0.w + v1.w + v2.w);
    }
    __syncthreads();

    {
        int row = tid >> 4, hg = tid & 15;
        float a0 = b1[hg * 4 + 0], a1 = b1[hg * 4 + 1];
        float a2 = b1[hg * 4 + 2], a3 = b1[hg * 4 + 3];
#pragma unroll 8
        for (int d = 0; d < NHID; d++) {
            float h = hS[row][d];
            float4 w = *(const float4*)&w1T[d][hg * 4];
            a0 = fmaf(h, w.x, a0); a1 = fmaf(h, w.y, a1);
            a2 = fmaf(h, w.z, a2); a3 = fmaf(h, w.w, a3);
        }
        z1S[row][hg * 4 + 0] = tanhf(a0);
        z1S[row][hg * 4 + 1] = tanhf(a1);
        z1S[row][hg * 4 + 2] = tanhf(a2);
        z1S[row][hg * 4 + 3] = tanhf(a3);
    }
    __syncthreads();

    const float ew = expf(rescale[0]);
    for (int p = tid; p < 16 * 32; p += 256) {
        int row = p >> 5, j = p & 31;
        float acc = b2[j];
#pragma unroll 8
        for (int k = 0; k < ST_HID; k++)
            acc += z1S[row][k] * w2[j * ST_HID + k];
        int grow = row0 + row;
        if (j < ST_OUT)
            out[(size_t)grow * ST_OUT + j] = ew * tanhf(acc);
        else
            out[(size_t)MFLAT * ST_OUT + (size_t)grow * ST_OUT + (j - ST_OUT)] = acc;
    }
}

// ---------------------------------------------------------------------------
extern "C" void kernel_launch(void* const* d_in, const int* in_sizes, int n_in,
                              void* d_out, int out_size) {
    const float* x       = (const float*)d_in[0];
    const float* adj     = (const float*)d_in[1];
    const float* emb_w   = (const float*)d_in[2];
    const float* gc1_w   = (const float*)d_in[3];
    const float* gc2_w   = (const float*)d_in[4];
    const float* gc3_w   = (const float*)d_in[5];
    const float* st_w1   = (const float*)d_in[6];
    const float* st_b1   = (const float*)d_in[7];
    const float* st_w2   = (const float*)d_in[8];
    const float* st_b2   = (const float*)d_in[9];
    const float* rescale = (const float*)d_in[10];
    float* out = (float*)d_out;

    float *adjhi, *adjlo, *supphi, *supplo, *oe;
    float *c1hi, *c1lo, *w2hi, *w2lo, *w3hi, *w3lo;
    cudaGetSymbolAddress((void**)&adjhi,  g_adjhi);
    cudaGetSymbolAddress((void**)&adjlo,  g_adjlo);
    cudaGetSymbolAddress((void**)&supphi, g_supphi);
    cudaGetSymbolAddress((void**)&supplo, g_supplo);
    cudaGetSymbolAddress((void**)&oe,     g_oe);
    cudaGetSymbolAddress((void**)&c1hi,   g_c1hi);
    cudaGetSymbolAddress((void**)&c1lo,   g_c1lo);
    cudaGetSymbolAddress((void**)&w2hi,   g_w2hi);
    cudaGetSymbolAddress((void**)&w2lo,   g_w2lo);
    cudaGetSymbolAddress((void**)&w3hi,   g_w3hi);
    cudaGetSymbolAddress((void**)&w3lo,   g_w3lo);

    cudaFuncSetAttribute(agg_wmma<1>, cudaFuncAttributeMaxDynamicSharedMemorySize, AG_SMEM);
    cudaFuncSetAttribute(agg_wmma<0>, cudaFuncAttributeMaxDynamicSharedMemorySize, AG_SMEM);
    cudaFuncSetAttribute(support_wmma<NFEAT, 1>, cudaFuncAttributeMaxDynamicSharedMemorySize, SP_SMEM);
    cudaFuncSetAttribute(support_wmma<NHID, 3>,  cudaFuncAttributeMaxDynamicSharedMemorySize, SP_SMEM);

    const int adjN4 = (Bq * Eq * Nq * Nq) / 4;
    const int wN4   = (Eq * NHID * NHID) / 4;
    split_kernel<<<(adjN4 + 255) / 256, 256>>>(adj, adjhi, adjlo, adjN4);
    split_kernel<<<(wN4 + 255) / 256, 256>>>(gc2_w, w2hi, w2lo, wN4);
    split_kernel<<<(wN4 + 255) / 256, 256>>>(gc3_w, w3hi, w3lo, wN4);
    c1_split_kernel<<<(Eq * NFEAT * NHID + 255) / 256, 256>>>(emb_w, gc1_w, c1hi, c1lo);

    dim3 sgrid(MFLAT / 128, Eq);      // (192, 3)
    dim3 agrid(Nq / 128, Bq, Eq);     // (3, 64, 3)

    support_wmma<NFEAT, 1><<<sgrid, 256, SP_SMEM>>>(x, c1hi, c1lo, supphi, supplo);
    agg_wmma<1><<<agrid, 256, AG_SMEM>>>(adjhi, adjlo, supphi, supplo, oe);
    support_wmma<NHID, 3><<<sgrid, 256, SP_SMEM>>>(oe, w2hi, w2lo, supphi, supplo);
    agg_wmma<1><<<agrid, 256, AG_SMEM>>>(adjhi, adjlo, supphi, supplo, oe);
    support_wmma<NHID, 3><<<sgrid, 256, SP_SMEM>>>(oe, w3hi, w3lo, supphi, supplo);
    agg_wmma<0><<<agrid, 256, AG_SMEM>>>(adjhi, adjlo, supphi, supplo, oe);

    head_kernel<<<MFLAT / 16, 256>>>(oe, st_w1, st_b1, st_w2, st_b2, rescale, out);
}

// round 8
// speedup vs baseline: 2.7554x; 2.2829x over previous
#include <cuda_runtime.h>
#include <cuda_fp16.h>
#include <mma.h>
#include <math.h>

using namespace nvcuda;

#define Bq     64
#define Nq     384
#define NFEAT  16
#define Eq     3
#define NHID   128
#define ST_HID 64
#define ST_OUT 16
#define MFLAT  (Bq * Nq)
#define SCALE_DN 0.0625f
#define SCALE_UP 16.0f

// ---------------- device scratch (fp16 split pairs) ----------------
__device__ __half g_adjhi[Bq * Eq * Nq * Nq];     // 56.6 MB
__device__ __half g_adjlo[Bq * Eq * Nq * Nq];     // 56.6 MB
__device__ __half g_supphi[Bq * Eq * Nq * NHID];  // scaled by 1/16
__device__ __half g_supplo[Bq * Eq * Nq * NHID];
__device__ float  g_oe[Bq * Eq * Nq * NHID];      // per-relation fp32 (true scale)
__device__ __half g_c1hi[Eq * NFEAT * NHID];
__device__ __half g_c1lo[Eq * NFEAT * NHID];
__device__ __half g_w2hi[Eq * NHID * NHID];
__device__ __half g_w2lo[Eq * NHID * NHID];
__device__ __half g_w3hi[Eq * NHID * NHID];
__device__ __half g_w3lo[Eq * NHID * NHID];

// ---------------- fp16 Dekker split ----------------
__device__ __forceinline__ void split1h(float v, __half& h, __half& l) {
    h = __float2half_rn(v);
    l = __float2half_rn(v - __half2float(h));
}

struct alignas(16) H8 { __half v[8]; };

__global__ void split_kernel(const float* __restrict__ src,
                             __half* __restrict__ hi, __half* __restrict__ lo,
                             int n8) {
    int i = blockIdx.x * blockDim.x + threadIdx.x;
    if (i >= n8) return;
    float4 a = *(const float4*)(src + (size_t)i * 8);
    float4 b = *(const float4*)(src + (size_t)i * 8 + 4);
    float vv[8] = {a.x, a.y, a.z, a.w, b.x, b.y, b.z, b.w};
    H8 H, L;
#pragma unroll
    for (int j = 0; j < 8; j++) split1h(vv[j], H.v[j], L.v[j]);
    *(H8*)(hi + (size_t)i * 8) = H;
    *(H8*)(lo + (size_t)i * 8) = L;
}

__global__ void c1_split_kernel(const float* __restrict__ emb_w,
                                const float* __restrict__ gc1_w,
                                __half* __restrict__ hi, __half* __restrict__ lo) {
    int idx = blockIdx.x * 256 + threadIdx.x;
    if (idx >= Eq * NFEAT * NHID) return;
    int h = idx & 127, f = (idx >> 7) & 15, e = idx >> 11;
    float acc = 0.f;
#pragma unroll
    for (int d = 0; d < NFEAT; d++)
        acc += emb_w[d * NFEAT + f] * gc1_w[(e * NFEAT + d) * NHID + h];
    split1h(acc, hi[idx], lo[idx]);
}

// ---------------- cp.async ----------------
__device__ __forceinline__ void cpa16(unsigned s, const void* g) {
    asm volatile("cp.async.cg.shared.global [%0], [%1], 16;" :: "r"(s), "l"(g));
}
#define CPA_COMMIT() asm volatile("cp.async.commit_group;" ::: "memory")
#define CPA_WAIT(N)  asm volatile("cp.async.wait_group %0;" :: "n"(N) : "memory")

// ---------------- smem layout (offsets in halfs) ----------------
#define LDA_H 24      // 16 data + 8 pad halfs (48 B rows)
#define LDB_H 136     // 128 + 8 pad halfs (272 B rows)
#define H_AHI 0
#define H_ALO (128 * LDA_H)           // 3072
#define H_BHI (2 * 128 * LDA_H)       // 6144
#define H_BLO (H_BHI + 16 * LDB_H)    // 8320
#define STAGE_H (H_BLO + 16 * LDB_H)  // 10496 halfs = 20992 B
#define AG_SMEM (2 * STAGE_H * 2)     // 41984 B
#define ELDM 132
#define SP_SMEM (64 * ELDM * 4)       // 33792 B (epilogue stage dominates)

typedef wmma::fragment<wmma::matrix_a, 16, 16, 16, __half, wmma::row_major> AF;
typedef wmma::fragment<wmma::matrix_b, 16, 16, 16, __half, wmma::row_major> BF;
typedef wmma::fragment<wmma::accumulator, 16, 16, 16, float> CF;

// ---------------------------------------------------------------------------
// Per-relation aggregation, double-buffered cp.async, fp16 3-MMA split:
//   oe[b,e,m,:] = act( 16 * adj[b,e,m,:] @ supp_scaled[b,e,:,:] )
// BM=128, BN=128, BK=16, 256 thr (8 warps 4x2), warp tile 32x64.
// grid: (3, Bq, Eq)
// ---------------------------------------------------------------------------
__device__ __forceinline__ void ag_load_stage(unsigned sb, const __half* aH,
                                              const __half* aL, const __half* bH,
                                              const __half* bL, int kt, int tid) {
    {   // A: 128x16 halfs hi/lo, 1 chunk each per thread
        int r = tid >> 1, c8 = tid & 1;
        size_t g = (size_t)r * Nq + kt * 16 + c8 * 8;
        cpa16(sb + (H_AHI + r * LDA_H + c8 * 8) * 2, aH + g);
        cpa16(sb + (H_ALO + r * LDA_H + c8 * 8) * 2, aL + g);
    }
    {   // B: 16x128 halfs hi/lo
        int r = tid >> 4, c8 = tid & 15;
        size_t g = (size_t)(kt * 16 + r) * NHID + c8 * 8;
        cpa16(sb + (H_BHI + r * LDB_H + c8 * 8) * 2, bH + g);
        cpa16(sb + (H_BLO + r * LDB_H + c8 * 8) * 2, bL + g);
    }
}

template <int RELU>
__global__ __launch_bounds__(256, 2)
void agg_wmma(const __half* __restrict__ adjhi, const __half* __restrict__ adjlo,
              const __half* __restrict__ shi, const __half* __restrict__ slo,
              float* __restrict__ oe) {
    extern __shared__ __half smh[];
    const unsigned sbase = (unsigned)__cvta_generic_to_shared(smh);

    const int tid = threadIdx.x;
    const int wid = tid >> 5;
    const int wm = wid >> 1, wn = wid & 1;     // 4 x 2 warps, 32x64 tiles
    const int m0 = blockIdx.x * 128;
    const int b = blockIdx.y, e = blockIdx.z;

    const __half* aH = adjhi + ((size_t)(b * Eq + e) * Nq + m0) * Nq;
    const __half* aL = adjlo + ((size_t)(b * Eq + e) * Nq + m0) * Nq;
    const __half* bH = shi + (size_t)(b * Eq + e) * Nq * NHID;
    const __half* bL = slo + (size_t)(b * Eq + e) * Nq * NHID;

    CF c[2][4];
#pragma unroll
    for (int i = 0; i < 2; i++)
#pragma unroll
        for (int j = 0; j < 4; j++) wmma::fill_fragment(c[i][j], 0.f);

    constexpr int KT = Nq / 16;                // 24
    ag_load_stage(sbase, aH, aL, bH, bL, 0, tid);
    CPA_COMMIT();

    for (int kt = 0; kt < KT; kt++) {
        if (kt + 1 < KT) {
            ag_load_stage(sbase + ((kt + 1) & 1) * STAGE_H * 2,
                          aH, aL, bH, bL, kt + 1, tid);
            CPA_COMMIT();
            CPA_WAIT(1);
        } else {
            CPA_WAIT(0);
        }
        __syncthreads();

        const __half* S = smh + (kt & 1) * STAGE_H;
        AF afH[2], afL[2];
#pragma unroll
        for (int i = 0; i < 2; i++) {
            const __half* p = S + H_AHI + (wm * 32 + i * 16) * LDA_H;
            wmma::load_matrix_sync(afH[i], p, LDA_H);
            wmma::load_matrix_sync(afL[i], p + (H_ALO - H_AHI), LDA_H);
        }
#pragma unroll
        for (int j = 0; j < 4; j++) {
            BF bfH, bfL;
            const __half* p = S + H_BHI + wn * 64 + j * 16;
            wmma::load_matrix_sync(bfH, p, LDB_H);
            wmma::load_matrix_sync(bfL, p + (H_BLO - H_BHI), LDB_H);
#pragma unroll
            for (int i = 0; i < 2; i++) {
                wmma::mma_sync(c[i][j], afH[i], bfH, c[i][j]);
                wmma::mma_sync(c[i][j], afH[i], bfL, c[i][j]);
                wmma::mma_sync(c[i][j], afL[i], bfH, c[i][j]);
            }
        }
        __syncthreads();
    }

    // Epilogue: unscale (x16), optional relu, direct fp32 store
#pragma unroll
    for (int i = 0; i < 2; i++)
#pragma unroll
        for (int j = 0; j < 4; j++) {
#pragma unroll
            for (int t = 0; t < c[i][j].num_elements; t++) {
                float v = c[i][j].x[t] * SCALE_UP;
                c[i][j].x[t] = RELU ? fmaxf(v, 0.f) : v;
            }
            float* op = oe + ((size_t)(b * Eq + e) * Nq + m0 + wm * 32 + i * 16) * NHID
                           + wn * 64 + j * 16;
            wmma::store_matrix_sync(op, c[i][j], NHID, wmma::mem_row_major);
        }
}

// ---------------------------------------------------------------------------
// Support: supp_scaled[b,e,n,:] = (rowin * 2^-4) @ W[e]
// rowin = x (NE=1) or sum_e' oe (NE=3), fp32 in, split-to-fp16 on the fly.
// Output stored as fp16 hi/lo (scaled by 2^-4).
// BM=128, BN=128, BK=16. grid: (MFLAT/128=192, Eq)
// ---------------------------------------------------------------------------
template <int K, int NE>
__global__ __launch_bounds__(256, 2)
void support_wmma(const float* __restrict__ in,
                  const __half* __restrict__ whi, const __half* __restrict__ wlo,
                  __half* __restrict__ supphi, __half* __restrict__ supplo) {
    extern __shared__ __half smh[];
    __half* Ahi = smh + H_AHI;
    __half* Alo = smh + H_ALO;
    __half* Bhi = smh + H_BHI;
    __half* Blo = smh + H_BLO;
    float* E = (float*)smh;

    const int tid = threadIdx.x;
    const int wid = tid >> 5;
    const int wm = wid >> 1, wn = wid & 1;
    const int e = blockIdx.y;
    const int m0 = blockIdx.x * 128;
    const int b = m0 / Nq, n0 = m0 % Nq;

    const float* aBase = (NE == 1)
        ? in + (size_t)m0 * K
        : in + (size_t)(b * Eq) * Nq * NHID + (size_t)n0 * NHID;
    const size_t eS = (size_t)Nq * NHID;
    const __half* wH = whi + (size_t)e * K * NHID;
    const __half* wL = wlo + (size_t)e * K * NHID;

    CF c[2][4];
#pragma unroll
    for (int i = 0; i < 2; i++)
#pragma unroll
        for (int j = 0; j < 4; j++) wmma::fill_fragment(c[i][j], 0.f);

#pragma unroll
    for (int kt = 0; kt < K / 16; kt++) {
        // A: 128x16 fp32 -> (sum e) -> *2^-4 -> fp16 split -> smem
#pragma unroll
        for (int t = 0; t < 2; t++) {
            int idx = tid + t * 256;
            int r = idx >> 2, c4 = idx & 3;
            const float* rp = aBase + (size_t)r * K + kt * 16 + c4 * 4;
            float4 v = *(const float4*)rp;
            if (NE == 3) {
                float4 v1 = *(const float4*)(rp + eS);
                float4 v2 = *(const float4*)(rp + 2 * eS);
                v.x += v1.x + v2.x; v.y += v1.y + v2.y;
                v.z += v1.z + v2.z; v.w += v1.w + v2.w;
            }
            v.x *= SCALE_DN; v.y *= SCALE_DN; v.z *= SCALE_DN; v.w *= SCALE_DN;
            __half h0, h1, h2, h3, l0, l1, l2, l3;
            split1h(v.x, h0, l0); split1h(v.y, h1, l1);
            split1h(v.z, h2, l2); split1h(v.w, h3, l3);
            __half* pa = Ahi + r * LDA_H + c4 * 4;
            *(half2*)pa       = __halves2half2(h0, h1);
            *(half2*)(pa + 2) = __halves2half2(h2, h3);
            __half* pl = Alo + r * LDA_H + c4 * 4;
            *(half2*)pl       = __halves2half2(l0, l1);
            *(half2*)(pl + 2) = __halves2half2(l2, l3);
        }
        // B: 16x128 halfs hi/lo, 1 uint4/thread each
        {
            int r = tid >> 4, c8 = tid & 15;
            size_t g = (size_t)(kt * 16 + r) * NHID + c8 * 8;
            *(uint4*)&Bhi[r * LDB_H + c8 * 8] = *(const uint4*)(wH + g);
            *(uint4*)&Blo[r * LDB_H + c8 * 8] = *(const uint4*)(wL + g);
        }
        __syncthreads();

        AF afH[2], afL[2];
#pragma unroll
        for (int i = 0; i < 2; i++) {
            const __half* p = Ahi + (wm * 32 + i * 16) * LDA_H;
            wmma::load_matrix_sync(afH[i], p, LDA_H);
            wmma::load_matrix_sync(afL[i], p + (H_ALO - H_AHI), LDA_H);
        }
#pragma unroll
        for (int j = 0; j < 4; j++) {
            BF bfH, bfL;
            const __half* p = Bhi + wn * 64 + j * 16;
            wmma::load_matrix_sync(bfH, p, LDB_H);
            wmma::load_matrix_sync(bfL, p + (H_BLO - H_BHI), LDB_H);
#pragma unroll
            for (int i = 0; i < 2; i++) {
                wmma::mma_sync(c[i][j], afH[i], bfH, c[i][j]);
                wmma::mma_sync(c[i][j], afH[i], bfL, c[i][j]);
                wmma::mma_sync(c[i][j], afL[i], bfH, c[i][j]);
            }
        }
        __syncthreads();
    }

    // Epilogue: stage 64 rows of fp32 per pass, split to fp16 hi/lo, write
#pragma unroll
    for (int i = 0; i < 2; i++) {
#pragma unroll
        for (int j = 0; j < 4; j++)
            wmma::store_matrix_sync(&E[(wm * 16) * ELDM + wn * 64 + j * 16],
                                    c[i][j], ELDM, wmma::mem_row_major);
        __syncthreads();
#pragma unroll
        for (int t = 0; t < 8; t++) {               // 64*128/4 quads / 256 thr
            int p = tid + t * 256;
            int rr = p >> 5, c4 = (p & 31) * 4;
            float4 v = *(float4*)&E[rr * ELDM + c4];
            __half h0, h1, h2, h3, l0, l1, l2, l3;
            split1h(v.x, h0, l0); split1h(v.y, h1, l1);
            split1h(v.z, h2, l2); split1h(v.w, h3, l3);
            int n = n0 + (rr >> 4) * 32 + i * 16 + (rr & 15);
            size_t o = ((size_t)(b * Eq + e) * Nq + n) * NHID + c4;
            half2 hA = __halves2half2(h0, h1), hB = __halves2half2(h2, h3);
            half2 lA = __halves2half2(l0, l1), lB = __halves2half2(l2, l3);
            uint2 uh, ul;
            uh.x = *(unsigned*)&hA; uh.y = *(unsigned*)&hB;
            ul.x = *(unsigned*)&lA; ul.y = *(unsigned*)&lB;
            *(uint2*)(supphi + o) = uh;
            *(uint2*)(supplo + o) = ul;
        }
        __syncthreads();
    }
}

// ---------------------------------------------------------------------------
// Head
// ---------------------------------------------------------------------------
__global__ __launch_bounds__(256)
void head_kernel(const float* __restrict__ oe,
                 const float* __restrict__ w1, const float* __restrict__ b1,
                 const float* __restrict__ w2, const float* __restrict__ b2,
                 const float* __restrict__ rescale, float* __restrict__ out) {
    __shared__ float w1T[NHID][68];
    __shared__ float hS[16][NHID];
    __shared__ float z1S[16][68];

    const int tid = threadIdx.x;
    const int row0 = blockIdx.x * 16;
    const int b = row0 / Nq;
    const int n0 = row0 % Nq;

    for (int i = tid; i < ST_HID * NHID; i += 256) {
        int hid = i >> 7, d = i & 127;
        w1T[d][hid] = w1[i];
    }
    const float* base = oe + (size_t)(b * Eq) * Nq * NHID + (size_t)n0 * NHID;
    const size_t eS = (size_t)Nq * NHID;
#pragma unroll
    for (int t = 0; t < 2; t++) {
        int idx = tid + t * 256;
        int r = idx >> 5, c = idx & 31;
        float4 v0 = *(const float4*)(base + (size_t)r * NHID + c * 4);
        float4 v1 = *(const float4*)(base + eS + (size_t)r * NHID + c * 4);
        float4 v2 = *(const float4*)(base + 2 * eS + (size_t)r * NHID + c * 4);
        *(float4*)&hS[r][c * 4] = make_float4(v0.x + v1.x + v2.x, v0.y + v1.y + v2.y,
                                              v0.z + v1.z + v2.z, v0.w + v1.w + v2.w);
    }
    __syncthreads();

    {
        int row = tid >> 4, hg = tid & 15;
        float a0 = b1[hg * 4 + 0], a1 = b1[hg * 4 + 1];
        float a2 = b1[hg * 4 + 2], a3 = b1[hg * 4 + 3];
#pragma unroll 8
        for (int d = 0; d < NHID; d++) {
            float h = hS[row][d];
            float4 w = *(const float4*)&w1T[d][hg * 4];
            a0 = fmaf(h, w.x, a0); a1 = fmaf(h, w.y, a1);
            a2 = fmaf(h, w.z, a2); a3 = fmaf(h, w.w, a3);
        }
        z1S[row][hg * 4 + 0] = tanhf(a0);
        z1S[row][hg * 4 + 1] = tanhf(a1);
        z1S[row][hg * 4 + 2] = tanhf(a2);
        z1S[row][hg * 4 + 3] = tanhf(a3);
    }
    __syncthreads();

    const float ew = expf(rescale[0]);
    for (int p = tid; p < 16 * 32; p += 256) {
        int row = p >> 5, j = p & 31;
        float acc = b2[j];
#pragma unroll 8
        for (int k = 0; k < ST_HID; k++)
            acc += z1S[row][k] * w2[j * ST_HID + k];
        int grow = row0 + row;
        if (j < ST_OUT)
            out[(size_t)grow * ST_OUT + j] = ew * tanhf(acc);
        else
            out[(size_t)MFLAT * ST_OUT + (size_t)grow * ST_OUT + (j - ST_OUT)] = acc;
    }
}

// ---------------------------------------------------------------------------
extern "C" void kernel_launch(void* const* d_in, const int* in_sizes, int n_in,
                              void* d_out, int out_size) {
    const float* x       = (const float*)d_in[0];
    const float* adj     = (const float*)d_in[1];
    const float* emb_w   = (const float*)d_in[2];
    const float* gc1_w   = (const float*)d_in[3];
    const float* gc2_w   = (const float*)d_in[4];
    const float* gc3_w   = (const float*)d_in[5];
    const float* st_w1   = (const float*)d_in[6];
    const float* st_b1   = (const float*)d_in[7];
    const float* st_w2   = (const float*)d_in[8];
    const float* st_b2   = (const float*)d_in[9];
    const float* rescale = (const float*)d_in[10];
    float* out = (float*)d_out;

    __half *adjhi, *adjlo, *supphi, *supplo;
    __half *c1hi, *c1lo, *w2hi, *w2lo, *w3hi, *w3lo;
    float* oe;
    cudaGetSymbolAddress((void**)&adjhi,  g_adjhi);
    cudaGetSymbolAddress((void**)&adjlo,  g_adjlo);
    cudaGetSymbolAddress((void**)&supphi, g_supphi);
    cudaGetSymbolAddress((void**)&supplo, g_supplo);
    cudaGetSymbolAddress((void**)&oe,     g_oe);
    cudaGetSymbolAddress((void**)&c1hi,   g_c1hi);
    cudaGetSymbolAddress((void**)&c1lo,   g_c1lo);
    cudaGetSymbolAddress((void**)&w2hi,   g_w2hi);
    cudaGetSymbolAddress((void**)&w2lo,   g_w2lo);
    cudaGetSymbolAddress((void**)&w3hi,   g_w3hi);
    cudaGetSymbolAddress((void**)&w3lo,   g_w3lo);

    cudaFuncSetAttribute(agg_wmma<1>, cudaFuncAttributeMaxDynamicSharedMemorySize, AG_SMEM);
    cudaFuncSetAttribute(agg_wmma<0>, cudaFuncAttributeMaxDynamicSharedMemorySize, AG_SMEM);
    cudaFuncSetAttribute(support_wmma<NFEAT, 1>, cudaFuncAttributeMaxDynamicSharedMemorySize, SP_SMEM);
    cudaFuncSetAttribute(support_wmma<NHID, 3>,  cudaFuncAttributeMaxDynamicSharedMemorySize, SP_SMEM);

    const int adjN8 = (Bq * Eq * Nq * Nq) / 8;
    const int wN8   = (Eq * NHID * NHID) / 8;
    split_kernel<<<(adjN8 + 255) / 256, 256>>>(adj, adjhi, adjlo, adjN8);
    split_kernel<<<(wN8 + 255) / 256, 256>>>(gc2_w, w2hi, w2lo, wN8);
    split_kernel<<<(wN8 + 255) / 256, 256>>>(gc3_w, w3hi, w3lo, wN8);
    c1_split_kernel<<<(Eq * NFEAT * NHID + 255) / 256, 256>>>(emb_w, gc1_w, c1hi, c1lo);

    dim3 sgrid(MFLAT / 128, Eq);      // (192, 3)
    dim3 agrid(Nq / 128, Bq, Eq);     // (3, 64, 3)

    support_wmma<NFEAT, 1><<<sgrid, 256, SP_SMEM>>>(x, c1hi, c1lo, supphi, supplo);
    agg_wmma<1><<<agrid, 256, AG_SMEM>>>(adjhi, adjlo, supphi, supplo, oe);
    support_wmma<NHID, 3><<<sgrid, 256, SP_SMEM>>>(oe, w2hi, w2lo, supphi, supplo);
    agg_wmma<1><<<agrid, 256, AG_SMEM>>>(adjhi, adjlo, supphi, supplo, oe);
    support_wmma<NHID, 3><<<sgrid, 256, SP_SMEM>>>(oe, w3hi, w3lo, supphi, supplo);
    agg_wmma<0><<<agrid, 256, AG_SMEM>>>(adjhi, adjlo, supphi, supplo, oe);

    head_kernel<<<MFLAT / 16, 256>>>(oe, st_w1, st_b1, st_w2, st_b2, rescale, out);
}

// round 9
// speedup vs baseline: 2.9097x; 1.0560x over previous
#include <cuda_runtime.h>
#include <cuda_fp16.h>
#include <mma.h>
#include <math.h>

using namespace nvcuda;

#define Bq     64
#define Nq     384
#define NFEAT  16
#define Eq     3
#define NHID   128
#define ST_HID 64
#define ST_OUT 16
#define MFLAT  (Bq * Nq)
#define SCALE_DN 0.0625f
#define SCALE_UP 16.0f

// ---------------- device scratch (fp16 split pairs) ----------------
__device__ __half g_adjhi[Bq * Eq * Nq * Nq];
__device__ __half g_adjlo[Bq * Eq * Nq * Nq];
__device__ __half g_supphi[Bq * Eq * Nq * NHID];  // scaled by 1/16
__device__ __half g_supplo[Bq * Eq * Nq * NHID];
__device__ float  g_oe[Bq * Eq * Nq * NHID];
__device__ __half g_c1hi[Eq * NFEAT * NHID];
__device__ __half g_c1lo[Eq * NFEAT * NHID];
__device__ __half g_w2hi[Eq * NHID * NHID];
__device__ __half g_w2lo[Eq * NHID * NHID];
__device__ __half g_w3hi[Eq * NHID * NHID];
__device__ __half g_w3lo[Eq * NHID * NHID];

// ---------------- fp16 Dekker split ----------------
__device__ __forceinline__ void split1h(float v, __half& h, __half& l) {
    h = __float2half_rn(v);
    l = __float2half_rn(v - __half2float(h));
}

struct alignas(16) H8 { __half v[8]; };

__global__ void split_kernel(const float* __restrict__ src,
                             __half* __restrict__ hi, __half* __restrict__ lo,
                             int n8) {
    int i = blockIdx.x * blockDim.x + threadIdx.x;
    if (i >= n8) return;
    float4 a = *(const float4*)(src + (size_t)i * 8);
    float4 b = *(const float4*)(src + (size_t)i * 8 + 4);
    float vv[8] = {a.x, a.y, a.z, a.w, b.x, b.y, b.z, b.w};
    H8 H, L;
#pragma unroll
    for (int j = 0; j < 8; j++) split1h(vv[j], H.v[j], L.v[j]);
    *(H8*)(hi + (size_t)i * 8) = H;
    *(H8*)(lo + (size_t)i * 8) = L;
}

// Fused weight prep: splits gc2, gc3 and computes+splits C1 in ONE launch.
#define WN8 ((Eq * NHID * NHID) / 8)     // 6144 chunks per weight
#define WBLK ((2 * WN8) / 256)           // 48 blocks for w2+w3
__global__ void weight_prep_kernel(const float* __restrict__ gc2_w,
                                   const float* __restrict__ gc3_w,
                                   const float* __restrict__ emb_w,
                                   const float* __restrict__ gc1_w,
                                   __half* __restrict__ w2hi, __half* __restrict__ w2lo,
                                   __half* __restrict__ w3hi, __half* __restrict__ w3lo,
                                   __half* __restrict__ c1hi, __half* __restrict__ c1lo) {
    int bx = blockIdx.x;
    if (bx < WBLK) {
        int i = bx * 256 + threadIdx.x;
        const float* src;
        __half *hi, *lo;
        if (i < WN8) { src = gc2_w; hi = w2hi; lo = w2lo; }
        else { src = gc3_w; hi = w3hi; lo = w3lo; i -= WN8; }
        float4 a = *(const float4*)(src + (size_t)i * 8);
        float4 b = *(const float4*)(src + (size_t)i * 8 + 4);
        float vv[8] = {a.x, a.y, a.z, a.w, b.x, b.y, b.z, b.w};
        H8 H, L;
#pragma unroll
        for (int j = 0; j < 8; j++) split1h(vv[j], H.v[j], L.v[j]);
        *(H8*)(hi + (size_t)i * 8) = H;
        *(H8*)(lo + (size_t)i * 8) = L;
    } else {
        int idx = (bx - WBLK) * 256 + threadIdx.x;
        if (idx >= Eq * NFEAT * NHID) return;
        int h = idx & 127, f = (idx >> 7) & 15, e = idx >> 11;
        float acc = 0.f;
#pragma unroll
        for (int d = 0; d < NFEAT; d++)
            acc += emb_w[d * NFEAT + f] * gc1_w[(e * NFEAT + d) * NHID + h];
        split1h(acc, c1hi[idx], c1lo[idx]);
    }
}

// ---------------- cp.async ----------------
__device__ __forceinline__ void cpa16(unsigned s, const void* g) {
    asm volatile("cp.async.cg.shared.global [%0], [%1], 16;" :: "r"(s), "l"(g));
}
#define CPA_COMMIT() asm volatile("cp.async.commit_group;" ::: "memory")
#define CPA_WAIT(N)  asm volatile("cp.async.wait_group %0;" :: "n"(N) : "memory")

// ---------------- smem layout (offsets in halfs) ----------------
// agg stage (BK=32): A 128x32 (ld 40) hi/lo, B 32x128 (ld 136) hi/lo
#define AG_LDA 40
#define LDB_H  136
#define H_AHI 0
#define H_ALO (128 * AG_LDA)              // 5120
#define H_BHI (2 * 128 * AG_LDA)          // 10240
#define H_BLO (H_BHI + 32 * LDB_H)        // 14592
#define STAGE_H (H_BLO + 32 * LDB_H)      // 18944 halfs
#define AG_SMEM (2 * STAGE_H * 2)         // 75776 B

// support (BK=16, single stage): A 128x16 (ld 24) hi/lo, B 16x128 hi/lo
#define SP_LDA 24
#define S_AHI 0
#define S_ALO (128 * SP_LDA)              // 3072
#define S_BHI (2 * 128 * SP_LDA)          // 6144
#define S_BLO (S_BHI + 16 * LDB_H)        // 8320
#define ELDM 132
#define SP_SMEM (64 * ELDM * 4)           // 33792 B (epilogue fp32 stage dominates)

typedef wmma::fragment<wmma::matrix_a, 16, 16, 16, __half, wmma::row_major> AF;
typedef wmma::fragment<wmma::matrix_b, 16, 16, 16, __half, wmma::row_major> BF;
typedef wmma::fragment<wmma::accumulator, 16, 16, 16, float> CF;

// ---------------------------------------------------------------------------
// Per-relation aggregation, BK=32, double-buffered cp.async, fp16 3-MMA:
//   oe[b,e,m,:] = act( 16 * adj[b,e,m,:] @ supp_scaled[b,e,:,:] )
// BM=128, BN=128, 256 thr (8 warps 4x2), warp tile 32x64. grid: (3, Bq, Eq)
// ---------------------------------------------------------------------------
__device__ __forceinline__ void ag_load_stage(unsigned sb, const __half* aH,
                                              const __half* aL, const __half* bH,
                                              const __half* bL, int kt, int tid) {
#pragma unroll
    for (int t = 0; t < 2; t++) {          // A: 128x32 halfs, hi+lo
        int idx = tid + t * 256;           // [0,512)
        int r = idx >> 2, c8 = idx & 3;
        size_t g = (size_t)r * Nq + kt * 32 + c8 * 8;
        cpa16(sb + (H_AHI + r * AG_LDA + c8 * 8) * 2, aH + g);
        cpa16(sb + (H_ALO + r * AG_LDA + c8 * 8) * 2, aL + g);
    }
#pragma unroll
    for (int t = 0; t < 2; t++) {          // B: 32x128 halfs, hi+lo
        int idx = tid + t * 256;
        int r = idx >> 4, c8 = idx & 15;
        size_t g = (size_t)(kt * 32 + r) * NHID + c8 * 8;
        cpa16(sb + (H_BHI + r * LDB_H + c8 * 8) * 2, bH + g);
        cpa16(sb + (H_BLO + r * LDB_H + c8 * 8) * 2, bL + g);
    }
}

template <int RELU>
__global__ __launch_bounds__(256, 2)
void agg_wmma(const __half* __restrict__ adjhi, const __half* __restrict__ adjlo,
              const __half* __restrict__ shi, const __half* __restrict__ slo,
              float* __restrict__ oe) {
    extern __shared__ __half smh[];
    const unsigned sbase = (unsigned)__cvta_generic_to_shared(smh);

    const int tid = threadIdx.x;
    const int wid = tid >> 5;
    const int wm = wid >> 1, wn = wid & 1;
    const int m0 = blockIdx.x * 128;
    const int b = blockIdx.y, e = blockIdx.z;

    const __half* aH = adjhi + ((size_t)(b * Eq + e) * Nq + m0) * Nq;
    const __half* aL = adjlo + ((size_t)(b * Eq + e) * Nq + m0) * Nq;
    const __half* bH = shi + (size_t)(b * Eq + e) * Nq * NHID;
    const __half* bL = slo + (size_t)(b * Eq + e) * Nq * NHID;

    CF c[2][4];
#pragma unroll
    for (int i = 0; i < 2; i++)
#pragma unroll
        for (int j = 0; j < 4; j++) wmma::fill_fragment(c[i][j], 0.f);

    constexpr int KT = Nq / 32;            // 12
    ag_load_stage(sbase, aH, aL, bH, bL, 0, tid);
    CPA_COMMIT();

    for (int kt = 0; kt < KT; kt++) {
        if (kt + 1 < KT) {
            ag_load_stage(sbase + ((kt + 1) & 1) * STAGE_H * 2,
                          aH, aL, bH, bL, kt + 1, tid);
            CPA_COMMIT();
            CPA_WAIT(1);
        } else {
            CPA_WAIT(0);
        }
        __syncthreads();

        const __half* S = smh + (kt & 1) * STAGE_H;
#pragma unroll
        for (int k16 = 0; k16 < 2; k16++) {
            AF afH[2], afL[2];
#pragma unroll
            for (int i = 0; i < 2; i++) {
                const __half* p = S + H_AHI + (wm * 32 + i * 16) * AG_LDA + k16 * 16;
                wmma::load_matrix_sync(afH[i], p, AG_LDA);
                wmma::load_matrix_sync(afL[i], p + (H_ALO - H_AHI), AG_LDA);
            }
#pragma unroll
            for (int j = 0; j < 4; j++) {
                BF bfH, bfL;
                const __half* p = S + H_BHI + (k16 * 16) * LDB_H + wn * 64 + j * 16;
                wmma::load_matrix_sync(bfH, p, LDB_H);
                wmma::load_matrix_sync(bfL, p + (H_BLO - H_BHI), LDB_H);
#pragma unroll
                for (int i = 0; i < 2; i++) {
                    wmma::mma_sync(c[i][j], afH[i], bfH, c[i][j]);
                    wmma::mma_sync(c[i][j], afH[i], bfL, c[i][j]);
                    wmma::mma_sync(c[i][j], afL[i], bfH, c[i][j]);
                }
            }
        }
        __syncthreads();
    }

#pragma unroll
    for (int i = 0; i < 2; i++)
#pragma unroll
        for (int j = 0; j < 4; j++) {
#pragma unroll
            for (int t = 0; t < c[i][j].num_elements; t++) {
                float v = c[i][j].x[t] * SCALE_UP;
                c[i][j].x[t] = RELU ? fmaxf(v, 0.f) : v;
            }
            float* op = oe + ((size_t)(b * Eq + e) * Nq + m0 + wm * 32 + i * 16) * NHID
                           + wn * 64 + j * 16;
            wmma::store_matrix_sync(op, c[i][j], NHID, wmma::mem_row_major);
        }
}

// ---------------------------------------------------------------------------
// Support: supp_scaled[b,e,n,:] = (rowin * 2^-4) @ W[e]
// rowin = x (NE=1) or sum_e' oe (NE=3). grid: (MFLAT/128, Eq)
// ---------------------------------------------------------------------------
template <int K, int NE>
__global__ __launch_bounds__(256, 2)
void support_wmma(const float* __restrict__ in,
                  const __half* __restrict__ whi, const __half* __restrict__ wlo,
                  __half* __restrict__ supphi, __half* __restrict__ supplo) {
    extern __shared__ __half smh[];
    __half* Ahi = smh + S_AHI;
    __half* Alo = smh + S_ALO;
    __half* Bhi = smh + S_BHI;
    __half* Blo = smh + S_BLO;
    float* E = (float*)smh;

    const int tid = threadIdx.x;
    const int wid = tid >> 5;
    const int wm = wid >> 1, wn = wid & 1;
    const int e = blockIdx.y;
    const int m0 = blockIdx.x * 128;
    const int b = m0 / Nq, n0 = m0 % Nq;

    const float* aBase = (NE == 1)
        ? in + (size_t)m0 * K
        : in + (size_t)(b * Eq) * Nq * NHID + (size_t)n0 * NHID;
    const size_t eS = (size_t)Nq * NHID;
    const __half* wH = whi + (size_t)e * K * NHID;
    const __half* wL = wlo + (size_t)e * K * NHID;

    CF c[2][4];
#pragma unroll
    for (int i = 0; i < 2; i++)
#pragma unroll
        for (int j = 0; j < 4; j++) wmma::fill_fragment(c[i][j], 0.f);

#pragma unroll
    for (int kt = 0; kt < K / 16; kt++) {
#pragma unroll
        for (int t = 0; t < 2; t++) {
            int idx = tid + t * 256;
            int r = idx >> 2, c4 = idx & 3;
            const float* rp = aBase + (size_t)r * K + kt * 16 + c4 * 4;
            float4 v = *(const float4*)rp;
            if (NE == 3) {
                float4 v1 = *(const float4*)(rp + eS);
                float4 v2 = *(const float4*)(rp + 2 * eS);
                v.x += v1.x + v2.x; v.y += v1.y + v2.y;
                v.z += v1.z + v2.z; v.w += v1.w + v2.w;
            }
            v.x *= SCALE_DN; v.y *= SCALE_DN; v.z *= SCALE_DN; v.w *= SCALE_DN;
            __half h0, h1, h2, h3, l0, l1, l2, l3;
            split1h(v.x, h0, l0); split1h(v.y, h1, l1);
            split1h(v.z, h2, l2); split1h(v.w, h3, l3);
            __half* pa = Ahi + r * SP_LDA + c4 * 4;
            *(half2*)pa       = __halves2half2(h0, h1);
            *(half2*)(pa + 2) = __halves2half2(h2, h3);
            __half* pl = Alo + r * SP_LDA + c4 * 4;
            *(half2*)pl       = __halves2half2(l0, l1);
            *(half2*)(pl + 2) = __halves2half2(l2, l3);
        }
        {
            int r = tid >> 4, c8 = tid & 15;
            size_t g = (size_t)(kt * 16 + r) * NHID + c8 * 8;
            *(uint4*)&Bhi[r * LDB_H + c8 * 8] = *(const uint4*)(wH + g);
            *(uint4*)&Blo[r * LDB_H + c8 * 8] = *(const uint4*)(wL + g);
        }
        __syncthreads();

        AF afH[2], afL[2];
#pragma unroll
        for (int i = 0; i < 2; i++) {
            const __half* p = Ahi + (wm * 32 + i * 16) * SP_LDA;
            wmma::load_matrix_sync(afH[i], p, SP_LDA);
            wmma::load_matrix_sync(afL[i], p + (S_ALO - S_AHI), SP_LDA);
        }
#pragma unroll
        for (int j = 0; j < 4; j++) {
            BF bfH, bfL;
            const __half* p = Bhi + wn * 64 + j * 16;
            wmma::load_matrix_sync(bfH, p, LDB_H);
            wmma::load_matrix_sync(bfL, p + (S_BLO - S_BHI), LDB_H);
#pragma unroll
            for (int i = 0; i < 2; i++) {
                wmma::mma_sync(c[i][j], afH[i], bfH, c[i][j]);
                wmma::mma_sync(c[i][j], afH[i], bfL, c[i][j]);
                wmma::mma_sync(c[i][j], afL[i], bfH, c[i][j]);
            }
        }
        __syncthreads();
    }

    // Epilogue: stage 64 rows fp32, split to fp16 hi/lo, write
#pragma unroll
    for (int i = 0; i < 2; i++) {
#pragma unroll
        for (int j = 0; j < 4; j++)
            wmma::store_matrix_sync(&E[(wm * 16) * ELDM + wn * 64 + j * 16],
                                    c[i][j], ELDM, wmma::mem_row_major);
        __syncthreads();
#pragma unroll
        for (int t = 0; t < 8; t++) {
            int p = tid + t * 256;
            int rr = p >> 5, c4 = (p & 31) * 4;
            float4 v = *(float4*)&E[rr * ELDM + c4];
            __half h0, h1, h2, h3, l0, l1, l2, l3;
            split1h(v.x, h0, l0); split1h(v.y, h1, l1);
            split1h(v.z, h2, l2); split1h(v.w, h3, l3);
            int n = n0 + (rr >> 4) * 32 + i * 16 + (rr & 15);
            size_t o = ((size_t)(b * Eq + e) * Nq + n) * NHID + c4;
            half2 hA = __halves2half2(h0, h1), hB = __halves2half2(h2, h3);
            half2 lA = __halves2half2(l0, l1), lB = __halves2half2(l2, l3);
            uint2 uh, ul;
            uh.x = *(unsigned*)&hA; uh.y = *(unsigned*)&hB;
            ul.x = *(unsigned*)&lA; ul.y = *(unsigned*)&lB;
            *(uint2*)(supphi + o) = uh;
            *(uint2*)(supplo + o) = ul;
        }
        __syncthreads();
    }
}

// ---------------------------------------------------------------------------
// Head
// ---------------------------------------------------------------------------
__global__ __launch_bounds__(256)
void head_kernel(const float* __restrict__ oe,
                 const float* __restrict__ w1, const float* __restrict__ b1,
                 const float* __restrict__ w2, const float* __restrict__ b2,
                 const float* __restrict__ rescale, float* __restrict__ out) {
    __shared__ float w1T[NHID][68];
    __shared__ float hS[16][NHID];
    __shared__ float z1S[16][68];

    const int tid = threadIdx.x;
    const int row0 = blockIdx.x * 16;
    const int b = row0 / Nq;
    const int n0 = row0 % Nq;

    for (int i = tid; i < ST_HID * NHID; i += 256) {
        int hid = i >> 7, d = i & 127;
        w1T[d][hid] = w1[i];
    }
    const float* base = oe + (size_t)(b * Eq) * Nq * NHID + (size_t)n0 * NHID;
    const size_t eS = (size_t)Nq * NHID;
#pragma unroll
    for (int t = 0; t < 2; t++) {
        int idx = tid + t * 256;
        int r = idx >> 5, c = idx & 31;
        float4 v0 = *(const float4*)(base + (size_t)r * NHID + c * 4);
        float4 v1 = *(const float4*)(base + eS + (size_t)r * NHID + c * 4);
        float4 v2 = *(const float4*)(base + 2 * eS + (size_t)r * NHID + c * 4);
        *(float4*)&hS[r][c * 4] = make_float4(v0.x + v1.x + v2.x, v0.y + v1.y + v2.y,
                                              v0.z + v1.z + v2.z, v0.w + v1.w + v2.w);
    }
    __syncthreads();

    {
        int row = tid >> 4, hg = tid & 15;
        float a0 = b1[hg * 4 + 0], a1 = b1[hg * 4 + 1];
        float a2 = b1[hg * 4 + 2], a3 = b1[hg * 4 + 3];
#pragma unroll 8
        for (int d = 0; d < NHID; d++) {
            float h = hS[row][d];
            float4 w = *(const float4*)&w1T[d][hg * 4];
            a0 = fmaf(h, w.x, a0); a1 = fmaf(h, w.y, a1);
            a2 = fmaf(h, w.z, a2); a3 = fmaf(h, w.w, a3);
        }
        z1S[row][hg * 4 + 0] = tanhf(a0);
        z1S[row][hg * 4 + 1] = tanhf(a1);
        z1S[row][hg * 4 + 2] = tanhf(a2);
        z1S[row][hg * 4 + 3] = tanhf(a3);
    }
    __syncthreads();

    const float ew = expf(rescale[0]);
    for (int p = tid; p < 16 * 32; p += 256) {
        int row = p >> 5, j = p & 31;
        float acc = b2[j];
#pragma unroll 8
        for (int k = 0; k < ST_HID; k++)
            acc += z1S[row][k] * w2[j * ST_HID + k];
        int grow = row0 + row;
        if (j < ST_OUT)
            out[(size_t)grow * ST_OUT + j] = ew * tanhf(acc);
        else
            out[(size_t)MFLAT * ST_OUT + (size_t)grow * ST_OUT + (j - ST_OUT)] = acc;
    }
}

// ---------------------------------------------------------------------------
extern "C" void kernel_launch(void* const* d_in, const int* in_sizes, int n_in,
                              void* d_out, int out_size) {
    const float* x       = (const float*)d_in[0];
    const float* adj     = (const float*)d_in[1];
    const float* emb_w   = (const float*)d_in[2];
    const float* gc1_w   = (const float*)d_in[3];
    const float* gc2_w   = (const float*)d_in[4];
    const float* gc3_w   = (const float*)d_in[5];
    const float* st_w1   = (const float*)d_in[6];
    const float* st_b1   = (const float*)d_in[7];
    const float* st_w2   = (const float*)d_in[8];
    const float* st_b2   = (const float*)d_in[9];
    const float* rescale = (const float*)d_in[10];
    float* out = (float*)d_out;

    __half *adjhi, *adjlo, *supphi, *supplo;
    __half *c1hi, *c1lo, *w2hi, *w2lo, *w3hi, *w3lo;
    float* oe;
    cudaGetSymbolAddress((void**)&adjhi,  g_adjhi);
    cudaGetSymbolAddress((void**)&adjlo,  g_adjlo);
    cudaGetSymbolAddress((void**)&supphi, g_supphi);
    cudaGetSymbolAddress((void**)&supplo, g_supplo);
    cudaGetSymbolAddress((void**)&oe,     g_oe);
    cudaGetSymbolAddress((void**)&c1hi,   g_c1hi);
    cudaGetSymbolAddress((void**)&c1lo,   g_c1lo);
    cudaGetSymbolAddress((void**)&w2hi,   g_w2hi);
    cudaGetSymbolAddress((void**)&w2lo,   g_w2lo);
    cudaGetSymbolAddress((void**)&w3hi,   g_w3hi);
    cudaGetSymbolAddress((void**)&w3lo,   g_w3lo);

    cudaFuncSetAttribute(agg_wmma<1>, cudaFuncAttributeMaxDynamicSharedMemorySize, AG_SMEM);
    cudaFuncSetAttribute(agg_wmma<0>, cudaFuncAttributeMaxDynamicSharedMemorySize, AG_SMEM);
    cudaFuncSetAttribute(support_wmma<NFEAT, 1>, cudaFuncAttributeMaxDynamicSharedMemorySize, SP_SMEM);
    cudaFuncSetAttribute(support_wmma<NHID, 3>,  cudaFuncAttributeMaxDynamicSharedMemorySize, SP_SMEM);

    // prep: exactly 2 launches
    const int adjN8 = (Bq * Eq * Nq * Nq) / 8;
    split_kernel<<<(adjN8 + 255) / 256, 256>>>(adj, adjhi, adjlo, adjN8);
    weight_prep_kernel<<<WBLK + (Eq * NFEAT * NHID + 255) / 256, 256>>>(
        gc2_w, gc3_w, emb_w, gc1_w, w2hi, w2lo, w3hi, w3lo, c1hi, c1lo);

    dim3 sgrid(MFLAT / 128, Eq);      // (192, 3)
    dim3 agrid(Nq / 128, Bq, Eq);     // (3, 64, 3)

    support_wmma<NFEAT, 1><<<sgrid, 256, SP_SMEM>>>(x, c1hi, c1lo, supphi, supplo);
    agg_wmma<1><<<agrid, 256, AG_SMEM>>>(adjhi, adjlo, supphi, supplo, oe);
    support_wmma<NHID, 3><<<sgrid, 256, SP_SMEM>>>(oe, w2hi, w2lo, supphi, supplo);
    agg_wmma<1><<<agrid, 256, AG_SMEM>>>(adjhi, adjlo, supphi, supplo, oe);
    support_wmma<NHID, 3><<<sgrid, 256, SP_SMEM>>>(oe, w3hi, w3lo, supphi, supplo);
    agg_wmma<0><<<agrid, 256, AG_SMEM>>>(adjhi, adjlo, supphi, supplo, oe);

    head_kernel<<<MFLAT / 16, 256>>>(oe, st_w1, st_b1, st_w2, st_b2, rescale, out);
}

// round 12
// speedup vs baseline: 3.1009x; 1.0657x over previous
#include <cuda_runtime.h>
#include <cuda_fp16.h>
#include <mma.h>
#include <math.h>

using namespace nvcuda;

#define Bq     64
#define Nq     384
#define NFEAT  16
#define Eq     3
#define NHID   128
#define ST_HID 64
#define ST_OUT 16
#define MFLAT  (Bq * Nq)
#define SCALE_DN 0.0625f
#define SCALE_UP 16.0f

// ---------------- device scratch ----------------
__device__ __half g_adjhi[Bq * Eq * Nq * Nq];
__device__ __half g_adjlo[Bq * Eq * Nq * Nq];
__device__ __half g_supphi[Bq * Eq * Nq * NHID];   // scaled 2^-4
__device__ __half g_supplo[Bq * Eq * Nq * NHID];
__device__ float  g_oe[Bq * Eq * Nq * NHID];       // per-relation fp32
__device__ __half g_hhi[MFLAT * NHID];             // summed h, scaled 2^-4
__device__ __half g_hlo[MFLAT * NHID];
__device__ __half g_h0hi[MFLAT * NFEAT];           // h0 = x@emb^T, scaled 2^-4
__device__ __half g_h0lo[MFLAT * NFEAT];
__device__ __half g_t1hi[Bq * Eq * Nq * NFEAT];    // t1 = adj@h0 (scaled 2^-4)
__device__ __half g_t1lo[Bq * Eq * Nq * NFEAT];
__device__ __half g_w1hi[Eq * NFEAT * NHID];       // gc1_w split (raw)
__device__ __half g_w1lo[Eq * NFEAT * NHID];
__device__ __half g_w2hi[Eq * NHID * NHID];
__device__ __half g_w2lo[Eq * NHID * NHID];
__device__ __half g_w3hi[Eq * NHID * NHID];
__device__ __half g_w3lo[Eq * NHID * NHID];

// ---------------- fp16 Dekker split ----------------
__device__ __forceinline__ void split1h(float v, __half& h, __half& l) {
    h = __float2half_rn(v);
    l = __float2half_rn(v - __half2float(h));
}
struct alignas(16) H8 { __half v[8]; };

__global__ void split_kernel(const float* __restrict__ src,
                             __half* __restrict__ hi, __half* __restrict__ lo,
                             int n8) {
    int i = blockIdx.x * blockDim.x + threadIdx.x;
    if (i >= n8) return;
    float4 a = *(const float4*)(src + (size_t)i * 8);
    float4 b = *(const float4*)(src + (size_t)i * 8 + 4);
    float vv[8] = {a.x, a.y, a.z, a.w, b.x, b.y, b.z, b.w};
    H8 H, L;
#pragma unroll
    for (int j = 0; j < 8; j++) split1h(vv[j], H.v[j], L.v[j]);
    *(H8*)(hi + (size_t)i * 8) = H;
    *(H8*)(lo + (size_t)i * 8) = L;
}

// Fused prep: split gc2/gc3, split gc1 (raw), compute+split h0 (scaled).
#define WN8 ((Eq * NHID * NHID) / 8)    // 6144
#define WBLK ((2 * WN8) / 256)          // 48
#define W1BLK ((Eq * NFEAT * NHID) / 8 / 256 + 1)  // 4
#define H0BLK ((MFLAT * NFEAT) / 256)   // 1536
__global__ void weight_prep_kernel(const float* __restrict__ gc2_w,
                                   const float* __restrict__ gc3_w,
                                   const float* __restrict__ emb_w,
                                   const float* __restrict__ gc1_w,
                                   const float* __restrict__ x,
                                   __half* __restrict__ w2hi, __half* __restrict__ w2lo,
                                   __half* __restrict__ w3hi, __half* __restrict__ w3lo,
                                   __half* __restrict__ w1hi, __half* __restrict__ w1lo,
                                   __half* __restrict__ h0hi, __half* __restrict__ h0lo) {
    int bx = blockIdx.x;
    if (bx < WBLK) {
        int i = bx * 256 + threadIdx.x;
        const float* src;
        __half *hi, *lo;
        if (i < WN8) { src = gc2_w; hi = w2hi; lo = w2lo; }
        else { src = gc3_w; hi = w3hi; lo = w3lo; i -= WN8; }
        float4 a = *(const float4*)(src + (size_t)i * 8);
        float4 b = *(const float4*)(src + (size_t)i * 8 + 4);
        float vv[8] = {a.x, a.y, a.z, a.w, b.x, b.y, b.z, b.w};
        H8 H, L;
#pragma unroll
        for (int j = 0; j < 8; j++) split1h(vv[j], H.v[j], L.v[j]);
        *(H8*)(hi + (size_t)i * 8) = H;
        *(H8*)(lo + (size_t)i * 8) = L;
    } else if (bx < WBLK + W1BLK) {
        int i = (bx - WBLK) * 256 + threadIdx.x;
        if (i >= (Eq * NFEAT * NHID) / 8) return;
        float4 a = *(const float4*)(gc1_w + (size_t)i * 8);
        float4 b = *(const float4*)(gc1_w + (size_t)i * 8 + 4);
        float vv[8] = {a.x, a.y, a.z, a.w, b.x, b.y, b.z, b.w};
        H8 H, L;
#pragma unroll
        for (int j = 0; j < 8; j++) split1h(vv[j], H.v[j], L.v[j]);
        *(H8*)(w1hi + (size_t)i * 8) = H;
        *(H8*)(w1lo + (size_t)i * 8) = L;
    } else {
        int idx = (bx - WBLK - W1BLK) * 256 + threadIdx.x;   // over MFLAT*16
        int row = idx >> 4, f = idx & 15;
        float acc = 0.f;
#pragma unroll
        for (int d = 0; d < NFEAT; d++)
            acc += x[(size_t)row * NFEAT + d] * emb_w[f * NFEAT + d];
        split1h(acc * SCALE_DN, h0hi[idx], h0lo[idx]);
    }
}

// hsum_split: h_scaled = split( 2^-4 * sum_e oe )
__global__ void hsum_split_kernel(const float* __restrict__ oe,
                                  __half* __restrict__ hhi, __half* __restrict__ hlo) {
    int idx = blockIdx.x * 256 + threadIdx.x;
    size_t e8 = (size_t)idx * 8;
    int row = (int)(e8 >> 7), c = (int)(e8 & 127);
    int b = row / Nq, n = row % Nq;
    const size_t eS = (size_t)Nq * NHID;
    const float* base = oe + ((size_t)(b * Eq) * Nq + n) * NHID + c;
    H8 H, L;
#pragma unroll
    for (int q = 0; q < 2; q++) {
        float4 v0 = *(const float4*)(base + q * 4);
        float4 v1 = *(const float4*)(base + eS + q * 4);
        float4 v2 = *(const float4*)(base + 2 * eS + q * 4);
        float s[4] = {(v0.x + v1.x + v2.x) * SCALE_DN, (v0.y + v1.y + v2.y) * SCALE_DN,
                      (v0.z + v1.z + v2.z) * SCALE_DN, (v0.w + v1.w + v2.w) * SCALE_DN};
#pragma unroll
        for (int j = 0; j < 4; j++) split1h(s[j], H.v[q * 4 + j], L.v[q * 4 + j]);
    }
    *(H8*)(hhi + e8) = H;
    *(H8*)(hlo + e8) = L;
}

// ---------------- cp.async ----------------
__device__ __forceinline__ void cpa16(unsigned s, const void* g) {
    asm volatile("cp.async.cg.shared.global [%0], [%1], 16;" :: "r"(s), "l"(g));
}
#define CPA_COMMIT() asm volatile("cp.async.commit_group;" ::: "memory")
#define CPA_WAIT(N)  asm volatile("cp.async.wait_group %0;" :: "n"(N) : "memory")

typedef wmma::fragment<wmma::matrix_a, 16, 16, 16, __half, wmma::row_major> AF;
typedef wmma::fragment<wmma::matrix_b, 16, 16, 16, __half, wmma::row_major> BF;
typedef wmma::fragment<wmma::accumulator, 16, 16, 16, float> CF;

// ---------------- smem layouts (offsets in halfs) ----------------
#define AG_LDA 40
#define LDB_H  136
#define H_AHI 0
#define H_ALO (128 * AG_LDA)
#define H_BHI (2 * 128 * AG_LDA)
#define H_BLO (H_BHI + 32 * LDB_H)
#define STAGE_H (H_BLO + 32 * LDB_H)       // 18944
#define AG_SMEM (2 * STAGE_H * 2)          // 75776 B
#define LDB16 24
#define A16_AHI 0
#define A16_ALO (128 * AG_LDA)
#define A16_BHI (2 * 128 * AG_LDA)
#define A16_BLO (A16_BHI + 32 * LDB16)
#define STAGE16_H (A16_BLO + 32 * LDB16)   // 11776
#define AG16_SMEM (2 * STAGE16_H * 2)      // 47104 B
#define S1_LDA 24
#define S1_AHI 0
#define S1_ALO (128 * S1_LDA)
#define S1_BHI (2 * 128 * S1_LDA)
#define S1_BLO (S1_BHI + 16 * LDB_H)
#define S1_SMEM ((S1_BLO + 16 * LDB_H) * 2)
#define SP_STAGE_H (2 * 128 * AG_LDA)      // 10240 halfs/stage
#define SP_WHI (2 * SP_STAGE_H)            // 20480
#define SP_WLO (SP_WHI + 128 * LDB_H)
#define SP_SMEM ((SP_WLO + 128 * LDB_H) * 2) // 110592 B

// ---------------------------------------------------------------------------
// agg (layers 2/3): oe = act(16 * adj_split @ supp_scaled). grid (3,Bq,Eq)
// ---------------------------------------------------------------------------
__device__ __forceinline__ void ag_load_stage(unsigned sb, const __half* aH,
                                              const __half* aL, const __half* bH,
                                              const __half* bL, int kt, int tid) {
#pragma unroll
    for (int t = 0; t < 2; t++) {
        int idx = tid + t * 256;
        int r = idx >> 2, c8 = idx & 3;
        size_t g = (size_t)r * Nq + kt * 32 + c8 * 8;
        cpa16(sb + (H_AHI + r * AG_LDA + c8 * 8) * 2, aH + g);
        cpa16(sb + (H_ALO + r * AG_LDA + c8 * 8) * 2, aL + g);
    }
#pragma unroll
    for (int t = 0; t < 2; t++) {
        int idx = tid + t * 256;
        int r = idx >> 4, c8 = idx & 15;
        size_t g = (size_t)(kt * 32 + r) * NHID + c8 * 8;
        cpa16(sb + (H_BHI + r * LDB_H + c8 * 8) * 2, bH + g);
        cpa16(sb + (H_BLO + r * LDB_H + c8 * 8) * 2, bL + g);
    }
}

template <int RELU>
__global__ __launch_bounds__(256, 2)
void agg_wmma(const __half* __restrict__ adjhi, const __half* __restrict__ adjlo,
              const __half* __restrict__ shi, const __half* __restrict__ slo,
              float* __restrict__ oe) {
    extern __shared__ __half smh[];
    const unsigned sbase = (unsigned)__cvta_generic_to_shared(smh);

    const int tid = threadIdx.x;
    const int wid = tid >> 5;
    const int wm = wid >> 1, wn = wid & 1;
    const int m0 = blockIdx.x * 128;
    const int b = blockIdx.y, e = blockIdx.z;

    const __half* aH = adjhi + ((size_t)(b * Eq + e) * Nq + m0) * Nq;
    const __half* aL = adjlo + ((size_t)(b * Eq + e) * Nq + m0) * Nq;
    const __half* bH = shi + (size_t)(b * Eq + e) * Nq * NHID;
    const __half* bL = slo + (size_t)(b * Eq + e) * Nq * NHID;

    CF c[2][4];
#pragma unroll
    for (int i = 0; i < 2; i++)
#pragma unroll
        for (int j = 0; j < 4; j++) wmma::fill_fragment(c[i][j], 0.f);

    constexpr int KT = Nq / 32;
    ag_load_stage(sbase, aH, aL, bH, bL, 0, tid);
    CPA_COMMIT();

    for (int kt = 0; kt < KT; kt++) {
        if (kt + 1 < KT) {
            ag_load_stage(sbase + ((kt + 1) & 1) * STAGE_H * 2,
                          aH, aL, bH, bL, kt + 1, tid);
            CPA_COMMIT();
            CPA_WAIT(1);
        } else {
            CPA_WAIT(0);
        }
        __syncthreads();

        const __half* S = smh + (kt & 1) * STAGE_H;
#pragma unroll
        for (int k16 = 0; k16 < 2; k16++) {
            AF afH[2], afL[2];
#pragma unroll
            for (int i = 0; i < 2; i++) {
                const __half* p = S + H_AHI + (wm * 32 + i * 16) * AG_LDA + k16 * 16;
                wmma::load_matrix_sync(afH[i], p, AG_LDA);
                wmma::load_matrix_sync(afL[i], p + (H_ALO - H_AHI), AG_LDA);
            }
#pragma unroll
            for (int j = 0; j < 4; j++) {
                BF bfH, bfL;
                const __half* p = S + H_BHI + (k16 * 16) * LDB_H + wn * 64 + j * 16;
                wmma::load_matrix_sync(bfH, p, LDB_H);
                wmma::load_matrix_sync(bfL, p + (H_BLO - H_BHI), LDB_H);
#pragma unroll
                for (int i = 0; i < 2; i++) {
                    wmma::mma_sync(c[i][j], afH[i], bfH, c[i][j]);
                    wmma::mma_sync(c[i][j], afH[i], bfL, c[i][j]);
                    wmma::mma_sync(c[i][j], afL[i], bfH, c[i][j]);
                }
            }
        }
        __syncthreads();
    }

#pragma unroll
    for (int i = 0; i < 2; i++)
#pragma unroll
        for (int j = 0; j < 4; j++) {
#pragma unroll
            for (int t = 0; t < c[i][j].num_elements; t++) {
                float v = c[i][j].x[t] * SCALE_UP;
                c[i][j].x[t] = RELU ? fmaxf(v, 0.f) : v;
            }
            float* op = oe + ((size_t)(b * Eq + e) * Nq + m0 + wm * 32 + i * 16) * NHID
                           + wn * 64 + j * 16;
            wmma::store_matrix_sync(op, c[i][j], NHID, wmma::mem_row_major);
        }
}

// ---------------------------------------------------------------------------
// agg16: t1_scaled[b,e] = adj_split @ h0_scaled  (H=16). grid (3,Bq,Eq)
// ---------------------------------------------------------------------------
__device__ __forceinline__ void ag16_load_stage(unsigned sb, const __half* aH,
                                                const __half* aL, const __half* bH,
                                                const __half* bL, int kt, int tid) {
#pragma unroll
    for (int t = 0; t < 2; t++) {
        int idx = tid + t * 256;
        int r = idx >> 2, c8 = idx & 3;
        size_t g = (size_t)r * Nq + kt * 32 + c8 * 8;
        cpa16(sb + (A16_AHI + r * AG_LDA + c8 * 8) * 2, aH + g);
        cpa16(sb + (A16_ALO + r * AG_LDA + c8 * 8) * 2, aL + g);
    }
    if (tid < 64) {
        int r = tid >> 1, c8 = tid & 1;
        size_t g = (size_t)(kt * 32 + r) * NFEAT + c8 * 8;
        cpa16(sb + (A16_BHI + r * LDB16 + c8 * 8) * 2, bH + g);
        cpa16(sb + (A16_BLO + r * LDB16 + c8 * 8) * 2, bL + g);
    }
}

__global__ __launch_bounds__(256)
void agg16_wmma(const __half* __restrict__ adjhi, const __half* __restrict__ adjlo,
                const __half* __restrict__ h0hi, const __half* __restrict__ h0lo,
                __half* __restrict__ t1hi, __half* __restrict__ t1lo) {
    extern __shared__ __half smh[];
    const unsigned sbase = (unsigned)__cvta_generic_to_shared(smh);

    const int tid = threadIdx.x;
    const int wid = tid >> 5, lane = tid & 31;
    const int m0 = blockIdx.x * 128;
    const int b = blockIdx.y, e = blockIdx.z;

    const __half* aH = adjhi + ((size_t)(b * Eq + e) * Nq + m0) * Nq;
    const __half* aL = adjlo + ((size_t)(b * Eq + e) * Nq + m0) * Nq;
    const __half* bH = h0hi + (size_t)b * Nq * NFEAT;
    const __half* bL = h0lo + (size_t)b * Nq * NFEAT;

    CF acc;
    wmma::fill_fragment(acc, 0.f);

    constexpr int KT = Nq / 32;
    ag16_load_stage(sbase, aH, aL, bH, bL, 0, tid);
    CPA_COMMIT();

    for (int kt = 0; kt < KT; kt++) {
        if (kt + 1 < KT) {
            ag16_load_stage(sbase + ((kt + 1) & 1) * STAGE16_H * 2,
                            aH, aL, bH, bL, kt + 1, tid);
            CPA_COMMIT();
            CPA_WAIT(1);
        } else {
            CPA_WAIT(0);
        }
        __syncthreads();

        const __half* S = smh + (kt & 1) * STAGE16_H;
#pragma unroll
        for (int k16 = 0; k16 < 2; k16++) {
            AF afH, afL;
            const __half* pa = S + A16_AHI + (wid * 16) * AG_LDA + k16 * 16;
            wmma::load_matrix_sync(afH, pa, AG_LDA);
            wmma::load_matrix_sync(afL, pa + (A16_ALO - A16_AHI), AG_LDA);
            BF bfH, bfL;
            const __half* pb = S + A16_BHI + (k16 * 16) * LDB16;
            wmma::load_matrix_sync(bfH, pb, LDB16);
            wmma::load_matrix_sync(bfL, pb + (A16_BLO - A16_BHI), LDB16);
            wmma::mma_sync(acc, afH, bfH, acc);
            wmma::mma_sync(acc, afH, bfL, acc);
            wmma::mma_sync(acc, afL, bfH, acc);
        }
        __syncthreads();
    }

    __syncthreads();
    float* E = (float*)smh + wid * (16 * 20);
    wmma::store_matrix_sync(E, acc, 20, wmma::mem_row_major);
    __syncwarp();
    {
        int r = lane >> 1, c0 = (lane & 1) * 8;
        H8 H, L;
#pragma unroll
        for (int j = 0; j < 8; j++)
            split1h(E[r * 20 + c0 + j], H.v[j], L.v[j]);
        size_t o = ((size_t)(b * Eq + e) * Nq + m0 + wid * 16 + r) * NFEAT + c0;
        *(H8*)(t1hi + o) = H;
        *(H8*)(t1lo + o) = L;
    }
}

// ---------------------------------------------------------------------------
// support1: oe = relu(16 * (t1_scaled @ gc1_w[e]_split)). grid (MFLAT/128, Eq)
// ---------------------------------------------------------------------------
__global__ __launch_bounds__(256, 2)
void support1_wmma(const __half* __restrict__ t1hi, const __half* __restrict__ t1lo,
                   const __half* __restrict__ w1hi, const __half* __restrict__ w1lo,
                   float* __restrict__ oe) {
    extern __shared__ __half smh[];
    __half* Ahi = smh + S1_AHI;
    __half* Alo = smh + S1_ALO;
    __half* Bhi = smh + S1_BHI;
    __half* Blo = smh + S1_BLO;

    const int tid = threadIdx.x;
    const int wid = tid >> 5;
    const int wm = wid >> 1, wn = wid & 1;
    const int e = blockIdx.y;
    const int m0 = blockIdx.x * 128;
    const int b = m0 / Nq, n0 = m0 % Nq;

    {
        int r = tid >> 1, c8 = tid & 1;
        size_t g = ((size_t)(b * Eq + e) * Nq + n0 + r) * NFEAT + c8 * 8;
        *(uint4*)&Ahi[r * S1_LDA + c8 * 8] = *(const uint4*)(t1hi + g);
        *(uint4*)&Alo[r * S1_LDA + c8 * 8] = *(const uint4*)(t1lo + g);
    }
    {
        int r = tid >> 4, c8 = tid & 15;
        size_t g = (size_t)(e * NFEAT + r) * NHID + c8 * 8;
        *(uint4*)&Bhi[r * LDB_H + c8 * 8] = *(const uint4*)(w1hi + g);
        *(uint4*)&Blo[r * LDB_H + c8 * 8] = *(const uint4*)(w1lo + g);
    }
    __syncthreads();

    CF c[2][4];
#pragma unroll
    for (int i = 0; i < 2; i++)
#pragma unroll
        for (int j = 0; j < 4; j++) wmma::fill_fragment(c[i][j], 0.f);

    AF afH[2], afL[2];
#pragma unroll
    for (int i = 0; i < 2; i++) {
        const __half* p = Ahi + (wm * 32 + i * 16) * S1_LDA;
        wmma::load_matrix_sync(afH[i], p, S1_LDA);
        wmma::load_matrix_sync(afL[i], p + (S1_ALO - S1_AHI), S1_LDA);
    }
#pragma unroll
    for (int j = 0; j < 4; j++) {
        BF bfH, bfL;
        const __half* p = Bhi + wn * 64 + j * 16;
        wmma::load_matrix_sync(bfH, p, LDB_H);
        wmma::load_matrix_sync(bfL, p + (S1_BLO - S1_BHI), LDB_H);
#pragma unroll
        for (int i = 0; i < 2; i++) {
            wmma::mma_sync(c[i][j], afH[i], bfH, c[i][j]);
            wmma::mma_sync(c[i][j], afH[i], bfL, c[i][j]);
            wmma::mma_sync(c[i][j], afL[i], bfH, c[i][j]);
        }
    }

#pragma unroll
    for (int i = 0; i < 2; i++)
#pragma unroll
        for (int j = 0; j < 4; j++) {
#pragma unroll
            for (int t = 0; t < c[i][j].num_elements; t++)
                c[i][j].x[t] = fmaxf(c[i][j].x[t] * SCALE_UP, 0.f);
            float* op = oe + ((size_t)(b * Eq + e) * Nq + n0 + wm * 32 + i * 16) * NHID
                           + wn * 64 + j * 16;
            wmma::store_matrix_sync(op, c[i][j], NHID, wmma::mem_row_major);
        }
}

// ---------------------------------------------------------------------------
// support23: supp_scaled = h_scaled @ W[e]_split. W resident, A double-buffered.
// grid (MFLAT/128, Eq)
// ---------------------------------------------------------------------------
__device__ __forceinline__ void sp_load_stage(unsigned sb, const __half* aH,
                                              const __half* aL, int kt, int tid) {
#pragma unroll
    for (int t = 0; t < 2; t++) {
        int idx = tid + t * 256;
        int r = idx >> 2, c8 = idx & 3;
        size_t g = (size_t)r * NHID + kt * 32 + c8 * 8;
        cpa16(sb + (r * AG_LDA + c8 * 8) * 2, aH + g);
        cpa16(sb + (128 * AG_LDA + r * AG_LDA + c8 * 8) * 2, aL + g);
    }
}

__global__ __launch_bounds__(256, 2)
void support23_wmma(const __half* __restrict__ hhi, const __half* __restrict__ hlo,
                    const __half* __restrict__ whi, const __half* __restrict__ wlo,
                    __half* __restrict__ supphi, __half* __restrict__ supplo) {
    extern __shared__ __half smh[];
    const unsigned sbase = (unsigned)__cvta_generic_to_shared(smh);
    __half* WHI = smh + SP_WHI;
    __half* WLO = smh + SP_WLO;

    const int tid = threadIdx.x;
    const int wid = tid >> 5, lane = tid & 31;
    const int wm = wid >> 1, wn = wid & 1;
    const int e = blockIdx.y;
    const int m0 = blockIdx.x * 128;
    const int b = m0 / Nq, n0 = m0 % Nq;

    const __half* aH = hhi + (size_t)m0 * NHID;
    const __half* aL = hlo + (size_t)m0 * NHID;
    const __half* wH = whi + (size_t)e * NHID * NHID;
    const __half* wL = wlo + (size_t)e * NHID * NHID;

#pragma unroll
    for (int t = 0; t < 8; t++) {
        int idx = tid + t * 256;
        int r = idx >> 4, c8 = idx & 15;
        size_t g = (size_t)r * NHID + c8 * 8;
        *(uint4*)&WHI[r * LDB_H + c8 * 8] = *(const uint4*)(wH + g);
        *(uint4*)&WLO[r * LDB_H + c8 * 8] = *(const uint4*)(wL + g);
    }

    CF c[2][4];
#pragma unroll
    for (int i = 0; i < 2; i++)
#pragma unroll
        for (int j = 0; j < 4; j++) wmma::fill_fragment(c[i][j], 0.f);

    sp_load_stage(sbase, aH, aL, 0, tid);
    CPA_COMMIT();
    constexpr int KT = NHID / 32;   // 4

#pragma unroll
    for (int kt = 0; kt < KT; kt++) {
        if (kt + 1 < KT) {
            sp_load_stage(sbase + ((kt + 1) & 1) * SP_STAGE_H * 2, aH, aL, kt + 1, tid);
            CPA_COMMIT();
            CPA_WAIT(1);
        } else {
            CPA_WAIT(0);
        }
        __syncthreads();

        const __half* S = smh + (kt & 1) * SP_STAGE_H;
#pragma unroll
        for (int k16 = 0; k16 < 2; k16++) {
            AF afH[2], afL[2];
#pragma unroll
            for (int i = 0; i < 2; i++) {
                const __half* p = S + (wm * 32 + i * 16) * AG_LDA + k16 * 16;
                wmma::load_matrix_sync(afH[i], p, AG_LDA);
                wmma::load_matrix_sync(afL[i], p + 128 * AG_LDA, AG_LDA);
            }
#pragma unroll
            for (int j = 0; j < 4; j++) {
                BF bfH, bfL;
                const __half* p = WHI + (kt * 32 + k16 * 16) * LDB_H + wn * 64 + j * 16;
                wmma::load_matrix_sync(bfH, p, LDB_H);
                wmma::load_matrix_sync(bfL, p + (SP_WLO - SP_WHI), LDB_H);
#pragma unroll
                for (int i = 0; i < 2; i++) {
                    wmma::mma_sync(c[i][j], afH[i], bfH, c[i][j]);
                    wmma::mma_sync(c[i][j], afH[i], bfL, c[i][j]);
                    wmma::mma_sync(c[i][j], afL[i], bfH, c[i][j]);
                }
            }
        }
        __syncthreads();
    }

    __syncthreads();
    float* E = (float*)(smh + SP_WHI) + wid * (32 * 68);
#pragma unroll
    for (int i = 0; i < 2; i++)
#pragma unroll
        for (int j = 0; j < 4; j++)
            wmma::store_matrix_sync(E + (i * 16) * 68 + j * 16, c[i][j], 68,
                                    wmma::mem_row_major);
    __syncwarp();
#pragma unroll
    for (int t = 0; t < 16; t++) {              // FIX: 512 quads per warp (32 rows)
        int p = lane + t * 32;
        int r = p >> 4, c4 = (p & 15) * 4;
        float4 v = *(float4*)&E[r * 68 + c4];
        __half h0, h1, h2, h3, l0, l1, l2, l3;
        split1h(v.x, h0, l0); split1h(v.y, h1, l1);
        split1h(v.z, h2, l2); split1h(v.w, h3, l3);
        size_t o = ((size_t)(b * Eq + e) * Nq + n0 + wm * 32 + r) * NHID + wn * 64 + c4;
        half2 hA = __halves2half2(h0, h1), hB = __halves2half2(h2, h3);
        half2 lA = __halves2half2(l0, l1), lB = __halves2half2(l2, l3);
        uint2 uh, ul;
        uh.x = *(unsigned*)&hA; uh.y = *(unsigned*)&hB;
        ul.x = *(unsigned*)&lA; ul.y = *(unsigned*)&lB;
        *(uint2*)(supphi + o) = uh;
        *(uint2*)(supplo + o) = ul;
    }
}

// ---------------------------------------------------------------------------
// Head
// ---------------------------------------------------------------------------
__global__ __launch_bounds__(256)
void head_kernel(const float* __restrict__ oe,
                 const float* __restrict__ w1, const float* __restrict__ b1,
                 const float* __restrict__ w2, const float* __restrict__ b2,
                 const float* __restrict__ rescale, float* __restrict__ out) {
    __shared__ float w1T[NHID][68];
    __shared__ float hS[16][NHID];
    __shared__ float z1S[16][68];

    const int tid = threadIdx.x;
    const int row0 = blockIdx.x * 16;
    const int b = row0 / Nq;
    const int n0 = row0 % Nq;

    for (int i = tid; i < ST_HID * NHID; i += 256) {
        int hid = i >> 7, d = i & 127;
        w1T[d][hid] = w1[i];
    }
    const float* base = oe + (size_t)(b * Eq) * Nq * NHID + (size_t)n0 * NHID;
    const size_t eS = (size_t)Nq * NHID;
#pragma unroll
    for (int t = 0; t < 2; t++) {
        int idx = tid + t * 256;
        int r = idx >> 5, c = idx & 31;
        float4 v0 = *(const float4*)(base + (size_t)r * NHID + c * 4);
        float4 v1 = *(const float4*)(base + eS + (size_t)r * NHID + c * 4);
        float4 v2 = *(const float4*)(base + 2 * eS + (size_t)r * NHID + c * 4);
        *(float4*)&hS[r][c * 4] = make_float4(v0.x + v1.x + v2.x, v0.y + v1.y + v2.y,
                                              v0.z + v1.z + v2.z, v0.w + v1.w + v2.w);
    }
    __syncthreads();

    {
        int row = tid >> 4, hg = tid & 15;
        float a0 = b1[hg * 4 + 0], a1 = b1[hg * 4 + 1];
        float a2 = b1[hg * 4 + 2], a3 = b1[hg * 4 + 3];
#pragma unroll 8
        for (int d = 0; d < NHID; d++) {
            float h = hS[row][d];
            float4 w = *(const float4*)&w1T[d][hg * 4];
            a0 = fmaf(h, w.x, a0); a1 = fmaf(h, w.y, a1);
            a2 = fmaf(h, w.z, a2); a3 = fmaf(h, w.w, a3);
        }
        z1S[row][hg * 4 + 0] = tanhf(a0);
        z1S[row][hg * 4 + 1] = tanhf(a1);
        z1S[row][hg * 4 + 2] = tanhf(a2);
        z1S[row][hg * 4 + 3] = tanhf(a3);
    }
    __syncthreads();

    const float ew = expf(rescale[0]);
    for (int p = tid; p < 16 * 32; p += 256) {
        int row = p >> 5, j = p & 31;
        float acc = b2[j];
#pragma unroll 8
        for (int k = 0; k < ST_HID; k++)
            acc += z1S[row][k] * w2[j * ST_HID + k];
        int grow = row0 + row;
        if (j < ST_OUT)
            out[(size_t)grow * ST_OUT + j] = ew * tanhf(acc);
        else
            out[(size_t)MFLAT * ST_OUT + (size_t)grow * ST_OUT + (j - ST_OUT)] = acc;
    }
}

// ---------------------------------------------------------------------------
extern "C" void kernel_launch(void* const* d_in, const int* in_sizes, int n_in,
                              void* d_out, int out_size) {
    const float* x       = (const float*)d_in[0];
    const float* adj     = (const float*)d_in[1];
    const float* emb_w   = (const float*)d_in[2];
    const float* gc1_w   = (const float*)d_in[3];
    const float* gc2_w   = (const float*)d_in[4];
    const float* gc3_w   = (const float*)d_in[5];
    const float* st_w1   = (const float*)d_in[6];
    const float* st_b1   = (const float*)d_in[7];
    const float* st_w2   = (const float*)d_in[8];
    const float* st_b2   = (const float*)d_in[9];
    const float* rescale = (const float*)d_in[10];
    float* out = (float*)d_out;

    __half *adjhi, *adjlo, *supphi, *supplo, *hhi, *hlo, *h0hi, *h0lo, *t1hi, *t1lo;
    __half *w1hi, *w1lo, *w2hi, *w2lo, *w3hi, *w3lo;
    float* oe;
    cudaGetSymbolAddress((void**)&adjhi,  g_adjhi);
    cudaGetSymbolAddress((void**)&adjlo,  g_adjlo);
    cudaGetSymbolAddress((void**)&supphi, g_supphi);
    cudaGetSymbolAddress((void**)&supplo, g_supplo);
    cudaGetSymbolAddress((void**)&oe,     g_oe);
    cudaGetSymbolAddress((void**)&hhi,    g_hhi);
    cudaGetSymbolAddress((void**)&hlo,    g_hlo);
    cudaGetSymbolAddress((void**)&h0hi,   g_h0hi);
    cudaGetSymbolAddress((void**)&h0lo,   g_h0lo);
    cudaGetSymbolAddress((void**)&t1hi,   g_t1hi);
    cudaGetSymbolAddress((void**)&t1lo,   g_t1lo);
    cudaGetSymbolAddress((void**)&w1hi,   g_w1hi);
    cudaGetSymbolAddress((void**)&w1lo,   g_w1lo);
    cudaGetSymbolAddress((void**)&w2hi,   g_w2hi);
    cudaGetSymbolAddress((void**)&w2lo,   g_w2lo);
    cudaGetSymbolAddress((void**)&w3hi,   g_w3hi);
    cudaGetSymbolAddress((void**)&w3lo,   g_w3lo);

    cudaFuncSetAttribute(agg_wmma<1>, cudaFuncAttributeMaxDynamicSharedMemorySize, AG_SMEM);
    cudaFuncSetAttribute(agg_wmma<0>, cudaFuncAttributeMaxDynamicSharedMemorySize, AG_SMEM);
    cudaFuncSetAttribute(agg16_wmma, cudaFuncAttributeMaxDynamicSharedMemorySize, AG16_SMEM);
    cudaFuncSetAttribute(support1_wmma, cudaFuncAttributeMaxDynamicSharedMemorySize, S1_SMEM);
    cudaFuncSetAttribute(support23_wmma, cudaFuncAttributeMaxDynamicSharedMemorySize, SP_SMEM);

    const int adjN8 = (Bq * Eq * Nq * Nq) / 8;
    split_kernel<<<(adjN8 + 255) / 256, 256>>>(adj, adjhi, adjlo, adjN8);
    weight_prep_kernel<<<WBLK + W1BLK + H0BLK, 256>>>(
        gc2_w, gc3_w, emb_w, gc1_w, x,
        w2hi, w2lo, w3hi, w3lo, w1hi, w1lo, h0hi, h0lo);

    dim3 agrid(Nq / 128, Bq, Eq);     // (3, 64, 3)
    dim3 sgrid(MFLAT / 128, Eq);      // (192, 3)
    const int hsumBlocks = (MFLAT * NHID) / (256 * 8);

    // Layer 1 (reordered): t1 = adj@h0, then oe = relu(t1@gc1_w)
    agg16_wmma<<<agrid, 256, AG16_SMEM>>>(adjhi, adjlo, h0hi, h0lo, t1hi, t1lo);
    support1_wmma<<<sgrid, 256, S1_SMEM>>>(t1hi, t1lo, w1hi, w1lo, oe);
    // Layer 2
    hsum_split_kernel<<<hsumBlocks, 256>>>(oe, hhi, hlo);
    support23_wmma<<<sgrid, 256, SP_SMEM>>>(hhi, hlo, w2hi, w2lo, supphi, supplo);
    agg_wmma<1><<<agrid, 256, AG_SMEM>>>(adjhi, adjlo, supphi, supplo, oe);
    // Layer 3
    hsum_split_kernel<<<hsumBlocks, 256>>>(oe, hhi, hlo);
    support23_wmma<<<sgrid, 256, SP_SMEM>>>(hhi, hlo, w3hi, w3lo, supphi, supplo);
    agg_wmma<0><<<agrid, 256, AG_SMEM>>>(adjhi, adjlo, supphi, supplo, oe);

    // Head
    head_kernel<<<MFLAT / 16, 256>>>(oe, st_w1, st_b1, st_w2, st_b2, rescale, out);
}

// round 13
// speedup vs baseline: 3.1063x; 1.0018x over previous
#include <cuda_runtime.h>
#include <cuda_fp16.h>
#include <mma.h>
#include <math.h>

using namespace nvcuda;

#define Bq     64
#define Nq     384
#define NFEAT  16
#define Eq     3
#define NHID   128
#define ST_HID 64
#define ST_OUT 16
#define MFLAT  (Bq * Nq)
#define SCALE_DN 0.0625f
#define SCALE_UP 16.0f

// ---------------- device scratch ----------------
__device__ __half g_adjhi[Bq * Eq * Nq * Nq];
__device__ __half g_adjlo[Bq * Eq * Nq * Nq];
__device__ __half g_supphi[Bq * Eq * Nq * NHID];   // scaled 2^-4
__device__ __half g_supplo[Bq * Eq * Nq * NHID];
__device__ float  g_oe[Bq * Eq * Nq * NHID];       // per-relation fp32
__device__ __half g_hhi[MFLAT * NHID];             // summed h, scaled 2^-4
__device__ __half g_hlo[MFLAT * NHID];
__device__ __half g_h0hi[MFLAT * NFEAT];           // h0 = x@emb^T, scaled 2^-4
__device__ __half g_h0lo[MFLAT * NFEAT];
__device__ __half g_t1hi[Bq * Eq * Nq * NFEAT];    // t1 = adj@h0 (scaled 2^-4)
__device__ __half g_t1lo[Bq * Eq * Nq * NFEAT];
__device__ __half g_w1hi[Eq * NFEAT * NHID];       // gc1_w split (raw)
__device__ __half g_w1lo[Eq * NFEAT * NHID];
__device__ __half g_w2hi[Eq * NHID * NHID];
__device__ __half g_w2lo[Eq * NHID * NHID];
__device__ __half g_w3hi[Eq * NHID * NHID];
__device__ __half g_w3lo[Eq * NHID * NHID];

// ---------------- fp16 Dekker split ----------------
__device__ __forceinline__ void split1h(float v, __half& h, __half& l) {
    h = __float2half_rn(v);
    l = __float2half_rn(v - __half2float(h));
}
struct alignas(16) H8 { __half v[8]; };

__global__ void split_kernel(const float* __restrict__ src,
                             __half* __restrict__ hi, __half* __restrict__ lo,
                             int n8) {
    int i = blockIdx.x * blockDim.x + threadIdx.x;
    if (i >= n8) return;
    float4 a = *(const float4*)(src + (size_t)i * 8);
    float4 b = *(const float4*)(src + (size_t)i * 8 + 4);
    float vv[8] = {a.x, a.y, a.z, a.w, b.x, b.y, b.z, b.w};
    H8 H, L;
#pragma unroll
    for (int j = 0; j < 8; j++) split1h(vv[j], H.v[j], L.v[j]);
    *(H8*)(hi + (size_t)i * 8) = H;
    *(H8*)(lo + (size_t)i * 8) = L;
}

// Fused prep: split gc2/gc3, split gc1 (raw), compute+split h0 (scaled).
#define WN8 ((Eq * NHID * NHID) / 8)    // 6144
#define WBLK ((2 * WN8) / 256)          // 48
#define W1BLK ((Eq * NFEAT * NHID) / 8 / 256 + 1)  // 4
#define H0BLK ((MFLAT * NFEAT) / 256)   // 1536
__global__ void weight_prep_kernel(const float* __restrict__ gc2_w,
                                   const float* __restrict__ gc3_w,
                                   const float* __restrict__ emb_w,
                                   const float* __restrict__ gc1_w,
                                   const float* __restrict__ x,
                                   __half* __restrict__ w2hi, __half* __restrict__ w2lo,
                                   __half* __restrict__ w3hi, __half* __restrict__ w3lo,
                                   __half* __restrict__ w1hi, __half* __restrict__ w1lo,
                                   __half* __restrict__ h0hi, __half* __restrict__ h0lo) {
    int bx = blockIdx.x;
    if (bx < WBLK) {
        int i = bx * 256 + threadIdx.x;
        const float* src;
        __half *hi, *lo;
        if (i < WN8) { src = gc2_w; hi = w2hi; lo = w2lo; }
        else { src = gc3_w; hi = w3hi; lo = w3lo; i -= WN8; }
        float4 a = *(const float4*)(src + (size_t)i * 8);
        float4 b = *(const float4*)(src + (size_t)i * 8 + 4);
        float vv[8] = {a.x, a.y, a.z, a.w, b.x, b.y, b.z, b.w};
        H8 H, L;
#pragma unroll
        for (int j = 0; j < 8; j++) split1h(vv[j], H.v[j], L.v[j]);
        *(H8*)(hi + (size_t)i * 8) = H;
        *(H8*)(lo + (size_t)i * 8) = L;
    } else if (bx < WBLK + W1BLK) {
        int i = (bx - WBLK) * 256 + threadIdx.x;
        if (i >= (Eq * NFEAT * NHID) / 8) return;
        float4 a = *(const float4*)(gc1_w + (size_t)i * 8);
        float4 b = *(const float4*)(gc1_w + (size_t)i * 8 + 4);
        float vv[8] = {a.x, a.y, a.z, a.w, b.x, b.y, b.z, b.w};
        H8 H, L;
#pragma unroll
        for (int j = 0; j < 8; j++) split1h(vv[j], H.v[j], L.v[j]);
        *(H8*)(w1hi + (size_t)i * 8) = H;
        *(H8*)(w1lo + (size_t)i * 8) = L;
    } else {
        int idx = (bx - WBLK - W1BLK) * 256 + threadIdx.x;   // over MFLAT*16
        int row = idx >> 4, f = idx & 15;
        float acc = 0.f;
#pragma unroll
        for (int d = 0; d < NFEAT; d++)
            acc += x[(size_t)row * NFEAT + d] * emb_w[f * NFEAT + d];
        split1h(acc * SCALE_DN, h0hi[idx], h0lo[idx]);
    }
}

// hsum_split: h_scaled = split( 2^-4 * sum_e oe )
__global__ void hsum_split_kernel(const float* __restrict__ oe,
                                  __half* __restrict__ hhi, __half* __restrict__ hlo) {
    int idx = blockIdx.x * 256 + threadIdx.x;
    size_t e8 = (size_t)idx * 8;
    int row = (int)(e8 >> 7), c = (int)(e8 & 127);
    int b = row / Nq, n = row % Nq;
    const size_t eS = (size_t)Nq * NHID;
    const float* base = oe + ((size_t)(b * Eq) * Nq + n) * NHID + c;
    H8 H, L;
#pragma unroll
    for (int q = 0; q < 2; q++) {
        float4 v0 = *(const float4*)(base + q * 4);
        float4 v1 = *(const float4*)(base + eS + q * 4);
        float4 v2 = *(const float4*)(base + 2 * eS + q * 4);
        float s[4] = {(v0.x + v1.x + v2.x) * SCALE_DN, (v0.y + v1.y + v2.y) * SCALE_DN,
                      (v0.z + v1.z + v2.z) * SCALE_DN, (v0.w + v1.w + v2.w) * SCALE_DN};
#pragma unroll
        for (int j = 0; j < 4; j++) split1h(s[j], H.v[q * 4 + j], L.v[q * 4 + j]);
    }
    *(H8*)(hhi + e8) = H;
    *(H8*)(hlo + e8) = L;
}

// ---------------- cp.async ----------------
__device__ __forceinline__ void cpa16(unsigned s, const void* g) {
    asm volatile("cp.async.cg.shared.global [%0], [%1], 16;" :: "r"(s), "l"(g));
}
#define CPA_COMMIT() asm volatile("cp.async.commit_group;" ::: "memory")
#define CPA_WAIT(N)  asm volatile("cp.async.wait_group %0;" :: "n"(N) : "memory")

typedef wmma::fragment<wmma::matrix_a, 16, 16, 16, __half, wmma::row_major> AF;
typedef wmma::fragment<wmma::matrix_b, 16, 16, 16, __half, wmma::row_major> BF;
typedef wmma::fragment<wmma::accumulator, 16, 16, 16, float> CF;

// ---------------- smem layouts (offsets in halfs) ----------------
#define AG_LDA 40
#define LDB_H  136
#define H_AHI 0
#define H_ALO (128 * AG_LDA)
#define H_BHI (2 * 128 * AG_LDA)
#define H_BLO (H_BHI + 32 * LDB_H)
#define STAGE_H (H_BLO + 32 * LDB_H)       // 18944 halfs
#define AG_SMEM (2 * STAGE_H * 2)          // 75776 B (also used by support23)
#define LDB16 24
#define A16_AHI 0
#define A16_ALO (128 * AG_LDA)
#define A16_BHI (2 * 128 * AG_LDA)
#define A16_BLO (A16_BHI + 32 * LDB16)
#define STAGE16_H (A16_BLO + 32 * LDB16)   // 11776
#define AG16_SMEM (2 * STAGE16_H * 2)      // 47104 B
#define S1_LDA 24
#define S1_AHI 0
#define S1_ALO (128 * S1_LDA)
#define S1_BHI (2 * 128 * S1_LDA)
#define S1_BLO (S1_BHI + 16 * LDB_H)
#define S1_SMEM ((S1_BLO + 16 * LDB_H) * 2)

// ---------------------------------------------------------------------------
// Generic two-stage tile loader: A[128 x 32] rows stride AStride (halfs),
// B[32 x 128] rows stride 128. Used by agg (AStride=Nq) and support23 (NHID).
// ---------------------------------------------------------------------------
__device__ __forceinline__ void gm_load_stage(unsigned sb, const __half* aH,
                                              const __half* aL, const __half* bH,
                                              const __half* bL, int kt, int tid,
                                              int aStride) {
#pragma unroll
    for (int t = 0; t < 2; t++) {
        int idx = tid + t * 256;
        int r = idx >> 2, c8 = idx & 3;
        size_t g = (size_t)r * aStride + kt * 32 + c8 * 8;
        cpa16(sb + (H_AHI + r * AG_LDA + c8 * 8) * 2, aH + g);
        cpa16(sb + (H_ALO + r * AG_LDA + c8 * 8) * 2, aL + g);
    }
#pragma unroll
    for (int t = 0; t < 2; t++) {
        int idx = tid + t * 256;
        int r = idx >> 4, c8 = idx & 15;
        size_t g = (size_t)(kt * 32 + r) * NHID + c8 * 8;
        cpa16(sb + (H_BHI + r * LDB_H + c8 * 8) * 2, bH + g);
        cpa16(sb + (H_BLO + r * LDB_H + c8 * 8) * 2, bL + g);
    }
}

// Shared mainloop: accumulates over KT k-tiles into c[2][4].
template <int KT>
__device__ __forceinline__ void gemm_mainloop(
        __half* smh, unsigned sbase, const __half* aH, const __half* aL,
        const __half* bH, const __half* bL, int aStride, int tid,
        int wm, int wn, CF (&c)[2][4]) {
    gm_load_stage(sbase, aH, aL, bH, bL, 0, tid, aStride);
    CPA_COMMIT();
    for (int kt = 0; kt < KT; kt++) {
        if (kt + 1 < KT) {
            gm_load_stage(sbase + ((kt + 1) & 1) * STAGE_H * 2,
                          aH, aL, bH, bL, kt + 1, tid, aStride);
            CPA_COMMIT();
            CPA_WAIT(1);
        } else {
            CPA_WAIT(0);
        }
        __syncthreads();

        const __half* S = smh + (kt & 1) * STAGE_H;
#pragma unroll
        for (int k16 = 0; k16 < 2; k16++) {
            AF afH[2], afL[2];
#pragma unroll
            for (int i = 0; i < 2; i++) {
                const __half* p = S + H_AHI + (wm * 32 + i * 16) * AG_LDA + k16 * 16;
                wmma::load_matrix_sync(afH[i], p, AG_LDA);
                wmma::load_matrix_sync(afL[i], p + (H_ALO - H_AHI), AG_LDA);
            }
#pragma unroll
            for (int j = 0; j < 4; j++) {
                BF bfH, bfL;
                const __half* p = S + H_BHI + (k16 * 16) * LDB_H + wn * 64 + j * 16;
                wmma::load_matrix_sync(bfH, p, LDB_H);
                wmma::load_matrix_sync(bfL, p + (H_BLO - H_BHI), LDB_H);
#pragma unroll
                for (int i = 0; i < 2; i++) {
                    wmma::mma_sync(c[i][j], afH[i], bfH, c[i][j]);
                    wmma::mma_sync(c[i][j], afH[i], bfL, c[i][j]);
                    wmma::mma_sync(c[i][j], afL[i], bfH, c[i][j]);
                }
            }
        }
        __syncthreads();
    }
}

// ---------------------------------------------------------------------------
// agg (layers 2/3): oe = act(16 * adj_split @ supp_scaled). grid (3,Bq,Eq)
// ---------------------------------------------------------------------------
template <int RELU>
__global__ __launch_bounds__(256, 2)
void agg_wmma(const __half* __restrict__ adjhi, const __half* __restrict__ adjlo,
              const __half* __restrict__ shi, const __half* __restrict__ slo,
              float* __restrict__ oe) {
    extern __shared__ __half smh[];
    const unsigned sbase = (unsigned)__cvta_generic_to_shared(smh);

    const int tid = threadIdx.x;
    const int wid = tid >> 5;
    const int wm = wid >> 1, wn = wid & 1;
    const int m0 = blockIdx.x * 128;
    const int b = blockIdx.y, e = blockIdx.z;

    const __half* aH = adjhi + ((size_t)(b * Eq + e) * Nq + m0) * Nq;
    const __half* aL = adjlo + ((size_t)(b * Eq + e) * Nq + m0) * Nq;
    const __half* bH = shi + (size_t)(b * Eq + e) * Nq * NHID;
    const __half* bL = slo + (size_t)(b * Eq + e) * Nq * NHID;

    CF c[2][4];
#pragma unroll
    for (int i = 0; i < 2; i++)
#pragma unroll
        for (int j = 0; j < 4; j++) wmma::fill_fragment(c[i][j], 0.f);

    gemm_mainloop<Nq / 32>(smh, sbase, aH, aL, bH, bL, Nq, tid, wm, wn, c);

#pragma unroll
    for (int i = 0; i < 2; i++)
#pragma unroll
        for (int j = 0; j < 4; j++) {
#pragma unroll
            for (int t = 0; t < c[i][j].num_elements; t++) {
                float v = c[i][j].x[t] * SCALE_UP;
                c[i][j].x[t] = RELU ? fmaxf(v, 0.f) : v;
            }
            float* op = oe + ((size_t)(b * Eq + e) * Nq + m0 + wm * 32 + i * 16) * NHID
                           + wn * 64 + j * 16;
            wmma::store_matrix_sync(op, c[i][j], NHID, wmma::mem_row_major);
        }
}

// ---------------------------------------------------------------------------
// support23: supp_scaled = h_scaled @ W[e]_split, streamed W (occ 2).
// grid (MFLAT/128, Eq)
// ---------------------------------------------------------------------------
__global__ __launch_bounds__(256, 2)
void support23_wmma(const __half* __restrict__ hhi, const __half* __restrict__ hlo,
                    const __half* __restrict__ whi, const __half* __restrict__ wlo,
                    __half* __restrict__ supphi, __half* __restrict__ supplo) {
    extern __shared__ __half smh[];
    const unsigned sbase = (unsigned)__cvta_generic_to_shared(smh);

    const int tid = threadIdx.x;
    const int wid = tid >> 5, lane = tid & 31;
    const int wm = wid >> 1, wn = wid & 1;
    const int e = blockIdx.y;
    const int m0 = blockIdx.x * 128;
    const int b = m0 / Nq, n0 = m0 % Nq;

    const __half* aH = hhi + (size_t)m0 * NHID;
    const __half* aL = hlo + (size_t)m0 * NHID;
    const __half* bH = whi + (size_t)e * NHID * NHID;
    const __half* bL = wlo + (size_t)e * NHID * NHID;

    CF c[2][4];
#pragma unroll
    for (int i = 0; i < 2; i++)
#pragma unroll
        for (int j = 0; j < 4; j++) wmma::fill_fragment(c[i][j], 0.f);

    gemm_mainloop<NHID / 32>(smh, sbase, aH, aL, bH, bL, NHID, tid, wm, wn, c);

    // Epilogue: per-warp fp32 staging in smem, split to fp16 hi/lo, write.
    float* E = (float*)smh + wid * (32 * 68);   // 8 * 8704B = 69.6KB <= 75.7KB
#pragma unroll
    for (int i = 0; i < 2; i++)
#pragma unroll
        for (int j = 0; j < 4; j++)
            wmma::store_matrix_sync(E + (i * 16) * 68 + j * 16, c[i][j], 68,
                                    wmma::mem_row_major);
    __syncwarp();
#pragma unroll
    for (int t = 0; t < 16; t++) {              // full 32 rows per warp
        int p = lane + t * 32;
        int r = p >> 4, c4 = (p & 15) * 4;
        float4 v = *(float4*)&E[r * 68 + c4];
        __half h0, h1, h2, h3, l0, l1, l2, l3;
        split1h(v.x, h0, l0); split1h(v.y, h1, l1);
        split1h(v.z, h2, l2); split1h(v.w, h3, l3);
        size_t o = ((size_t)(b * Eq + e) * Nq + n0 + wm * 32 + r) * NHID + wn * 64 + c4;
        half2 hA = __halves2half2(h0, h1), hB = __halves2half2(h2, h3);
        half2 lA = __halves2half2(l0, l1), lB = __halves2half2(l2, l3);
        uint2 uh, ul;
        uh.x = *(unsigned*)&hA; uh.y = *(unsigned*)&hB;
        ul.x = *(unsigned*)&lA; ul.y = *(unsigned*)&lB;
        *(uint2*)(supphi + o) = uh;
        *(uint2*)(supplo + o) = ul;
    }
}

// ---------------------------------------------------------------------------
// agg16: t1_scaled[b,e] = adj_split @ h0_scaled  (H=16). grid (3,Bq,Eq)
// ---------------------------------------------------------------------------
__device__ __forceinline__ void ag16_load_stage(unsigned sb, const __half* aH,
                                                const __half* aL, const __half* bH,
                                                const __half* bL, int kt, int tid) {
#pragma unroll
    for (int t = 0; t < 2; t++) {
        int idx = tid + t * 256;
        int r = idx >> 2, c8 = idx & 3;
        size_t g = (size_t)r * Nq + kt * 32 + c8 * 8;
        cpa16(sb + (A16_AHI + r * AG_LDA + c8 * 8) * 2, aH + g);
        cpa16(sb + (A16_ALO + r * AG_LDA + c8 * 8) * 2, aL + g);
    }
    if (tid < 64) {
        int r = tid >> 1, c8 = tid & 1;
        size_t g = (size_t)(kt * 32 + r) * NFEAT + c8 * 8;
        cpa16(sb + (A16_BHI + r * LDB16 + c8 * 8) * 2, bH + g);
        cpa16(sb + (A16_BLO + r * LDB16 + c8 * 8) * 2, bL + g);
    }
}

__global__ __launch_bounds__(256)
void agg16_wmma(const __half* __restrict__ adjhi, const __half* __restrict__ adjlo,
                const __half* __restrict__ h0hi, const __half* __restrict__ h0lo,
                __half* __restrict__ t1hi, __half* __restrict__ t1lo) {
    extern __shared__ __half smh[];
    const unsigned sbase = (unsigned)__cvta_generic_to_shared(smh);

    const int tid = threadIdx.x;
    const int wid = tid >> 5, lane = tid & 31;
    const int m0 = blockIdx.x * 128;
    const int b = blockIdx.y, e = blockIdx.z;

    const __half* aH = adjhi + ((size_t)(b * Eq + e) * Nq + m0) * Nq;
    const __half* aL = adjlo + ((size_t)(b * Eq + e) * Nq + m0) * Nq;
    const __half* bH = h0hi + (size_t)b * Nq * NFEAT;
    const __half* bL = h0lo + (size_t)b * Nq * NFEAT;

    CF acc;
    wmma::fill_fragment(acc, 0.f);

    constexpr int KT = Nq / 32;
    ag16_load_stage(sbase, aH, aL, bH, bL, 0, tid);
    CPA_COMMIT();

    for (int kt = 0; kt < KT; kt++) {
        if (kt + 1 < KT) {
            ag16_load_stage(sbase + ((kt + 1) & 1) * STAGE16_H * 2,
                            aH, aL, bH, bL, kt + 1, tid);
            CPA_COMMIT();
            CPA_WAIT(1);
        } else {
            CPA_WAIT(0);
        }
        __syncthreads();

        const __half* S = smh + (kt & 1) * STAGE16_H;
#pragma unroll
        for (int k16 = 0; k16 < 2; k16++) {
            AF afH, afL;
            const __half* pa = S + A16_AHI + (wid * 16) * AG_LDA + k16 * 16;
            wmma::load_matrix_sync(afH, pa, AG_LDA);
            wmma::load_matrix_sync(afL, pa + (A16_ALO - A16_AHI), AG_LDA);
            BF bfH, bfL;
            const __half* pb = S + A16_BHI + (k16 * 16) * LDB16;
            wmma::load_matrix_sync(bfH, pb, LDB16);
            wmma::load_matrix_sync(bfL, pb + (A16_BLO - A16_BHI), LDB16);
            wmma::mma_sync(acc, afH, bfH, acc);
            wmma::mma_sync(acc, afH, bfL, acc);
            wmma::mma_sync(acc, afL, bfH, acc);
        }
        __syncthreads();
    }

    __syncthreads();
    float* E = (float*)smh + wid * (16 * 20);
    wmma::store_matrix_sync(E, acc, 20, wmma::mem_row_major);
    __syncwarp();
    {
        int r = lane >> 1, c0 = (lane & 1) * 8;
        H8 H, L;
#pragma unroll
        for (int j = 0; j < 8; j++)
            split1h(E[r * 20 + c0 + j], H.v[j], L.v[j]);
        size_t o = ((size_t)(b * Eq + e) * Nq + m0 + wid * 16 + r) * NFEAT + c0;
        *(H8*)(t1hi + o) = H;
        *(H8*)(t1lo + o) = L;
    }
}

// ---------------------------------------------------------------------------
// support1: oe = relu(16 * (t1_scaled @ gc1_w[e]_split)). grid (MFLAT/128, Eq)
// ---------------------------------------------------------------------------
__global__ __launch_bounds__(256, 2)
void support1_wmma(const __half* __restrict__ t1hi, const __half* __restrict__ t1lo,
                   const __half* __restrict__ w1hi, const __half* __restrict__ w1lo,
                   float* __restrict__ oe) {
    extern __shared__ __half smh[];
    __half* Ahi = smh + S1_AHI;
    __half* Alo = smh + S1_ALO;
    __half* Bhi = smh + S1_BHI;
    __half* Blo = smh + S1_BLO;

    const int tid = threadIdx.x;
    const int wid = tid >> 5;
    const int wm = wid >> 1, wn = wid & 1;
    const int e = blockIdx.y;
    const int m0 = blockIdx.x * 128;
    const int b = m0 / Nq, n0 = m0 % Nq;

    {
        int r = tid >> 1, c8 = tid & 1;
        size_t g = ((size_t)(b * Eq + e) * Nq + n0 + r) * NFEAT + c8 * 8;
        *(uint4*)&Ahi[r * S1_LDA + c8 * 8] = *(const uint4*)(t1hi + g);
        *(uint4*)&Alo[r * S1_LDA + c8 * 8] = *(const uint4*)(t1lo + g);
    }
    {
        int r = tid >> 4, c8 = tid & 15;
        size_t g = (size_t)(e * NFEAT + r) * NHID + c8 * 8;
        *(uint4*)&Bhi[r * LDB_H + c8 * 8] = *(const uint4*)(w1hi + g);
        *(uint4*)&Blo[r * LDB_H + c8 * 8] = *(const uint4*)(w1lo + g);
    }
    __syncthreads();

    CF c[2][4];
#pragma unroll
    for (int i = 0; i < 2; i++)
#pragma unroll
        for (int j = 0; j < 4; j++) wmma::fill_fragment(c[i][j], 0.f);

    AF afH[2], afL[2];
#pragma unroll
    for (int i = 0; i < 2; i++) {
        const __half* p = Ahi + (wm * 32 + i * 16) * S1_LDA;
        wmma::load_matrix_sync(afH[i], p, S1_LDA);
        wmma::load_matrix_sync(afL[i], p + (S1_ALO - S1_AHI), S1_LDA);
    }
#pragma unroll
    for (int j = 0; j < 4; j++) {
        BF bfH, bfL;
        const __half* p = Bhi + wn * 64 + j * 16;
        wmma::load_matrix_sync(bfH, p, LDB_H);
        wmma::load_matrix_sync(bfL, p + (S1_BLO - S1_BHI), LDB_H);
#pragma unroll
        for (int i = 0; i < 2; i++) {
            wmma::mma_sync(c[i][j], afH[i], bfH, c[i][j]);
            wmma::mma_sync(c[i][j], afH[i], bfL, c[i][j]);
            wmma::mma_sync(c[i][j], afL[i], bfH, c[i][j]);
        }
    }

#pragma unroll
    for (int i = 0; i < 2; i++)
#pragma unroll
        for (int j = 0; j < 4; j++) {
#pragma unroll
            for (int t = 0; t < c[i][j].num_elements; t++)
                c[i][j].x[t] = fmaxf(c[i][j].x[t] * SCALE_UP, 0.f);
            float* op = oe + ((size_t)(b * Eq + e) * Nq + n0 + wm * 32 + i * 16) * NHID
                           + wn * 64 + j * 16;
            wmma::store_matrix_sync(op, c[i][j], NHID, wmma::mem_row_major);
        }
}

// ---------------------------------------------------------------------------
// Head
// ---------------------------------------------------------------------------
__global__ __launch_bounds__(256)
void head_kernel(const float* __restrict__ oe,
                 const float* __restrict__ w1, const float* __restrict__ b1,
                 const float* __restrict__ w2, const float* __restrict__ b2,
                 const float* __restrict__ rescale, float* __restrict__ out) {
    __shared__ float w1T[NHID][68];
    __shared__ float hS[16][NHID];
    __shared__ float z1S[16][68];

    const int tid = threadIdx.x;
    const int row0 = blockIdx.x * 16;
    const int b = row0 / Nq;
    const int n0 = row0 % Nq;

    for (int i = tid; i < ST_HID * NHID; i += 256) {
        int hid = i >> 7, d = i & 127;
        w1T[d][hid] = w1[i];
    }
    const float* base = oe + (size_t)(b * Eq) * Nq * NHID + (size_t)n0 * NHID;
    const size_t eS = (size_t)Nq * NHID;
#pragma unroll
    for (int t = 0; t < 2; t++) {
        int idx = tid + t * 256;
        int r = idx >> 5, c = idx & 31;
        float4 v0 = *(const float4*)(base + (size_t)r * NHID + c * 4);
        float4 v1 = *(const float4*)(base + eS + (size_t)r * NHID + c * 4);
        float4 v2 = *(const float4*)(base + 2 * eS + (size_t)r * NHID + c * 4);
        *(float4*)&hS[r][c * 4] = make_float4(v0.x + v1.x + v2.x, v0.y + v1.y + v2.y,
                                              v0.z + v1.z + v2.z, v0.w + v1.w + v2.w);
    }
    __syncthreads();

    {
        int row = tid >> 4, hg = tid & 15;
        float a0 = b1[hg * 4 + 0], a1 = b1[hg * 4 + 1];
        float a2 = b1[hg * 4 + 2], a3 = b1[hg * 4 + 3];
#pragma unroll 8
        for (int d = 0; d < NHID; d++) {
            float h = hS[row][d];
            float4 w = *(const float4*)&w1T[d][hg * 4];
            a0 = fmaf(h, w.x, a0); a1 = fmaf(h, w.y, a1);
            a2 = fmaf(h, w.z, a2); a3 = fmaf(h, w.w, a3);
        }
        z1S[row][hg * 4 + 0] = tanhf(a0);
        z1S[row][hg * 4 + 1] = tanhf(a1);
        z1S[row][hg * 4 + 2] = tanhf(a2);
        z1S[row][hg * 4 + 3] = tanhf(a3);
    }
    __syncthreads();

    const float ew = expf(rescale[0]);
    for (int p = tid; p < 16 * 32; p += 256) {
        int row = p >> 5, j = p & 31;
        float acc = b2[j];
#pragma unroll 8
        for (int k = 0; k < ST_HID; k++)
            acc += z1S[row][k] * w2[j * ST_HID + k];
        int grow = row0 + row;
        if (j < ST_OUT)
            out[(size_t)grow * ST_OUT + j] = ew * tanhf(acc);
        else
            out[(size_t)MFLAT * ST_OUT + (size_t)grow * ST_OUT + (j - ST_OUT)] = acc;
    }
}

// ---------------------------------------------------------------------------
extern "C" void kernel_launch(void* const* d_in, const int* in_sizes, int n_in,
                              void* d_out, int out_size) {
    const float* x       = (const float*)d_in[0];
    const float* adj     = (const float*)d_in[1];
    const float* emb_w   = (const float*)d_in[2];
    const float* gc1_w   = (const float*)d_in[3];
    const float* gc2_w   = (const float*)d_in[4];
    const float* gc3_w   = (const float*)d_in[5];
    const float* st_w1   = (const float*)d_in[6];
    const float* st_b1   = (const float*)d_in[7];
    const float* st_w2   = (const float*)d_in[8];
    const float* st_b2   = (const float*)d_in[9];
    const float* rescale = (const float*)d_in[10];
    float* out = (float*)d_out;

    __half *adjhi, *adjlo, *supphi, *supplo, *hhi, *hlo, *h0hi, *h0lo, *t1hi, *t1lo;
    __half *w1hi, *w1lo, *w2hi, *w2lo, *w3hi, *w3lo;
    float* oe;
    cudaGetSymbolAddress((void**)&adjhi,  g_adjhi);
    cudaGetSymbolAddress((void**)&adjlo,  g_adjlo);
    cudaGetSymbolAddress((void**)&supphi, g_supphi);
    cudaGetSymbolAddress((void**)&supplo, g_supplo);
    cudaGetSymbolAddress((void**)&oe,     g_oe);
    cudaGetSymbolAddress((void**)&hhi,    g_hhi);
    cudaGetSymbolAddress((void**)&hlo,    g_hlo);
    cudaGetSymbolAddress((void**)&h0hi,   g_h0hi);
    cudaGetSymbolAddress((void**)&h0lo,   g_h0lo);
    cudaGetSymbolAddress((void**)&t1hi,   g_t1hi);
    cudaGetSymbolAddress((void**)&t1lo,   g_t1lo);
    cudaGetSymbolAddress((void**)&w1hi,   g_w1hi);
    cudaGetSymbolAddress((void**)&w1lo,   g_w1lo);
    cudaGetSymbolAddress((void**)&w2hi,   g_w2hi);
    cudaGetSymbolAddress((void**)&w2lo,   g_w2lo);
    cudaGetSymbolAddress((void**)&w3hi,   g_w3hi);
    cudaGetSymbolAddress((void**)&w3lo,   g_w3lo);

    cudaFuncSetAttribute(agg_wmma<1>, cudaFuncAttributeMaxDynamicSharedMemorySize, AG_SMEM);
    cudaFuncSetAttribute(agg_wmma<0>, cudaFuncAttributeMaxDynamicSharedMemorySize, AG_SMEM);
    cudaFuncSetAttribute(agg16_wmma, cudaFuncAttributeMaxDynamicSharedMemorySize, AG16_SMEM);
    cudaFuncSetAttribute(support1_wmma, cudaFuncAttributeMaxDynamicSharedMemorySize, S1_SMEM);
    cudaFuncSetAttribute(support23_wmma, cudaFuncAttributeMaxDynamicSharedMemorySize, AG_SMEM);

    const int adjN8 = (Bq * Eq * Nq * Nq) / 8;
    split_kernel<<<(adjN8 + 255) / 256, 256>>>(adj, adjhi, adjlo, adjN8);
    weight_prep_kernel<<<WBLK + W1BLK + H0BLK, 256>>>(
        gc2_w, gc3_w, emb_w, gc1_w, x,
        w2hi, w2lo, w3hi, w3lo, w1hi, w1lo, h0hi, h0lo);

    dim3 agrid(Nq / 128, Bq, Eq);     // (3, 64, 3)
    dim3 sgrid(MFLAT / 128, Eq);      // (192, 3)
    const int hsumBlocks = (MFLAT * NHID) / (256 * 8);

    // Layer 1 (reordered): t1 = adj@h0, then oe = relu(t1@gc1_w)
    agg16_wmma<<<agrid, 256, AG16_SMEM>>>(adjhi, adjlo, h0hi, h0lo, t1hi, t1lo);
    support1_wmma<<<sgrid, 256, S1_SMEM>>>(t1hi, t1lo, w1hi, w1lo, oe);
    // Layer 2
    hsum_split_kernel<<<hsumBlocks, 256>>>(oe, hhi, hlo);
    support23_wmma<<<sgrid, 256, AG_SMEM>>>(hhi, hlo, w2hi, w2lo, supphi, supplo);
    agg_wmma<1><<<agrid, 256, AG_SMEM>>>(adjhi, adjlo, supphi, supplo, oe);
    // Layer 3
    hsum_split_kernel<<<hsumBlocks, 256>>>(oe, hhi, hlo);
    support23_wmma<<<sgrid, 256, AG_SMEM>>>(hhi, hlo, w3hi, w3lo, supphi, supplo);
    agg_wmma<0><<<agrid, 256, AG_SMEM>>>(adjhi, adjlo, supphi, supplo, oe);

    // Head
    head_kernel<<<MFLAT / 16, 256>>>(oe, st_w1, st_b1, st_w2, st_b2, rescale, out);
}

// round 14
// speedup vs baseline: 3.5927x; 1.1566x over previous
#include <cuda_runtime.h>
#include <cuda_fp16.h>
#include <mma.h>
#include <math.h>

using namespace nvcuda;

#define Bq     64
#define Nq     384
#define NFEAT  16
#define Eq     3
#define NHID   128
#define ST_HID 64
#define ST_OUT 16
#define MFLAT  (Bq * Nq)
#define SCALE_DN 0.0625f
#define SCALE_UP 16.0f

// ---------------- device scratch ----------------
__device__ __half g_adjhi[Bq * Eq * Nq * Nq];
__device__ __half g_adjlo[Bq * Eq * Nq * Nq];
__device__ __half g_supphi[Bq * Eq * Nq * NHID];
__device__ __half g_supplo[Bq * Eq * Nq * NHID];
__device__ __half g_s64hi[Bq * Eq * Nq * ST_HID];
__device__ __half g_s64lo[Bq * Eq * Nq * ST_HID];
__device__ float  g_oe[Bq * Eq * Nq * NHID];       // per-relation fp32 (also oe64)
__device__ __half g_hhi[MFLAT * NHID];
__device__ __half g_hlo[MFLAT * NHID];
__device__ __half g_h0hi[MFLAT * NFEAT];
__device__ __half g_h0lo[MFLAT * NFEAT];
__device__ __half g_t1hi[Bq * Eq * Nq * NFEAT];
__device__ __half g_t1lo[Bq * Eq * Nq * NFEAT];
__device__ __half g_w1hi[Eq * NFEAT * NHID];
__device__ __half g_w1lo[Eq * NFEAT * NHID];
__device__ __half g_w2hi[Eq * NHID * NHID];
__device__ __half g_w2lo[Eq * NHID * NHID];
__device__ __half g_w31hi[Eq * NHID * ST_HID];     // W3 @ w1^T, split
__device__ __half g_w31lo[Eq * NHID * ST_HID];

// ---------------- fp16 Dekker split ----------------
__device__ __forceinline__ void split1h(float v, __half& h, __half& l) {
    h = __float2half_rn(v);
    l = __float2half_rn(v - __half2float(h));
}
struct alignas(16) H8 { __half v[8]; };

// Fused prep: split gc2, split gc1, compute+split W31 = gc3@w1^T, compute+split h0.
#define W2BLK ((Eq * NHID * NHID) / 8 / 256)          // 24
#define W1BLK ((Eq * NFEAT * NHID) / 8 / 256)         // 3
#define W31BLK ((Eq * NHID * ST_HID) / 256)           // 96
#define H0BLK ((MFLAT * NFEAT) / 256)                 // 1536
__global__ void weight_prep_kernel(const float* __restrict__ gc2_w,
                                   const float* __restrict__ gc3_w,
                                   const float* __restrict__ emb_w,
                                   const float* __restrict__ gc1_w,
                                   const float* __restrict__ st_w1,
                                   const float* __restrict__ x,
                                   __half* __restrict__ w2hi, __half* __restrict__ w2lo,
                                   __half* __restrict__ w1hi, __half* __restrict__ w1lo,
                                   __half* __restrict__ w31hi, __half* __restrict__ w31lo,
                                   __half* __restrict__ h0hi, __half* __restrict__ h0lo) {
    int bx = blockIdx.x;
    if (bx < W2BLK) {
        int i = bx * 256 + threadIdx.x;
        float4 a = *(const float4*)(gc2_w + (size_t)i * 8);
        float4 b = *(const float4*)(gc2_w + (size_t)i * 8 + 4);
        float vv[8] = {a.x, a.y, a.z, a.w, b.x, b.y, b.z, b.w};
        H8 H, L;
#pragma unroll
        for (int j = 0; j < 8; j++) split1h(vv[j], H.v[j], L.v[j]);
        *(H8*)(w2hi + (size_t)i * 8) = H;
        *(H8*)(w2lo + (size_t)i * 8) = L;
    } else if (bx < W2BLK + W1BLK) {
        int i = (bx - W2BLK) * 256 + threadIdx.x;
        float4 a = *(const float4*)(gc1_w + (size_t)i * 8);
        float4 b = *(const float4*)(gc1_w + (size_t)i * 8 + 4);
        float vv[8] = {a.x, a.y, a.z, a.w, b.x, b.y, b.z, b.w};
        H8 H, L;
#pragma unroll
        for (int j = 0; j < 8; j++) split1h(vv[j], H.v[j], L.v[j]);
        *(H8*)(w1hi + (size_t)i * 8) = H;
        *(H8*)(w1lo + (size_t)i * 8) = L;
    } else if (bx < W2BLK + W1BLK + W31BLK) {
        int idx = (bx - W2BLK - W1BLK) * 256 + threadIdx.x;  // Eq*128*64
        int k = idx & 63, d = (idx >> 6) & 127, e = idx >> 13;
        float acc = 0.f;
#pragma unroll 8
        for (int h = 0; h < NHID; h++)
            acc += gc3_w[((size_t)(e * NHID + d)) * NHID + h] * st_w1[k * NHID + h];
        split1h(acc, w31hi[(size_t)(e * NHID + d) * ST_HID + k],
                     w31lo[(size_t)(e * NHID + d) * ST_HID + k]);
    } else {
        int idx = (bx - W2BLK - W1BLK - W31BLK) * 256 + threadIdx.x;
        int row = idx >> 4, f = idx & 15;
        float acc = 0.f;
#pragma unroll
        for (int d = 0; d < NFEAT; d++)
            acc += x[(size_t)row * NFEAT + d] * emb_w[f * NFEAT + d];
        split1h(acc * SCALE_DN, h0hi[idx], h0lo[idx]);
    }
}

// hsum_split: h_scaled = split( 2^-4 * sum_e oe )
__global__ void hsum_split_kernel(const float* __restrict__ oe,
                                  __half* __restrict__ hhi, __half* __restrict__ hlo) {
    int idx = blockIdx.x * 256 + threadIdx.x;
    size_t e8 = (size_t)idx * 8;
    int row = (int)(e8 >> 7), c = (int)(e8 & 127);
    int b = row / Nq, n = row % Nq;
    const size_t eS = (size_t)Nq * NHID;
    const float* base = oe + ((size_t)(b * Eq) * Nq + n) * NHID + c;
    H8 H, L;
#pragma unroll
    for (int q = 0; q < 2; q++) {
        float4 v0 = *(const float4*)(base + q * 4);
        float4 v1 = *(const float4*)(base + eS + q * 4);
        float4 v2 = *(const float4*)(base + 2 * eS + q * 4);
        float s[4] = {(v0.x + v1.x + v2.x) * SCALE_DN, (v0.y + v1.y + v2.y) * SCALE_DN,
                      (v0.z + v1.z + v2.z) * SCALE_DN, (v0.w + v1.w + v2.w) * SCALE_DN};
#pragma unroll
        for (int j = 0; j < 4; j++) split1h(s[j], H.v[q * 4 + j], L.v[q * 4 + j]);
    }
    *(H8*)(hhi + e8) = H;
    *(H8*)(hlo + e8) = L;
}

// ---------------- cp.async ----------------
__device__ __forceinline__ void cpa16(unsigned s, const void* g) {
    asm volatile("cp.async.cg.shared.global [%0], [%1], 16;" :: "r"(s), "l"(g));
}
#define CPA_COMMIT() asm volatile("cp.async.commit_group;" ::: "memory")
#define CPA_WAIT(N)  asm volatile("cp.async.wait_group %0;" :: "n"(N) : "memory")

typedef wmma::fragment<wmma::matrix_a, 16, 16, 16, __half, wmma::row_major> AF;
typedef wmma::fragment<wmma::matrix_b, 16, 16, 16, __half, wmma::row_major> BF;
typedef wmma::fragment<wmma::accumulator, 16, 16, 16, float> CF;

// ---------------- smem layouts (halfs) ----------------
#define AG_LDA 40
#define LDB_H  136
#define H_AHI 0
#define H_ALO (128 * AG_LDA)
#define H_BHI (2 * 128 * AG_LDA)
#define H_BLO (H_BHI + 32 * LDB_H)
#define STAGE_H (H_BLO + 32 * LDB_H)       // 18944
#define AG_SMEM (2 * STAGE_H * 2)          // 75776 B
// N=64 variants (supp3 / agg64)
#define LDB64 72
#define B64_BHI (2 * 128 * AG_LDA)
#define B64_BLO (B64_BHI + 32 * LDB64)
#define STAGE64_H (B64_BLO + 32 * LDB64)   // 14848
#define A64_SMEM (2 * STAGE64_H * 2)       // 59392 B
// agg16_split: A 128x32 (ld40) hi/lo + B(h0) 32x16 (ld24) hi/lo, single stage
#define A16S_BHI (2 * 128 * AG_LDA)        // 10240
#define A16S_BLO (A16S_BHI + 32 * 24)      // 11008
#define A16S_SMEM ((A16S_BLO + 32 * 24) * 2)  // 23552 B
// support1
#define S1_LDA 24
#define S1_AHI 0
#define S1_ALO (128 * S1_LDA)
#define S1_BHI (2 * 128 * S1_LDA)
#define S1_BLO (S1_BHI + 16 * LDB_H)
#define S1_SMEM ((S1_BLO + 16 * LDB_H) * 2)

// ---------------------------------------------------------------------------
// Generic loaders / mainloops
// ---------------------------------------------------------------------------
__device__ __forceinline__ void gm_load_stage(unsigned sb, const __half* aH,
                                              const __half* aL, const __half* bH,
                                              const __half* bL, int kt, int tid,
                                              int aStride) {
#pragma unroll
    for (int t = 0; t < 2; t++) {
        int idx = tid + t * 256;
        int r = idx >> 2, c8 = idx & 3;
        size_t g = (size_t)r * aStride + kt * 32 + c8 * 8;
        cpa16(sb + (H_AHI + r * AG_LDA + c8 * 8) * 2, aH + g);
        cpa16(sb + (H_ALO + r * AG_LDA + c8 * 8) * 2, aL + g);
    }
#pragma unroll
    for (int t = 0; t < 2; t++) {
        int idx = tid + t * 256;
        int r = idx >> 4, c8 = idx & 15;
        size_t g = (size_t)(kt * 32 + r) * NHID + c8 * 8;
        cpa16(sb + (H_BHI + r * LDB_H + c8 * 8) * 2, bH + g);
        cpa16(sb + (H_BLO + r * LDB_H + c8 * 8) * 2, bL + g);
    }
}

template <int KT>
__device__ __forceinline__ void gemm_mainloop(
        __half* smh, unsigned sbase, const __half* aH, const __half* aL,
        const __half* bH, const __half* bL, int aStride, int tid,
        int wm, int wn, CF (&c)[2][4]) {
    gm_load_stage(sbase, aH, aL, bH, bL, 0, tid, aStride);
    CPA_COMMIT();
    for (int kt = 0; kt < KT; kt++) {
        if (kt + 1 < KT) {
            gm_load_stage(sbase + ((kt + 1) & 1) * STAGE_H * 2,
                          aH, aL, bH, bL, kt + 1, tid, aStride);
            CPA_COMMIT();
            CPA_WAIT(1);
        } else {
            CPA_WAIT(0);
        }
        __syncthreads();

        const __half* S = smh + (kt & 1) * STAGE_H;
#pragma unroll
        for (int k16 = 0; k16 < 2; k16++) {
            AF afH[2], afL[2];
#pragma unroll
            for (int i = 0; i < 2; i++) {
                const __half* p = S + H_AHI + (wm * 32 + i * 16) * AG_LDA + k16 * 16;
                wmma::load_matrix_sync(afH[i], p, AG_LDA);
                wmma::load_matrix_sync(afL[i], p + (H_ALO - H_AHI), AG_LDA);
            }
#pragma unroll
            for (int j = 0; j < 4; j++) {
                BF bfH, bfL;
                const __half* p = S + H_BHI + (k16 * 16) * LDB_H + wn * 64 + j * 16;
                wmma::load_matrix_sync(bfH, p, LDB_H);
                wmma::load_matrix_sync(bfL, p + (H_BLO - H_BHI), LDB_H);
#pragma unroll
                for (int i = 0; i < 2; i++) {
                    wmma::mma_sync(c[i][j], afH[i], bfH, c[i][j]);
                    wmma::mma_sync(c[i][j], afH[i], bfL, c[i][j]);
                    wmma::mma_sync(c[i][j], afL[i], bfH, c[i][j]);
                }
            }
        }
        __syncthreads();
    }
}

// N=64 variants
__device__ __forceinline__ void gm64_load_stage(unsigned sb, const __half* aH,
                                                const __half* aL, const __half* bH,
                                                const __half* bL, int kt, int tid,
                                                int aStride) {
#pragma unroll
    for (int t = 0; t < 2; t++) {
        int idx = tid + t * 256;
        int r = idx >> 2, c8 = idx & 3;
        size_t g = (size_t)r * aStride + kt * 32 + c8 * 8;
        cpa16(sb + (r * AG_LDA + c8 * 8) * 2, aH + g);
        cpa16(sb + (128 * AG_LDA + r * AG_LDA + c8 * 8) * 2, aL + g);
    }
    {
        int r = tid >> 3, c8 = tid & 7;
        size_t g = (size_t)(kt * 32 + r) * ST_HID + c8 * 8;
        cpa16(sb + (B64_BHI + r * LDB64 + c8 * 8) * 2, bH + g);
        cpa16(sb + (B64_BLO + r * LDB64 + c8 * 8) * 2, bL + g);
    }
}

template <int KT>
__device__ __forceinline__ void gemm_mainloop64(
        __half* smh, unsigned sbase, const __half* aH, const __half* aL,
        const __half* bH, const __half* bL, int aStride, int tid,
        int wm, int wn, CF (&c)[2][2]) {
    gm64_load_stage(sbase, aH, aL, bH, bL, 0, tid, aStride);
    CPA_COMMIT();
    for (int kt = 0; kt < KT; kt++) {
        if (kt + 1 < KT) {
            gm64_load_stage(sbase + ((kt + 1) & 1) * STAGE64_H * 2,
                            aH, aL, bH, bL, kt + 1, tid, aStride);
            CPA_COMMIT();
            CPA_WAIT(1);
        } else {
            CPA_WAIT(0);
        }
        __syncthreads();

        const __half* S = smh + (kt & 1) * STAGE64_H;
#pragma unroll
        for (int k16 = 0; k16 < 2; k16++) {
            AF afH[2], afL[2];
#pragma unroll
            for (int i = 0; i < 2; i++) {
                const __half* p = S + (wm * 32 + i * 16) * AG_LDA + k16 * 16;
                wmma::load_matrix_sync(afH[i], p, AG_LDA);
                wmma::load_matrix_sync(afL[i], p + 128 * AG_LDA, AG_LDA);
            }
#pragma unroll
            for (int j = 0; j < 2; j++) {
                BF bfH, bfL;
                const __half* p = S + B64_BHI + (k16 * 16) * LDB64 + wn * 32 + j * 16;
                wmma::load_matrix_sync(bfH, p, LDB64);
                wmma::load_matrix_sync(bfL, p + (B64_BLO - B64_BHI), LDB64);
#pragma unroll
                for (int i = 0; i < 2; i++) {
                    wmma::mma_sync(c[i][j], afH[i], bfH, c[i][j]);
                    wmma::mma_sync(c[i][j], afH[i], bfL, c[i][j]);
                    wmma::mma_sync(c[i][j], afL[i], bfH, c[i][j]);
                }
            }
        }
        __syncthreads();
    }
}

// ---------------------------------------------------------------------------
// agg (layer 2): oe = relu(16 * adj_split @ supp_scaled). grid (3,Bq,Eq)
// ---------------------------------------------------------------------------
__global__ __launch_bounds__(256, 2)
void agg_wmma(const __half* __restrict__ adjhi, const __half* __restrict__ adjlo,
              const __half* __restrict__ shi, const __half* __restrict__ slo,
              float* __restrict__ oe) {
    extern __shared__ __half smh[];
    const unsigned sbase = (unsigned)__cvta_generic_to_shared(smh);
    const int tid = threadIdx.x;
    const int wid = tid >> 5;
    const int wm = wid >> 1, wn = wid & 1;
    const int m0 = blockIdx.x * 128;
    const int b = blockIdx.y, e = blockIdx.z;

    const __half* aH = adjhi + ((size_t)(b * Eq + e) * Nq + m0) * Nq;
    const __half* aL = adjlo + ((size_t)(b * Eq + e) * Nq + m0) * Nq;
    const __half* bH = shi + (size_t)(b * Eq + e) * Nq * NHID;
    const __half* bL = slo + (size_t)(b * Eq + e) * Nq * NHID;

    CF c[2][4];
#pragma unroll
    for (int i = 0; i < 2; i++)
#pragma unroll
        for (int j = 0; j < 4; j++) wmma::fill_fragment(c[i][j], 0.f);

    gemm_mainloop<Nq / 32>(smh, sbase, aH, aL, bH, bL, Nq, tid, wm, wn, c);

#pragma unroll
    for (int i = 0; i < 2; i++)
#pragma unroll
        for (int j = 0; j < 4; j++) {
#pragma unroll
            for (int t = 0; t < c[i][j].num_elements; t++)
                c[i][j].x[t] = fmaxf(c[i][j].x[t] * SCALE_UP, 0.f);
            float* op = oe + ((size_t)(b * Eq + e) * Nq + m0 + wm * 32 + i * 16) * NHID
                           + wn * 64 + j * 16;
            wmma::store_matrix_sync(op, c[i][j], NHID, wmma::mem_row_major);
        }
}

// ---------------------------------------------------------------------------
// agg64 (layer 3): oe64 = 16 * adj_split @ s64_scaled (no relu). grid (3,Bq,Eq)
// ---------------------------------------------------------------------------
__global__ __launch_bounds__(256, 2)
void agg64_wmma(const __half* __restrict__ adjhi, const __half* __restrict__ adjlo,
                const __half* __restrict__ shi, const __half* __restrict__ slo,
                float* __restrict__ oe64) {
    extern __shared__ __half smh[];
    const unsigned sbase = (unsigned)__cvta_generic_to_shared(smh);
    const int tid = threadIdx.x;
    const int wid = tid >> 5;
    const int wm = wid >> 1, wn = wid & 1;
    const int m0 = blockIdx.x * 128;
    const int b = blockIdx.y, e = blockIdx.z;

    const __half* aH = adjhi + ((size_t)(b * Eq + e) * Nq + m0) * Nq;
    const __half* aL = adjlo + ((size_t)(b * Eq + e) * Nq + m0) * Nq;
    const __half* bH = shi + (size_t)(b * Eq + e) * Nq * ST_HID;
    const __half* bL = slo + (size_t)(b * Eq + e) * Nq * ST_HID;

    CF c[2][2];
#pragma unroll
    for (int i = 0; i < 2; i++)
#pragma unroll
        for (int j = 0; j < 2; j++) wmma::fill_fragment(c[i][j], 0.f);

    gemm_mainloop64<Nq / 32>(smh, sbase, aH, aL, bH, bL, Nq, tid, wm, wn, c);

#pragma unroll
    for (int i = 0; i < 2; i++)
#pragma unroll
        for (int j = 0; j < 2; j++) {
#pragma unroll
            for (int t = 0; t < c[i][j].num_elements; t++)
                c[i][j].x[t] *= SCALE_UP;
            float* op = oe64 + ((size_t)(b * Eq + e) * Nq + m0 + wm * 32 + i * 16) * ST_HID
                             + wn * 32 + j * 16;
            wmma::store_matrix_sync(op, c[i][j], ST_HID, wmma::mem_row_major);
        }
}

// ---------------------------------------------------------------------------
// support23 (layer 2): supp_scaled = h_scaled @ W2[e]_split. grid (192, Eq)
// ---------------------------------------------------------------------------
__global__ __launch_bounds__(256, 2)
void support23_wmma(const __half* __restrict__ hhi, const __half* __restrict__ hlo,
                    const __half* __restrict__ whi, const __half* __restrict__ wlo,
                    __half* __restrict__ supphi, __half* __restrict__ supplo) {
    extern __shared__ __half smh[];
    const unsigned sbase = (unsigned)__cvta_generic_to_shared(smh);
    const int tid = threadIdx.x;
    const int wid = tid >> 5, lane = tid & 31;
    const int wm = wid >> 1, wn = wid & 1;
    const int e = blockIdx.y;
    const int m0 = blockIdx.x * 128;
    const int b = m0 / Nq, n0 = m0 % Nq;

    const __half* aH = hhi + (size_t)m0 * NHID;
    const __half* aL = hlo + (size_t)m0 * NHID;
    const __half* bH = whi + (size_t)e * NHID * NHID;
    const __half* bL = wlo + (size_t)e * NHID * NHID;

    CF c[2][4];
#pragma unroll
    for (int i = 0; i < 2; i++)
#pragma unroll
        for (int j = 0; j < 4; j++) wmma::fill_fragment(c[i][j], 0.f);

    gemm_mainloop<NHID / 32>(smh, sbase, aH, aL, bH, bL, NHID, tid, wm, wn, c);

    float* E = (float*)smh + wid * (32 * 68);
#pragma unroll
    for (int i = 0; i < 2; i++)
#pragma unroll
        for (int j = 0; j < 4; j++)
            wmma::store_matrix_sync(E + (i * 16) * 68 + j * 16, c[i][j], 68,
                                    wmma::mem_row_major);
    __syncwarp();
#pragma unroll
    for (int t = 0; t < 16; t++) {
        int p = lane + t * 32;
        int r = p >> 4, c4 = (p & 15) * 4;
        float4 v = *(float4*)&E[r * 68 + c4];
        __half h0, h1, h2, h3, l0, l1, l2, l3;
        split1h(v.x, h0, l0); split1h(v.y, h1, l1);
        split1h(v.z, h2, l2); split1h(v.w, h3, l3);
        size_t o = ((size_t)(b * Eq + e) * Nq + n0 + wm * 32 + r) * NHID + wn * 64 + c4;
        half2 hA = __halves2half2(h0, h1), hB = __halves2half2(h2, h3);
        half2 lA = __halves2half2(l0, l1), lB = __halves2half2(l2, l3);
        uint2 uh, ul;
        uh.x = *(unsigned*)&hA; uh.y = *(unsigned*)&hB;
        ul.x = *(unsigned*)&lA; ul.y = *(unsigned*)&lB;
        *(uint2*)(supphi + o) = uh;
        *(uint2*)(supplo + o) = ul;
    }
}

// ---------------------------------------------------------------------------
// supp3 (layer 3, N=64): s64_scaled = h_scaled @ W31[e]_split. grid (192, Eq)
// ---------------------------------------------------------------------------
__global__ __launch_bounds__(256, 2)
void supp3_wmma(const __half* __restrict__ hhi, const __half* __restrict__ hlo,
                const __half* __restrict__ whi, const __half* __restrict__ wlo,
                __half* __restrict__ s64hi, __half* __restrict__ s64lo) {
    extern __shared__ __half smh[];
    const unsigned sbase = (unsigned)__cvta_generic_to_shared(smh);
    const int tid = threadIdx.x;
    const int wid = tid >> 5, lane = tid & 31;
    const int wm = wid >> 1, wn = wid & 1;
    const int e = blockIdx.y;
    const int m0 = blockIdx.x * 128;
    const int b = m0 / Nq, n0 = m0 % Nq;

    const __half* aH = hhi + (size_t)m0 * NHID;
    const __half* aL = hlo + (size_t)m0 * NHID;
    const __half* bH = whi + (size_t)e * NHID * ST_HID;
    const __half* bL = wlo + (size_t)e * NHID * ST_HID;

    CF c[2][2];
#pragma unroll
    for (int i = 0; i < 2; i++)
#pragma unroll
        for (int j = 0; j < 2; j++) wmma::fill_fragment(c[i][j], 0.f);

    gemm_mainloop64<NHID / 32>(smh, sbase, aH, aL, bH, bL, NHID, tid, wm, wn, c);

    float* E = (float*)smh + wid * (32 * 36);
#pragma unroll
    for (int i = 0; i < 2; i++)
#pragma unroll
        for (int j = 0; j < 2; j++)
            wmma::store_matrix_sync(E + (i * 16) * 36 + j * 16, c[i][j], 36,
                                    wmma::mem_row_major);
    __syncwarp();
#pragma unroll
    for (int t = 0; t < 8; t++) {               // 32 rows x 8 quads
        int p = lane + t * 32;
        int r = p >> 3, c4 = (p & 7) * 4;
        float4 v = *(float4*)&E[r * 36 + c4];
        __half h0, h1, h2, h3, l0, l1, l2, l3;
        split1h(v.x, h0, l0); split1h(v.y, h1, l1);
        split1h(v.z, h2, l2); split1h(v.w, h3, l3);
        size_t o = ((size_t)(b * Eq + e) * Nq + n0 + wm * 32 + r) * ST_HID + wn * 32 + c4;
        half2 hA = __halves2half2(h0, h1), hB = __halves2half2(h2, h3);
        half2 lA = __halves2half2(l0, l1), lB = __halves2half2(l2, l3);
        uint2 uh, ul;
        uh.x = *(unsigned*)&hA; uh.y = *(unsigned*)&hB;
        ul.x = *(unsigned*)&lA; ul.y = *(unsigned*)&lB;
        *(uint2*)(s64hi + o) = uh;
        *(uint2*)(s64lo + o) = ul;
    }
}

// ---------------------------------------------------------------------------
// agg16_split: fused adj split + t1 = adj @ h0_scaled. grid (3,Bq,Eq)
// Reads fp32 adj, writes fp16 hi/lo (for layers 2/3) and t1 split.
// ---------------------------------------------------------------------------
__global__ __launch_bounds__(256, 2)
void agg16_split(const float* __restrict__ adjF,
                 __half* __restrict__ adjhi, __half* __restrict__ adjlo,
                 const __half* __restrict__ h0hi, const __half* __restrict__ h0lo,
                 __half* __restrict__ t1hi, __half* __restrict__ t1lo) {
    extern __shared__ __half smh[];
    __half* AHI = smh;
    __half* ALO = smh + 128 * AG_LDA;
    __half* BHI = smh + A16S_BHI;
    __half* BLO = smh + A16S_BLO;

    const int tid = threadIdx.x;
    const int wid = tid >> 5, lane = tid & 31;
    const int m0 = blockIdx.x * 128;
    const int b = blockIdx.y, e = blockIdx.z;

    const size_t gbase = ((size_t)(b * Eq + e) * Nq + m0) * Nq;
    const float* aF = adjF + gbase;
    const __half* bH = h0hi + (size_t)b * Nq * NFEAT;
    const __half* bL = h0lo + (size_t)b * Nq * NFEAT;

    CF acc;
    wmma::fill_fragment(acc, 0.f);

    for (int kt = 0; kt < Nq / 32; kt++) {
        // A: load fp32, split, STS + STG
#pragma unroll
        for (int t = 0; t < 2; t++) {
            int idx = tid + t * 256;          // 512 chunks of 8 floats
            int r = idx >> 2, c8 = idx & 3;
            const float* src = aF + (size_t)r * Nq + kt * 32 + c8 * 8;
            float4 v0 = *(const float4*)src;
            float4 v1 = *(const float4*)(src + 4);
            float vv[8] = {v0.x, v0.y, v0.z, v0.w, v1.x, v1.y, v1.z, v1.w};
            H8 H, L;
#pragma unroll
            for (int j = 0; j < 8; j++) split1h(vv[j], H.v[j], L.v[j]);
            *(H8*)&AHI[r * AG_LDA + c8 * 8] = H;
            *(H8*)&ALO[r * AG_LDA + c8 * 8] = L;
            size_t go = gbase + (size_t)r * Nq + kt * 32 + c8 * 8;
            *(H8*)(adjhi + go) = H;
            *(H8*)(adjlo + go) = L;
        }
        // B: h0 tile 32x16 hi/lo
        if (tid < 64) {
            int r = tid >> 1, c8 = tid & 1;
            size_t g = (size_t)(kt * 32 + r) * NFEAT + c8 * 8;
            *(uint4*)&BHI[r * 24 + c8 * 8] = *(const uint4*)(h0hi + (bH - h0hi) + g);
            *(uint4*)&BLO[r * 24 + c8 * 8] = *(const uint4*)(h0lo + (bL - h0lo) + g);
        }
        __syncthreads();

#pragma unroll
        for (int k16 = 0; k16 < 2; k16++) {
            AF afH, afL;
            const __half* pa = AHI + (wid * 16) * AG_LDA + k16 * 16;
            wmma::load_matrix_sync(afH, pa, AG_LDA);
            wmma::load_matrix_sync(afL, pa + 128 * AG_LDA, AG_LDA);
            BF bfH, bfL;
            const __half* pb = BHI + (k16 * 16) * 24;
            wmma::load_matrix_sync(bfH, pb, 24);
            wmma::load_matrix_sync(bfL, pb + (A16S_BLO - A16S_BHI), 24);
            wmma::mma_sync(acc, afH, bfH, acc);
            wmma::mma_sync(acc, afH, bfL, acc);
            wmma::mma_sync(acc, afL, bfH, acc);
        }
        __syncthreads();
    }

    // Epilogue: split t1 (already scaled via h0)
    float* E = (float*)smh + wid * (16 * 20);
    wmma::store_matrix_sync(E, acc, 20, wmma::mem_row_major);
    __syncwarp();
    {
        int r = lane >> 1, c0 = (lane & 1) * 8;
        H8 H, L;
#pragma unroll
        for (int j = 0; j < 8; j++)
            split1h(E[r * 20 + c0 + j], H.v[j], L.v[j]);
        size_t o = ((size_t)(b * Eq + e) * Nq + m0 + wid * 16 + r) * NFEAT + c0;
        *(H8*)(t1hi + o) = H;
        *(H8*)(t1lo + o) = L;
    }
}

// ---------------------------------------------------------------------------
// support1: oe = relu(16 * (t1_scaled @ gc1_w[e]_split)). grid (192, Eq)
// ---------------------------------------------------------------------------
__global__ __launch_bounds__(256, 2)
void support1_wmma(const __half* __restrict__ t1hi, const __half* __restrict__ t1lo,
                   const __half* __restrict__ w1hi, const __half* __restrict__ w1lo,
                   float* __restrict__ oe) {
    extern __shared__ __half smh[];
    __half* Ahi = smh + S1_AHI;
    __half* Alo = smh + S1_ALO;
    __half* Bhi = smh + S1_BHI;
    __half* Blo = smh + S1_BLO;

    const int tid = threadIdx.x;
    const int wid = tid >> 5;
    const int wm = wid >> 1, wn = wid & 1;
    const int e = blockIdx.y;
    const int m0 = blockIdx.x * 128;
    const int b = m0 / Nq, n0 = m0 % Nq;

    {
        int r = tid >> 1, c8 = tid & 1;
        size_t g = ((size_t)(b * Eq + e) * Nq + n0 + r) * NFEAT + c8 * 8;
        *(uint4*)&Ahi[r * S1_LDA + c8 * 8] = *(const uint4*)(t1hi + g);
        *(uint4*)&Alo[r * S1_LDA + c8 * 8] = *(const uint4*)(t1lo + g);
    }
    {
        int r = tid >> 4, c8 = tid & 15;
        size_t g = (size_t)(e * NFEAT + r) * NHID + c8 * 8;
        *(uint4*)&Bhi[r * LDB_H + c8 * 8] = *(const uint4*)(w1hi + g);
        *(uint4*)&Blo[r * LDB_H + c8 * 8] = *(const uint4*)(w1lo + g);
    }
    __syncthreads();

    CF c[2][4];
#pragma unroll
    for (int i = 0; i < 2; i++)
#pragma unroll
        for (int j = 0; j < 4; j++) wmma::fill_fragment(c[i][j], 0.f);

    AF afH[2], afL[2];
#pragma unroll
    for (int i = 0; i < 2; i++) {
        const __half* p = Ahi + (wm * 32 + i * 16) * S1_LDA;
        wmma::load_matrix_sync(afH[i], p, S1_LDA);
        wmma::load_matrix_sync(afL[i], p + (S1_ALO - S1_AHI), S1_LDA);
    }
#pragma unroll
    for (int j = 0; j < 4; j++) {
        BF bfH, bfL;
        const __half* p = Bhi + wn * 64 + j * 16;
        wmma::load_matrix_sync(bfH, p, LDB_H);
        wmma::load_matrix_sync(bfL, p + (S1_BLO - S1_BHI), LDB_H);
#pragma unroll
        for (int i = 0; i < 2; i++) {
            wmma::mma_sync(c[i][j], afH[i], bfH, c[i][j]);
            wmma::mma_sync(c[i][j], afH[i], bfL, c[i][j]);
            wmma::mma_sync(c[i][j], afL[i], bfH, c[i][j]);
        }
    }

#pragma unroll
    for (int i = 0; i < 2; i++)
#pragma unroll
        for (int j = 0; j < 4; j++) {
#pragma unroll
            for (int t = 0; t < c[i][j].num_elements; t++)
                c[i][j].x[t] = fmaxf(c[i][j].x[t] * SCALE_UP, 0.f);
            float* op = oe + ((size_t)(b * Eq + e) * Nq + n0 + wm * 32 + i * 16) * NHID
                           + wn * 64 + j * 16;
            wmma::store_matrix_sync(op, c[i][j], NHID, wmma::mem_row_major);
        }
}

// ---------------------------------------------------------------------------
// head64: z1 = tanh(sum_e oe64 + b1); z = z1@w2^T + b2; outputs. grid MFLAT/16
// ---------------------------------------------------------------------------
__global__ __launch_bounds__(256)
void head64_kernel(const float* __restrict__ oe64,
                   const float* __restrict__ b1,
                   const float* __restrict__ w2, const float* __restrict__ b2,
                   const float* __restrict__ rescale, float* __restrict__ out) {
    __shared__ float z1S[16][ST_HID + 4];

    const int tid = threadIdx.x;
    const int row0 = blockIdx.x * 16;
    const int b = row0 / Nq;
    const int n0 = row0 % Nq;

    const float* base = oe64 + ((size_t)(b * Eq) * Nq + n0) * ST_HID;
    const size_t eS = (size_t)Nq * ST_HID;
    {
        int r = tid >> 4, c4 = (tid & 15) * 4;    // 16 rows x 16 quads
        float4 v0 = *(const float4*)(base + (size_t)r * ST_HID + c4);
        float4 v1 = *(const float4*)(base + eS + (size_t)r * ST_HID + c4);
        float4 v2 = *(const float4*)(base + 2 * eS + (size_t)r * ST_HID + c4);
        z1S[r][c4 + 0] = tanhf(v0.x + v1.x + v2.x + b1[c4 + 0]);
        z1S[r][c4 + 1] = tanhf(v0.y + v1.y + v2.y + b1[c4 + 1]);
        z1S[r][c4 + 2] = tanhf(v0.z + v1.z + v2.z + b1[c4 + 2]);
        z1S[r][c4 + 3] = tanhf(v0.w + v1.w + v2.w + b1[c4 + 3]);
    }
    __syncthreads();

    const float ew = expf(rescale[0]);
    for (int p = tid; p < 16 * 32; p += 256) {
        int row = p >> 5, j = p & 31;
        float acc = b2[j];
#pragma unroll 8
        for (int k = 0; k < ST_HID; k++)
            acc += z1S[row][k] * w2[j * ST_HID + k];
        int grow = row0 + row;
        if (j < ST_OUT)
            out[(size_t)grow * ST_OUT + j] = ew * tanhf(acc);
        else
            out[(size_t)MFLAT * ST_OUT + (size_t)grow * ST_OUT + (j - ST_OUT)] = acc;
    }
}

// ---------------------------------------------------------------------------
extern "C" void kernel_launch(void* const* d_in, const int* in_sizes, int n_in,
                              void* d_out, int out_size) {
    const float* x       = (const float*)d_in[0];
    const float* adj     = (const float*)d_in[1];
    const float* emb_w   = (const float*)d_in[2];
    const float* gc1_w   = (const float*)d_in[3];
    const float* gc2_w   = (const float*)d_in[4];
    const float* gc3_w   = (const float*)d_in[5];
    const float* st_w1   = (const float*)d_in[6];
    const float* st_b1   = (const float*)d_in[7];
    const float* st_w2   = (const float*)d_in[8];
    const float* st_b2   = (const float*)d_in[9];
    const float* rescale = (const float*)d_in[10];
    float* out = (float*)d_out;

    __half *adjhi, *adjlo, *supphi, *supplo, *s64hi, *s64lo;
    __half *hhi, *hlo, *h0hi, *h0lo, *t1hi, *t1lo;
    __half *w1hi, *w1lo, *w2hi, *w2lo, *w31hi, *w31lo;
    float* oe;
    cudaGetSymbolAddress((void**)&adjhi,  g_adjhi);
    cudaGetSymbolAddress((void**)&adjlo,  g_adjlo);
    cudaGetSymbolAddress((void**)&supphi, g_supphi);
    cudaGetSymbolAddress((void**)&supplo, g_supplo);
    cudaGetSymbolAddress((void**)&s64hi,  g_s64hi);
    cudaGetSymbolAddress((void**)&s64lo,  g_s64lo);
    cudaGetSymbolAddress((void**)&oe,     g_oe);
    cudaGetSymbolAddress((void**)&hhi,    g_hhi);
    cudaGetSymbolAddress((void**)&hlo,    g_hlo);
    cudaGetSymbolAddress((void**)&h0hi,   g_h0hi);
    cudaGetSymbolAddress((void**)&h0lo,   g_h0lo);
    cudaGetSymbolAddress((void**)&t1hi,   g_t1hi);
    cudaGetSymbolAddress((void**)&t1lo,   g_t1lo);
    cudaGetSymbolAddress((void**)&w1hi,   g_w1hi);
    cudaGetSymbolAddress((void**)&w1lo,   g_w1lo);
    cudaGetSymbolAddress((void**)&w2hi,   g_w2hi);
    cudaGetSymbolAddress((void**)&w2lo,   g_w2lo);
    cudaGetSymbolAddress((void**)&w31hi,  g_w31hi);
    cudaGetSymbolAddress((void**)&w31lo,  g_w31lo);

    cudaFuncSetAttribute(agg_wmma,       cudaFuncAttributeMaxDynamicSharedMemorySize, AG_SMEM);
    cudaFuncSetAttribute(agg64_wmma,     cudaFuncAttributeMaxDynamicSharedMemorySize, A64_SMEM);
    cudaFuncSetAttribute(agg16_split,    cudaFuncAttributeMaxDynamicSharedMemorySize, A16S_SMEM);
    cudaFuncSetAttribute(support1_wmma,  cudaFuncAttributeMaxDynamicSharedMemorySize, S1_SMEM);
    cudaFuncSetAttribute(support23_wmma, cudaFuncAttributeMaxDynamicSharedMemorySize, AG_SMEM);
    cudaFuncSetAttribute(supp3_wmma,     cudaFuncAttributeMaxDynamicSharedMemorySize, A64_SMEM);

    weight_prep_kernel<<<W2BLK + W1BLK + W31BLK + H0BLK, 256>>>(
        gc2_w, gc3_w, emb_w, gc1_w, st_w1, x,
        w2hi, w2lo, w1hi, w1lo, w31hi, w31lo, h0hi, h0lo);

    dim3 agrid(Nq / 128, Bq, Eq);     // (3, 64, 3)
    dim3 sgrid(MFLAT / 128, Eq);      // (192, 3)
    const int hsumBlocks = (MFLAT * NHID) / (256 * 8);

    // Layer 1: fused adj split + t1 = adj@h0; then oe = relu(t1@gc1_w)
    agg16_split<<<agrid, 256, A16S_SMEM>>>(adj, adjhi, adjlo, h0hi, h0lo, t1hi, t1lo);
    support1_wmma<<<sgrid, 256, S1_SMEM>>>(t1hi, t1lo, w1hi, w1lo, oe);
    // Layer 2
    hsum_split_kernel<<<hsumBlocks, 256>>>(oe, hhi, hlo);
    support23_wmma<<<sgrid, 256, AG_SMEM>>>(hhi, hlo, w2hi, w2lo, supphi, supplo);
    agg_wmma<<<agrid, 256, AG_SMEM>>>(adjhi, adjlo, supphi, supplo, oe);
    // Layer 3 (w1 folded: N=64)
    hsum_split_kernel<<<hsumBlocks, 256>>>(oe, hhi, hlo);
    supp3_wmma<<<sgrid, 256, A64_SMEM>>>(hhi, hlo, w31hi, w31lo, s64hi, s64lo);
    agg64_wmma<<<agrid, 256, A64_SMEM>>>(adjhi, adjlo, s64hi, s64lo, oe);
    // Head (stage-1 GEMM folded away)
    head64_kernel<<<MFLAT / 16, 256>>>(oe, st_b1, st_w2, st_b2, rescale, out);
}

// round 15
// speedup vs baseline: 3.6335x; 1.0114x over previous
#include <cuda_runtime.h>
#include <cuda_fp16.h>
#include <mma.h>
#include <math.h>

using namespace nvcuda;

#define Bq     64
#define Nq     384
#define NFEAT  16
#define Eq     3
#define NHID   128
#define ST_HID 64
#define ST_OUT 16
#define MFLAT  (Bq * Nq)
#define SCALE_DN 0.0625f
#define SCALE_UP 16.0f

// ---------------- device scratch ----------------
__device__ __half g_adjhi[Bq * Eq * Nq * Nq];
__device__ __half g_adjlo[Bq * Eq * Nq * Nq];
__device__ __half g_supphi[Bq * Eq * Nq * NHID];
__device__ __half g_supplo[Bq * Eq * Nq * NHID];
__device__ __half g_s64hi[Bq * Eq * Nq * ST_HID];
__device__ __half g_s64lo[Bq * Eq * Nq * ST_HID];
__device__ float  g_oe[Bq * Eq * Nq * NHID];
__device__ __half g_hhi[MFLAT * NHID];
__device__ __half g_hlo[MFLAT * NHID];
__device__ __half g_h0hi[MFLAT * NFEAT];
__device__ __half g_h0lo[MFLAT * NFEAT];
__device__ __half g_t1hi[Bq * Eq * Nq * NFEAT];
__device__ __half g_t1lo[Bq * Eq * Nq * NFEAT];
__device__ __half g_w1hi[Eq * NFEAT * NHID];
__device__ __half g_w1lo[Eq * NFEAT * NHID];
__device__ __half g_w2hi[Eq * NHID * NHID];
__device__ __half g_w2lo[Eq * NHID * NHID];
__device__ __half g_w31hi[Eq * NHID * ST_HID];
__device__ __half g_w31lo[Eq * NHID * ST_HID];

// ---------------- fp16 Dekker split ----------------
__device__ __forceinline__ void split1h(float v, __half& h, __half& l) {
    h = __float2half_rn(v);
    l = __float2half_rn(v - __half2float(h));
}
struct alignas(16) H8 { __half v[8]; };

// Fused prep
#define W2BLK ((Eq * NHID * NHID) / 8 / 256)
#define W1BLK ((Eq * NFEAT * NHID) / 8 / 256)
#define W31BLK ((Eq * NHID * ST_HID) / 256)
#define H0BLK ((MFLAT * NFEAT) / 256)
__global__ void weight_prep_kernel(const float* __restrict__ gc2_w,
                                   const float* __restrict__ gc3_w,
                                   const float* __restrict__ emb_w,
                                   const float* __restrict__ gc1_w,
                                   const float* __restrict__ st_w1,
                                   const float* __restrict__ x,
                                   __half* __restrict__ w2hi, __half* __restrict__ w2lo,
                                   __half* __restrict__ w1hi, __half* __restrict__ w1lo,
                                   __half* __restrict__ w31hi, __half* __restrict__ w31lo,
                                   __half* __restrict__ h0hi, __half* __restrict__ h0lo) {
    int bx = blockIdx.x;
    if (bx < W2BLK) {
        int i = bx * 256 + threadIdx.x;
        float4 a = *(const float4*)(gc2_w + (size_t)i * 8);
        float4 b = *(const float4*)(gc2_w + (size_t)i * 8 + 4);
        float vv[8] = {a.x, a.y, a.z, a.w, b.x, b.y, b.z, b.w};
        H8 H, L;
#pragma unroll
        for (int j = 0; j < 8; j++) split1h(vv[j], H.v[j], L.v[j]);
        *(H8*)(w2hi + (size_t)i * 8) = H;
        *(H8*)(w2lo + (size_t)i * 8) = L;
    } else if (bx < W2BLK + W1BLK) {
        int i = (bx - W2BLK) * 256 + threadIdx.x;
        float4 a = *(const float4*)(gc1_w + (size_t)i * 8);
        float4 b = *(const float4*)(gc1_w + (size_t)i * 8 + 4);
        float vv[8] = {a.x, a.y, a.z, a.w, b.x, b.y, b.z, b.w};
        H8 H, L;
#pragma unroll
        for (int j = 0; j < 8; j++) split1h(vv[j], H.v[j], L.v[j]);
        *(H8*)(w1hi + (size_t)i * 8) = H;
        *(H8*)(w1lo + (size_t)i * 8) = L;
    } else if (bx < W2BLK + W1BLK + W31BLK) {
        int idx = (bx - W2BLK - W1BLK) * 256 + threadIdx.x;
        int k = idx & 63, d = (idx >> 6) & 127, e = idx >> 13;
        float acc = 0.f;
#pragma unroll 8
        for (int h = 0; h < NHID; h++)
            acc += gc3_w[((size_t)(e * NHID + d)) * NHID + h] * st_w1[k * NHID + h];
        split1h(acc, w31hi[(size_t)(e * NHID + d) * ST_HID + k],
                     w31lo[(size_t)(e * NHID + d) * ST_HID + k]);
    } else {
        int idx = (bx - W2BLK - W1BLK - W31BLK) * 256 + threadIdx.x;
        int row = idx >> 4, f = idx & 15;
        float acc = 0.f;
#pragma unroll
        for (int d = 0; d < NFEAT; d++)
            acc += x[(size_t)row * NFEAT + d] * emb_w[f * NFEAT + d];
        split1h(acc * SCALE_DN, h0hi[idx], h0lo[idx]);
    }
}

// hsum_split
__global__ void hsum_split_kernel(const float* __restrict__ oe,
                                  __half* __restrict__ hhi, __half* __restrict__ hlo) {
    int idx = blockIdx.x * 256 + threadIdx.x;
    size_t e8 = (size_t)idx * 8;
    int row = (int)(e8 >> 7), c = (int)(e8 & 127);
    int b = row / Nq, n = row % Nq;
    const size_t eS = (size_t)Nq * NHID;
    const float* base = oe + ((size_t)(b * Eq) * Nq + n) * NHID + c;
    H8 H, L;
#pragma unroll
    for (int q = 0; q < 2; q++) {
        float4 v0 = *(const float4*)(base + q * 4);
        float4 v1 = *(const float4*)(base + eS + q * 4);
        float4 v2 = *(const float4*)(base + 2 * eS + q * 4);
        float s[4] = {(v0.x + v1.x + v2.x) * SCALE_DN, (v0.y + v1.y + v2.y) * SCALE_DN,
                      (v0.z + v1.z + v2.z) * SCALE_DN, (v0.w + v1.w + v2.w) * SCALE_DN};
#pragma unroll
        for (int j = 0; j < 4; j++) split1h(s[j], H.v[q * 4 + j], L.v[q * 4 + j]);
    }
    *(H8*)(hhi + e8) = H;
    *(H8*)(hlo + e8) = L;
}

// ---------------- cp.async ----------------
__device__ __forceinline__ void cpa16(unsigned s, const void* g) {
    asm volatile("cp.async.cg.shared.global [%0], [%1], 16;" :: "r"(s), "l"(g));
}
#define CPA_COMMIT() asm volatile("cp.async.commit_group;" ::: "memory")
#define CPA_WAIT(N)  asm volatile("cp.async.wait_group %0;" :: "n"(N) : "memory")

typedef wmma::fragment<wmma::matrix_a, 16, 16, 16, __half, wmma::row_major> AF;
typedef wmma::fragment<wmma::matrix_b, 16, 16, 16, __half, wmma::row_major> BF;
typedef wmma::fragment<wmma::accumulator, 16, 16, 16, float> CF;

// ---------------- smem layouts (halfs) ----------------
#define AG_LDA 40
#define LDB_H  136
#define H_AHI 0
#define H_ALO (128 * AG_LDA)
#define H_BHI (2 * 128 * AG_LDA)
#define H_BLO (H_BHI + 32 * LDB_H)
#define STAGE_H (H_BLO + 32 * LDB_H)       // 18944
#define AG_SMEM (2 * STAGE_H * 2)          // 75776 B
#define LDB64 72
#define B64_BHI (2 * 128 * AG_LDA)
#define B64_BLO (B64_BHI + 32 * LDB64)
#define STAGE64_H (B64_BLO + 32 * LDB64)
#define A64_SMEM (2 * STAGE64_H * 2)       // 59392 B
// agg16_split: AHI/ALO (128x32 ld40) + resident h0 (384x16 hi/lo, ld16)
#define A16_BHI (2 * 128 * AG_LDA)         // 10240
#define A16_BLO (A16_BHI + Nq * NFEAT)     // 16384
#define A16_SMEM ((A16_BLO + Nq * NFEAT) * 2)  // 45056 B
// support1
#define S1_LDA 24
#define S1_AHI 0
#define S1_ALO (128 * S1_LDA)
#define S1_BHI (2 * 128 * S1_LDA)
#define S1_BLO (S1_BHI + 16 * LDB_H)
#define S1_SMEM ((S1_BLO + 16 * LDB_H) * 2)

// ---------------------------------------------------------------------------
// Generic loaders / mainloops
// ---------------------------------------------------------------------------
__device__ __forceinline__ void gm_load_stage(unsigned sb, const __half* aH,
                                              const __half* aL, const __half* bH,
                                              const __half* bL, int kt, int tid,
                                              int aStride) {
#pragma unroll
    for (int t = 0; t < 2; t++) {
        int idx = tid + t * 256;
        int r = idx >> 2, c8 = idx & 3;
        size_t g = (size_t)r * aStride + kt * 32 + c8 * 8;
        cpa16(sb + (H_AHI + r * AG_LDA + c8 * 8) * 2, aH + g);
        cpa16(sb + (H_ALO + r * AG_LDA + c8 * 8) * 2, aL + g);
    }
#pragma unroll
    for (int t = 0; t < 2; t++) {
        int idx = tid + t * 256;
        int r = idx >> 4, c8 = idx & 15;
        size_t g = (size_t)(kt * 32 + r) * NHID + c8 * 8;
        cpa16(sb + (H_BHI + r * LDB_H + c8 * 8) * 2, bH + g);
        cpa16(sb + (H_BLO + r * LDB_H + c8 * 8) * 2, bL + g);
    }
}

template <int KT>
__device__ __forceinline__ void gemm_mainloop(
        __half* smh, unsigned sbase, const __half* aH, const __half* aL,
        const __half* bH, const __half* bL, int aStride, int tid,
        int wm, int wn, CF (&c)[2][4]) {
    gm_load_stage(sbase, aH, aL, bH, bL, 0, tid, aStride);
    CPA_COMMIT();
    for (int kt = 0; kt < KT; kt++) {
        if (kt + 1 < KT) {
            gm_load_stage(sbase + ((kt + 1) & 1) * STAGE_H * 2,
                          aH, aL, bH, bL, kt + 1, tid, aStride);
            CPA_COMMIT();
            CPA_WAIT(1);
        } else {
            CPA_WAIT(0);
        }
        __syncthreads();

        const __half* S = smh + (kt & 1) * STAGE_H;
#pragma unroll
        for (int k16 = 0; k16 < 2; k16++) {
            AF afH[2], afL[2];
#pragma unroll
            for (int i = 0; i < 2; i++) {
                const __half* p = S + H_AHI + (wm * 32 + i * 16) * AG_LDA + k16 * 16;
                wmma::load_matrix_sync(afH[i], p, AG_LDA);
                wmma::load_matrix_sync(afL[i], p + (H_ALO - H_AHI), AG_LDA);
            }
#pragma unroll
            for (int j = 0; j < 4; j++) {
                BF bfH, bfL;
                const __half* p = S + H_BHI + (k16 * 16) * LDB_H + wn * 64 + j * 16;
                wmma::load_matrix_sync(bfH, p, LDB_H);
                wmma::load_matrix_sync(bfL, p + (H_BLO - H_BHI), LDB_H);
#pragma unroll
                for (int i = 0; i < 2; i++) {
                    wmma::mma_sync(c[i][j], afH[i], bfH, c[i][j]);
                    wmma::mma_sync(c[i][j], afH[i], bfL, c[i][j]);
                    wmma::mma_sync(c[i][j], afL[i], bfH, c[i][j]);
                }
            }
        }
        __syncthreads();
    }
}

__device__ __forceinline__ void gm64_load_stage(unsigned sb, const __half* aH,
                                                const __half* aL, const __half* bH,
                                                const __half* bL, int kt, int tid,
                                                int aStride) {
#pragma unroll
    for (int t = 0; t < 2; t++) {
        int idx = tid + t * 256;
        int r = idx >> 2, c8 = idx & 3;
        size_t g = (size_t)r * aStride + kt * 32 + c8 * 8;
        cpa16(sb + (r * AG_LDA + c8 * 8) * 2, aH + g);
        cpa16(sb + (128 * AG_LDA + r * AG_LDA + c8 * 8) * 2, aL + g);
    }
    {
        int r = tid >> 3, c8 = tid & 7;
        size_t g = (size_t)(kt * 32 + r) * ST_HID + c8 * 8;
        cpa16(sb + (B64_BHI + r * LDB64 + c8 * 8) * 2, bH + g);
        cpa16(sb + (B64_BLO + r * LDB64 + c8 * 8) * 2, bL + g);
    }
}

template <int KT>
__device__ __forceinline__ void gemm_mainloop64(
        __half* smh, unsigned sbase, const __half* aH, const __half* aL,
        const __half* bH, const __half* bL, int aStride, int tid,
        int wm, int wn, CF (&c)[2][2]) {
    gm64_load_stage(sbase, aH, aL, bH, bL, 0, tid, aStride);
    CPA_COMMIT();
    for (int kt = 0; kt < KT; kt++) {
        if (kt + 1 < KT) {
            gm64_load_stage(sbase + ((kt + 1) & 1) * STAGE64_H * 2,
                            aH, aL, bH, bL, kt + 1, tid, aStride);
            CPA_COMMIT();
            CPA_WAIT(1);
        } else {
            CPA_WAIT(0);
        }
        __syncthreads();

        const __half* S = smh + (kt & 1) * STAGE64_H;
#pragma unroll
        for (int k16 = 0; k16 < 2; k16++) {
            AF afH[2], afL[2];
#pragma unroll
            for (int i = 0; i < 2; i++) {
                const __half* p = S + (wm * 32 + i * 16) * AG_LDA + k16 * 16;
                wmma::load_matrix_sync(afH[i], p, AG_LDA);
                wmma::load_matrix_sync(afL[i], p + 128 * AG_LDA, AG_LDA);
            }
#pragma unroll
            for (int j = 0; j < 2; j++) {
                BF bfH, bfL;
                const __half* p = S + B64_BHI + (k16 * 16) * LDB64 + wn * 32 + j * 16;
                wmma::load_matrix_sync(bfH, p, LDB64);
                wmma::load_matrix_sync(bfL, p + (B64_BLO - B64_BHI), LDB64);
#pragma unroll
                for (int i = 0; i < 2; i++) {
                    wmma::mma_sync(c[i][j], afH[i], bfH, c[i][j]);
                    wmma::mma_sync(c[i][j], afH[i], bfL, c[i][j]);
                    wmma::mma_sync(c[i][j], afL[i], bfH, c[i][j]);
                }
            }
        }
        __syncthreads();
    }
}

// ---------------------------------------------------------------------------
// agg (layer 2)
// ---------------------------------------------------------------------------
__global__ __launch_bounds__(256, 2)
void agg_wmma(const __half* __restrict__ adjhi, const __half* __restrict__ adjlo,
              const __half* __restrict__ shi, const __half* __restrict__ slo,
              float* __restrict__ oe) {
    extern __shared__ __half smh[];
    const unsigned sbase = (unsigned)__cvta_generic_to_shared(smh);
    const int tid = threadIdx.x;
    const int wid = tid >> 5;
    const int wm = wid >> 1, wn = wid & 1;
    const int m0 = blockIdx.x * 128;
    const int b = blockIdx.y, e = blockIdx.z;

    const __half* aH = adjhi + ((size_t)(b * Eq + e) * Nq + m0) * Nq;
    const __half* aL = adjlo + ((size_t)(b * Eq + e) * Nq + m0) * Nq;
    const __half* bH = shi + (size_t)(b * Eq + e) * Nq * NHID;
    const __half* bL = slo + (size_t)(b * Eq + e) * Nq * NHID;

    CF c[2][4];
#pragma unroll
    for (int i = 0; i < 2; i++)
#pragma unroll
        for (int j = 0; j < 4; j++) wmma::fill_fragment(c[i][j], 0.f);

    gemm_mainloop<Nq / 32>(smh, sbase, aH, aL, bH, bL, Nq, tid, wm, wn, c);

#pragma unroll
    for (int i = 0; i < 2; i++)
#pragma unroll
        for (int j = 0; j < 4; j++) {
#pragma unroll
            for (int t = 0; t < c[i][j].num_elements; t++)
                c[i][j].x[t] = fmaxf(c[i][j].x[t] * SCALE_UP, 0.f);
            float* op = oe + ((size_t)(b * Eq + e) * Nq + m0 + wm * 32 + i * 16) * NHID
                           + wn * 64 + j * 16;
            wmma::store_matrix_sync(op, c[i][j], NHID, wmma::mem_row_major);
        }
}

// ---------------------------------------------------------------------------
// agg64 (layer 3)
// ---------------------------------------------------------------------------
__global__ __launch_bounds__(256, 2)
void agg64_wmma(const __half* __restrict__ adjhi, const __half* __restrict__ adjlo,
                const __half* __restrict__ shi, const __half* __restrict__ slo,
                float* __restrict__ oe64) {
    extern __shared__ __half smh[];
    const unsigned sbase = (unsigned)__cvta_generic_to_shared(smh);
    const int tid = threadIdx.x;
    const int wid = tid >> 5;
    const int wm = wid >> 1, wn = wid & 1;
    const int m0 = blockIdx.x * 128;
    const int b = blockIdx.y, e = blockIdx.z;

    const __half* aH = adjhi + ((size_t)(b * Eq + e) * Nq + m0) * Nq;
    const __half* aL = adjlo + ((size_t)(b * Eq + e) * Nq + m0) * Nq;
    const __half* bH = shi + (size_t)(b * Eq + e) * Nq * ST_HID;
    const __half* bL = slo + (size_t)(b * Eq + e) * Nq * ST_HID;

    CF c[2][2];
#pragma unroll
    for (int i = 0; i < 2; i++)
#pragma unroll
        for (int j = 0; j < 2; j++) wmma::fill_fragment(c[i][j], 0.f);

    gemm_mainloop64<Nq / 32>(smh, sbase, aH, aL, bH, bL, Nq, tid, wm, wn, c);

#pragma unroll
    for (int i = 0; i < 2; i++)
#pragma unroll
        for (int j = 0; j < 2; j++) {
#pragma unroll
            for (int t = 0; t < c[i][j].num_elements; t++)
                c[i][j].x[t] *= SCALE_UP;
            float* op = oe64 + ((size_t)(b * Eq + e) * Nq + m0 + wm * 32 + i * 16) * ST_HID
                             + wn * 32 + j * 16;
            wmma::store_matrix_sync(op, c[i][j], ST_HID, wmma::mem_row_major);
        }
}

// ---------------------------------------------------------------------------
// support23 (layer 2)
// ---------------------------------------------------------------------------
__global__ __launch_bounds__(256, 2)
void support23_wmma(const __half* __restrict__ hhi, const __half* __restrict__ hlo,
                    const __half* __restrict__ whi, const __half* __restrict__ wlo,
                    __half* __restrict__ supphi, __half* __restrict__ supplo) {
    extern __shared__ __half smh[];
    const unsigned sbase = (unsigned)__cvta_generic_to_shared(smh);
    const int tid = threadIdx.x;
    const int wid = tid >> 5, lane = tid & 31;
    const int wm = wid >> 1, wn = wid & 1;
    const int e = blockIdx.y;
    const int m0 = blockIdx.x * 128;
    const int b = m0 / Nq, n0 = m0 % Nq;

    const __half* aH = hhi + (size_t)m0 * NHID;
    const __half* aL = hlo + (size_t)m0 * NHID;
    const __half* bH = whi + (size_t)e * NHID * NHID;
    const __half* bL = wlo + (size_t)e * NHID * NHID;

    CF c[2][4];
#pragma unroll
    for (int i = 0; i < 2; i++)
#pragma unroll
        for (int j = 0; j < 4; j++) wmma::fill_fragment(c[i][j], 0.f);

    gemm_mainloop<NHID / 32>(smh, sbase, aH, aL, bH, bL, NHID, tid, wm, wn, c);

    float* E = (float*)smh + wid * (32 * 68);
#pragma unroll
    for (int i = 0; i < 2; i++)
#pragma unroll
        for (int j = 0; j < 4; j++)
            wmma::store_matrix_sync(E + (i * 16) * 68 + j * 16, c[i][j], 68,
                                    wmma::mem_row_major);
    __syncwarp();
#pragma unroll
    for (int t = 0; t < 16; t++) {
        int p = lane + t * 32;
        int r = p >> 4, c4 = (p & 15) * 4;
        float4 v = *(float4*)&E[r * 68 + c4];
        __half h0, h1, h2, h3, l0, l1, l2, l3;
        split1h(v.x, h0, l0); split1h(v.y, h1, l1);
        split1h(v.z, h2, l2); split1h(v.w, h3, l3);
        size_t o = ((size_t)(b * Eq + e) * Nq + n0 + wm * 32 + r) * NHID + wn * 64 + c4;
        half2 hA = __halves2half2(h0, h1), hB = __halves2half2(h2, h3);
        half2 lA = __halves2half2(l0, l1), lB = __halves2half2(l2, l3);
        uint2 uh, ul;
        uh.x = *(unsigned*)&hA; uh.y = *(unsigned*)&hB;
        ul.x = *(unsigned*)&lA; ul.y = *(unsigned*)&lB;
        *(uint2*)(supphi + o) = uh;
        *(uint2*)(supplo + o) = ul;
    }
}

// ---------------------------------------------------------------------------
// supp3 (layer 3, N=64)
// ---------------------------------------------------------------------------
__global__ __launch_bounds__(256, 2)
void supp3_wmma(const __half* __restrict__ hhi, const __half* __restrict__ hlo,
                const __half* __restrict__ whi, const __half* __restrict__ wlo,
                __half* __restrict__ s64hi, __half* __restrict__ s64lo) {
    extern __shared__ __half smh[];
    const unsigned sbase = (unsigned)__cvta_generic_to_shared(smh);
    const int tid = threadIdx.x;
    const int wid = tid >> 5, lane = tid & 31;
    const int wm = wid >> 1, wn = wid & 1;
    const int e = blockIdx.y;
    const int m0 = blockIdx.x * 128;
    const int b = m0 / Nq, n0 = m0 % Nq;

    const __half* aH = hhi + (size_t)m0 * NHID;
    const __half* aL = hlo + (size_t)m0 * NHID;
    const __half* bH = whi + (size_t)e * NHID * ST_HID;
    const __half* bL = wlo + (size_t)e * NHID * ST_HID;

    CF c[2][2];
#pragma unroll
    for (int i = 0; i < 2; i++)
#pragma unroll
        for (int j = 0; j < 2; j++) wmma::fill_fragment(c[i][j], 0.f);

    gemm_mainloop64<NHID / 32>(smh, sbase, aH, aL, bH, bL, NHID, tid, wm, wn, c);

    float* E = (float*)smh + wid * (32 * 36);
#pragma unroll
    for (int i = 0; i < 2; i++)
#pragma unroll
        for (int j = 0; j < 2; j++)
            wmma::store_matrix_sync(E + (i * 16) * 36 + j * 16, c[i][j], 36,
                                    wmma::mem_row_major);
    __syncwarp();
#pragma unroll
    for (int t = 0; t < 8; t++) {
        int p = lane + t * 32;
        int r = p >> 3, c4 = (p & 7) * 4;
        float4 v = *(float4*)&E[r * 36 + c4];
        __half h0, h1, h2, h3, l0, l1, l2, l3;
        split1h(v.x, h0, l0); split1h(v.y, h1, l1);
        split1h(v.z, h2, l2); split1h(v.w, h3, l3);
        size_t o = ((size_t)(b * Eq + e) * Nq + n0 + wm * 32 + r) * ST_HID + wn * 32 + c4;
        half2 hA = __halves2half2(h0, h1), hB = __halves2half2(h2, h3);
        half2 lA = __halves2half2(l0, l1), lB = __halves2half2(l2, l3);
        uint2 uh, ul;
        uh.x = *(unsigned*)&hA; uh.y = *(unsigned*)&hB;
        ul.x = *(unsigned*)&lA; ul.y = *(unsigned*)&lB;
        *(uint2*)(s64hi + o) = uh;
        *(uint2*)(s64lo + o) = ul;
    }
}

// ---------------------------------------------------------------------------
// agg16_split v2: register-double-buffered fp32 adj loads, resident h0.
// Reads fp32 adj; writes adj fp16 hi/lo; t1 = adj @ h0_scaled. grid (3,Bq,Eq)
// ---------------------------------------------------------------------------
__global__ __launch_bounds__(256, 2)
void agg16_split(const float* __restrict__ adjF,
                 __half* __restrict__ adjhi, __half* __restrict__ adjlo,
                 const __half* __restrict__ h0hi, const __half* __restrict__ h0lo,
                 __half* __restrict__ t1hi, __half* __restrict__ t1lo) {
    extern __shared__ __half smh[];
    __half* AHI = smh;
    __half* ALO = smh + 128 * AG_LDA;
    __half* BHI = smh + A16_BHI;     // resident h0[b]: 384x16 hi
    __half* BLO = smh + A16_BLO;     // lo

    const int tid = threadIdx.x;
    const int wid = tid >> 5, lane = tid & 31;
    const int m0 = blockIdx.x * 128;
    const int b = blockIdx.y, e = blockIdx.z;

    const size_t gbase = ((size_t)(b * Eq + e) * Nq + m0) * Nq;
    const float* aF = adjF + gbase;

    // Resident B: full h0[b] (384x16 halfs hi/lo), loaded once.
    {
        const __half* bH = h0hi + (size_t)b * Nq * NFEAT;
        const __half* bL = h0lo + (size_t)b * Nq * NFEAT;
#pragma unroll
        for (int t = 0; t < 3; t++) {
            int i8 = tid + t * 256;          // 768 chunks of 8 halfs
            *(uint4*)&BHI[i8 * 8] = *(const uint4*)(bH + (size_t)i8 * 8);
            *(uint4*)&BLO[i8 * 8] = *(const uint4*)(bL + (size_t)i8 * 8);
        }
    }

    CF acc;
    wmma::fill_fragment(acc, 0.f);

    // Per-thread A mapping: 2 chunks of 8 floats; chunk q -> row r, col c8
    const int r0 = tid >> 2, c80 = tid & 3;             // chunk 0
    const int r1 = (tid + 256) >> 2, c81 = (tid + 256) & 3;

    float4 cur[2][2], nxt[2][2];
    {   // prologue: load kt=0
        const float* s0 = aF + (size_t)r0 * Nq + c80 * 8;
        const float* s1 = aF + (size_t)r1 * Nq + c81 * 8;
        cur[0][0] = *(const float4*)s0; cur[0][1] = *(const float4*)(s0 + 4);
        cur[1][0] = *(const float4*)s1; cur[1][1] = *(const float4*)(s1 + 4);
    }
    __syncthreads();   // h0 resident

    constexpr int KT = Nq / 32;   // 12
    for (int kt = 0; kt < KT; kt++) {
        if (kt + 1 < KT) {
            const float* s0 = aF + (size_t)r0 * Nq + (kt + 1) * 32 + c80 * 8;
            const float* s1 = aF + (size_t)r1 * Nq + (kt + 1) * 32 + c81 * 8;
            nxt[0][0] = *(const float4*)s0; nxt[0][1] = *(const float4*)(s0 + 4);
            nxt[1][0] = *(const float4*)s1; nxt[1][1] = *(const float4*)(s1 + 4);
        }
        // split current regs -> smem A + global adj
#pragma unroll
        for (int q = 0; q < 2; q++) {
            int rr = q ? r1 : r0, cc = q ? c81 : c80;
            float vv[8] = {cur[q][0].x, cur[q][0].y, cur[q][0].z, cur[q][0].w,
                           cur[q][1].x, cur[q][1].y, cur[q][1].z, cur[q][1].w};
            H8 H, L;
#pragma unroll
            for (int j = 0; j < 8; j++) split1h(vv[j], H.v[j], L.v[j]);
            *(H8*)&AHI[rr * AG_LDA + cc * 8] = H;
            *(H8*)&ALO[rr * AG_LDA + cc * 8] = L;
            size_t go = gbase + (size_t)rr * Nq + kt * 32 + cc * 8;
            *(H8*)(adjhi + go) = H;
            *(H8*)(adjlo + go) = L;
        }
        __syncthreads();

#pragma unroll
        for (int k16 = 0; k16 < 2; k16++) {
            AF afH, afL;
            const __half* pa = AHI + (wid * 16) * AG_LDA + k16 * 16;
            wmma::load_matrix_sync(afH, pa, AG_LDA);
            wmma::load_matrix_sync(afL, pa + 128 * AG_LDA, AG_LDA);
            BF bfH, bfL;
            const __half* pb = BHI + (kt * 32 + k16 * 16) * NFEAT;
            wmma::load_matrix_sync(bfH, pb, NFEAT);
            wmma::load_matrix_sync(bfL, pb + (A16_BLO - A16_BHI), NFEAT);
            wmma::mma_sync(acc, afH, bfH, acc);
            wmma::mma_sync(acc, afH, bfL, acc);
            wmma::mma_sync(acc, afL, bfH, acc);
        }
        __syncthreads();
#pragma unroll
        for (int q = 0; q < 2; q++) {
            cur[q][0] = nxt[q][0];
            cur[q][1] = nxt[q][1];
        }
    }

    // Epilogue: split t1 (reuse AHI region as fp32 staging)
    float* E = (float*)smh + wid * (16 * 20);
    wmma::store_matrix_sync(E, acc, 20, wmma::mem_row_major);
    __syncwarp();
    {
        int r = lane >> 1, c0 = (lane & 1) * 8;
        H8 H, L;
#pragma unroll
        for (int j = 0; j < 8; j++)
            split1h(E[r * 20 + c0 + j], H.v[j], L.v[j]);
        size_t o = ((size_t)(b * Eq + e) * Nq + m0 + wid * 16 + r) * NFEAT + c0;
        *(H8*)(t1hi + o) = H;
        *(H8*)(t1lo + o) = L;
    }
}

// ---------------------------------------------------------------------------
// support1
// ---------------------------------------------------------------------------
__global__ __launch_bounds__(256, 2)
void support1_wmma(const __half* __restrict__ t1hi, const __half* __restrict__ t1lo,
                   const __half* __restrict__ w1hi, const __half* __restrict__ w1lo,
                   float* __restrict__ oe) {
    extern __shared__ __half smh[];
    __half* Ahi = smh + S1_AHI;
    __half* Alo = smh + S1_ALO;
    __half* Bhi = smh + S1_BHI;
    __half* Blo = smh + S1_BLO;

    const int tid = threadIdx.x;
    const int wid = tid >> 5;
    const int wm = wid >> 1, wn = wid & 1;
    const int e = blockIdx.y;
    const int m0 = blockIdx.x * 128;
    const int b = m0 / Nq, n0 = m0 % Nq;

    {
        int r = tid >> 1, c8 = tid & 1;
        size_t g = ((size_t)(b * Eq + e) * Nq + n0 + r) * NFEAT + c8 * 8;
        *(uint4*)&Ahi[r * S1_LDA + c8 * 8] = *(const uint4*)(t1hi + g);
        *(uint4*)&Alo[r * S1_LDA + c8 * 8] = *(const uint4*)(t1lo + g);
    }
    {
        int r = tid >> 4, c8 = tid & 15;
        size_t g = (size_t)(e * NFEAT + r) * NHID + c8 * 8;
        *(uint4*)&Bhi[r * LDB_H + c8 * 8] = *(const uint4*)(w1hi + g);
        *(uint4*)&Blo[r * LDB_H + c8 * 8] = *(const uint4*)(w1lo + g);
    }
    __syncthreads();

    CF c[2][4];
#pragma unroll
    for (int i = 0; i < 2; i++)
#pragma unroll
        for (int j = 0; j < 4; j++) wmma::fill_fragment(c[i][j], 0.f);

    AF afH[2], afL[2];
#pragma unroll
    for (int i = 0; i < 2; i++) {
        const __half* p = Ahi + (wm * 32 + i * 16) * S1_LDA;
        wmma::load_matrix_sync(afH[i], p, S1_LDA);
        wmma::load_matrix_sync(afL[i], p + (S1_ALO - S1_AHI), S1_LDA);
    }
#pragma unroll
    for (int j = 0; j < 4; j++) {
        BF bfH, bfL;
        const __half* p = Bhi + wn * 64 + j * 16;
        wmma::load_matrix_sync(bfH, p, LDB_H);
        wmma::load_matrix_sync(bfL, p + (S1_BLO - S1_BHI), LDB_H);
#pragma unroll
        for (int i = 0; i < 2; i++) {
            wmma::mma_sync(c[i][j], afH[i], bfH, c[i][j]);
            wmma::mma_sync(c[i][j], afH[i], bfL, c[i][j]);
            wmma::mma_sync(c[i][j], afL[i], bfH, c[i][j]);
        }
    }

#pragma unroll
    for (int i = 0; i < 2; i++)
#pragma unroll
        for (int j = 0; j < 4; j++) {
#pragma unroll
            for (int t = 0; t < c[i][j].num_elements; t++)
                c[i][j].x[t] = fmaxf(c[i][j].x[t] * SCALE_UP, 0.f);
            float* op = oe + ((size_t)(b * Eq + e) * Nq + n0 + wm * 32 + i * 16) * NHID
                           + wn * 64 + j * 16;
            wmma::store_matrix_sync(op, c[i][j], NHID, wmma::mem_row_major);
        }
}

// ---------------------------------------------------------------------------
// head64
// ---------------------------------------------------------------------------
__global__ __launch_bounds__(256)
void head64_kernel(const float* __restrict__ oe64,
                   const float* __restrict__ b1,
                   const float* __restrict__ w2, const float* __restrict__ b2,
                   const float* __restrict__ rescale, float* __restrict__ out) {
    __shared__ float z1S[16][ST_HID + 4];

    const int tid = threadIdx.x;
    const int row0 = blockIdx.x * 16;
    const int b = row0 / Nq;
    const int n0 = row0 % Nq;

    const float* base = oe64 + ((size_t)(b * Eq) * Nq + n0) * ST_HID;
    const size_t eS = (size_t)Nq * ST_HID;
    {
        int r = tid >> 4, c4 = (tid & 15) * 4;
        float4 v0 = *(const float4*)(base + (size_t)r * ST_HID + c4);
        float4 v1 = *(const float4*)(base + eS + (size_t)r * ST_HID + c4);
        float4 v2 = *(const float4*)(base + 2 * eS + (size_t)r * ST_HID + c4);
        z1S[r][c4 + 0] = tanhf(v0.x + v1.x + v2.x + b1[c4 + 0]);
        z1S[r][c4 + 1] = tanhf(v0.y + v1.y + v2.y + b1[c4 + 1]);
        z1S[r][c4 + 2] = tanhf(v0.z + v1.z + v2.z + b1[c4 + 2]);
        z1S[r][c4 + 3] = tanhf(v0.w + v1.w + v2.w + b1[c4 + 3]);
    }
    __syncthreads();

    const float ew = expf(rescale[0]);
    for (int p = tid; p < 16 * 32; p += 256) {
        int row = p >> 5, j = p & 31;
        float acc = b2[j];
#pragma unroll 8
        for (int k = 0; k < ST_HID; k++)
            acc += z1S[row][k] * w2[j * ST_HID + k];
        int grow = row0 + row;
        if (j < ST_OUT)
            out[(size_t)grow * ST_OUT + j] = ew * tanhf(acc);
        else
            out[(size_t)MFLAT * ST_OUT + (size_t)grow * ST_OUT + (j - ST_OUT)] = acc;
    }
}

// ---------------------------------------------------------------------------
extern "C" void kernel_launch(void* const* d_in, const int* in_sizes, int n_in,
                              void* d_out, int out_size) {
    const float* x       = (const float*)d_in[0];
    const float* adj     = (const float*)d_in[1];
    const float* emb_w   = (const float*)d_in[2];
    const float* gc1_w   = (const float*)d_in[3];
    const float* gc2_w   = (const float*)d_in[4];
    const float* gc3_w   = (const float*)d_in[5];
    const float* st_w1   = (const float*)d_in[6];
    const float* st_b1   = (const float*)d_in[7];
    const float* st_w2   = (const float*)d_in[8];
    const float* st_b2   = (const float*)d_in[9];
    const float* rescale = (const float*)d_in[10];
    float* out = (float*)d_out;

    __half *adjhi, *adjlo, *supphi, *supplo, *s64hi, *s64lo;
    __half *hhi, *hlo, *h0hi, *h0lo, *t1hi, *t1lo;
    __half *w1hi, *w1lo, *w2hi, *w2lo, *w31hi, *w31lo;
    float* oe;
    cudaGetSymbolAddress((void**)&adjhi,  g_adjhi);
    cudaGetSymbolAddress((void**)&adjlo,  g_adjlo);
    cudaGetSymbolAddress((void**)&supphi, g_supphi);
    cudaGetSymbolAddress((void**)&supplo, g_supplo);
    cudaGetSymbolAddress((void**)&s64hi,  g_s64hi);
    cudaGetSymbolAddress((void**)&s64lo,  g_s64lo);
    cudaGetSymbolAddress((void**)&oe,     g_oe);
    cudaGetSymbolAddress((void**)&hhi,    g_hhi);
    cudaGetSymbolAddress((void**)&hlo,    g_hlo);
    cudaGetSymbolAddress((void**)&h0hi,   g_h0hi);
    cudaGetSymbolAddress((void**)&h0lo,   g_h0lo);
    cudaGetSymbolAddress((void**)&t1hi,   g_t1hi);
    cudaGetSymbolAddress((void**)&t1lo,   g_t1lo);
    cudaGetSymbolAddress((void**)&w1hi,   g_w1hi);
    cudaGetSymbolAddress((void**)&w1lo,   g_w1lo);
    cudaGetSymbolAddress((void**)&w2hi,   g_w2hi);
    cudaGetSymbolAddress((void**)&w2lo,   g_w2lo);
    cudaGetSymbolAddress((void**)&w31hi,  g_w31hi);
    cudaGetSymbolAddress((void**)&w31lo,  g_w31lo);

    cudaFuncSetAttribute(agg_wmma,       cudaFuncAttributeMaxDynamicSharedMemorySize, AG_SMEM);
    cudaFuncSetAttribute(agg64_wmma,     cudaFuncAttributeMaxDynamicSharedMemorySize, A64_SMEM);
    cudaFuncSetAttribute(agg16_split,    cudaFuncAttributeMaxDynamicSharedMemorySize, A16_SMEM);
    cudaFuncSetAttribute(support1_wmma,  cudaFuncAttributeMaxDynamicSharedMemorySize, S1_SMEM);
    cudaFuncSetAttribute(support23_wmma, cudaFuncAttributeMaxDynamicSharedMemorySize, AG_SMEM);
    cudaFuncSetAttribute(supp3_wmma,     cudaFuncAttributeMaxDynamicSharedMemorySize, A64_SMEM);

    weight_prep_kernel<<<W2BLK + W1BLK + W31BLK + H0BLK, 256>>>(
        gc2_w, gc3_w, emb_w, gc1_w, st_w1, x,
        w2hi, w2lo, w1hi, w1lo, w31hi, w31lo, h0hi, h0lo);

    dim3 agrid(Nq / 128, Bq, Eq);     // (3, 64, 3)
    dim3 sgrid(MFLAT / 128, Eq);      // (192, 3)
    const int hsumBlocks = (MFLAT * NHID) / (256 * 8);

    // Layer 1: fused adj split + t1 = adj@h0; then oe = relu(t1@gc1_w)
    agg16_split<<<agrid, 256, A16_SMEM>>>(adj, adjhi, adjlo, h0hi, h0lo, t1hi, t1lo);
    support1_wmma<<<sgrid, 256, S1_SMEM>>>(t1hi, t1lo, w1hi, w1lo, oe);
    // Layer 2
    hsum_split_kernel<<<hsumBlocks, 256>>>(oe, hhi, hlo);
    support23_wmma<<<sgrid, 256, AG_SMEM>>>(hhi, hlo, w2hi, w2lo, supphi, supplo);
    agg_wmma<<<agrid, 256, AG_SMEM>>>(adjhi, adjlo, supphi, supplo, oe);
    // Layer 3 (w1 folded: N=64)
    hsum_split_kernel<<<hsumBlocks, 256>>>(oe, hhi, hlo);
    supp3_wmma<<<sgrid, 256, A64_SMEM>>>(hhi, hlo, w31hi, w31lo, s64hi, s64lo);
    agg64_wmma<<<agrid, 256, A64_SMEM>>>(adjhi, adjlo, s64hi, s64lo, oe);
    // Head
    head64_kernel<<<MFLAT / 16, 256>>>(oe, st_b1, st_w2, st_b2, rescale, out);
}